// round 1
// baseline (speedup 1.0000x reference)
#include <cuda_runtime.h>

// ---------------- problem constants ----------------
#define Bb   2
#define Ss   4096
#define Dd   2048
#define Hh   16
#define DK   128
#define DV   128
#define DH   8192
#define Ll   512
#define NSEGc 8
#define BSr  (Bb*Ss)      // 8192 rows
#define BHn  (Bb*Hh)      // 32 (batch,head) pairs

// ---------------- scratch (device globals; no allocs allowed) ----------------
__device__ float g_q  [BSr*Dd];
__device__ float g_k  [BSr*Dd];
__device__ float g_v  [BSr*Dd];
__device__ float g_att[BSr*Dd];
__device__ float g_a  [BSr*Dd];
__device__ float g_h1 [(size_t)BSr*DH];
__device__ float g_h2 [BSr*Dd];
__device__ float g_mem [BHn*DK*DV];
__device__ float g_zst [BHn*DK];
__device__ float g_vdel[BHn*Ll*DV];

// ---------------- helpers ----------------
__device__ __forceinline__ float gelu_exact(float x) {
    return 0.5f * x * (1.0f + erff(x * 0.70710678118654752440f));
}
__device__ __forceinline__ float elu1(float x) {      // elu(x)+1
    return (x > 0.0f) ? (x + 1.0f) : __expf(x);
}

// ---------------- state init (mem=0, z=1/DK) ----------------
__global__ void init_state_kernel() {
    int i = blockIdx.x * blockDim.x + threadIdx.x;
    if (i < BHn*DK*DV) g_mem[i] = 0.0f;
    if (i < BHn*DK)    g_zst[i] = 1.0f / (float)DK;
}

// ---------------- SGEMM: C[M,N] = A[M,K] @ B[K,N] + bias, optional GELU ----------------
// 128x128 block tile, BK=16, 256 threads, 8x8 per thread (cols split 4+4 for
// conflict-free float4 smem reads). M,N,K multiples of 128/16 here.
template<int EPI>
__global__ void __launch_bounds__(256)
gemm_kernel(const float* __restrict__ A, const float* __restrict__ B,
            const float* __restrict__ bias, float* __restrict__ C,
            int M, int N, int K)
{
    __shared__ float As[16][132];   // transposed A tile (k-major), padded
    __shared__ float Bs[16][128];

    const int bm = blockIdx.y * 128;
    const int bn = blockIdx.x * 128;
    const int tid = threadIdx.x;
    const int tx = tid & 15;        // 16 col-threads
    const int ty = tid >> 4;        // 16 row-threads

    float acc[8][8];
#pragma unroll
    for (int i = 0; i < 8; i++)
#pragma unroll
        for (int j = 0; j < 8; j++) acc[i][j] = 0.0f;

    for (int k0 = 0; k0 < K; k0 += 16) {
#pragma unroll
        for (int i = 0; i < 2; i++) {              // A tile: 128 rows x 16 k
            int idx = tid + i * 256;               // 0..511
            int r = idx >> 2, c = (idx & 3) * 4;
            float4 t = *(const float4*)(A + (size_t)(bm + r) * K + k0 + c);
            As[c+0][r] = t.x; As[c+1][r] = t.y; As[c+2][r] = t.z; As[c+3][r] = t.w;
        }
#pragma unroll
        for (int i = 0; i < 2; i++) {              // B tile: 16 k x 128 cols
            int idx = tid + i * 256;
            int r = idx >> 5, c = (idx & 31) * 4;
            *(float4*)&Bs[r][c] = *(const float4*)(B + (size_t)(k0 + r) * N + bn + c);
        }
        __syncthreads();
#pragma unroll
        for (int kk = 0; kk < 16; kk++) {
            float a[8], b[8];
#pragma unroll
            for (int i = 0; i < 8; i++) a[i] = As[kk][ty*8 + i];
            float4 b0 = *(const float4*)&Bs[kk][tx*4];
            float4 b1 = *(const float4*)&Bs[kk][64 + tx*4];
            b[0]=b0.x; b[1]=b0.y; b[2]=b0.z; b[3]=b0.w;
            b[4]=b1.x; b[5]=b1.y; b[6]=b1.z; b[7]=b1.w;
#pragma unroll
            for (int i = 0; i < 8; i++)
#pragma unroll
                for (int j = 0; j < 8; j++)
                    acc[i][j] += a[i] * b[j];
        }
        __syncthreads();
    }

#pragma unroll
    for (int i = 0; i < 8; i++) {
        int r = bm + ty*8 + i;
#pragma unroll
        for (int g = 0; g < 2; g++) {
            int c = bn + g*64 + tx*4;
            float4 o;
            o.x = acc[i][g*4+0] + bias[c+0];
            o.y = acc[i][g*4+1] + bias[c+1];
            o.z = acc[i][g*4+2] + bias[c+2];
            o.w = acc[i][g*4+3] + bias[c+3];
            if (EPI == 1) {
                o.x = gelu_exact(o.x); o.y = gelu_exact(o.y);
                o.z = gelu_exact(o.z); o.w = gelu_exact(o.w);
            }
            *(float4*)(C + (size_t)r * N + c) = o;
        }
    }
}

// ---------------- attention kernel A (per segment) ----------------
// grid (8 row-blocks, 32 bh), 256 threads. Each block owns 64 query rows.
// Dynamic smem layout (floats):
//   qsT  [128][65]            (q tile transposed; becomes sigma(q) in place)
//   bufB [128*128]            (k chunk transposed / v chunk / mem tile)
//   sc   [64][513]            (scores -> probabilities; later aliased as skT[128][65])
//   z_s  [128]
#define SM_QST 0
#define SM_BUF (128*65)
#define SM_SC  (128*65 + 128*128)
#define SM_Z   (128*65 + 128*128 + 64*513)
#define SMEM_A_FLOATS (128*65 + 128*128 + 64*513 + 128)
#define SMEM_A_BYTES  (SMEM_A_FLOATS * 4)

__global__ void __launch_bounds__(256)
attn_seg_a(const float* __restrict__ q, const float* __restrict__ k,
           const float* __restrict__ v, const float* __restrict__ betas,
           float* __restrict__ att, int seg)
{
    extern __shared__ float sm[];
    float* qsT  = sm + SM_QST;
    float* bufB = sm + SM_BUF;
    float* sc   = sm + SM_SC;
    float* skT  = sm + SM_SC;      // alias (after softmax/PV are done)
    float* z_s  = sm + SM_Z;

    const int tid = threadIdx.x;
    const int tx = tid & 15, ty = tid >> 4;
    const int rb = blockIdx.x;                 // 0..7 (row block)
    const int bh = blockIdx.y;                 // 0..31
    const int b  = bh >> 4, h = bh & 15;
    const int r0 = rb * 64;
    const size_t rowbase = (size_t)(b * Ss + seg * Ll);
    const int colbase = h * 128;

    // ---- load q tile transposed [k][row] (conflict-free writes) ----
    for (int i = tid; i < 64 * 128; i += 256) {
        int r = i >> 7, c = i & 127;
        qsT[c * 65 + r] = q[(rowbase + r0 + r) * Dd + colbase + c];
    }
    __syncthreads();

    const float scale = 0.088388347648318447f;   // 1/sqrt(128)

    // ---- phase 1: scores = q @ k^T * scale (only causal chunks) ----
    for (int ch = 0; ch <= rb; ch++) {
        for (int i = tid; i < 64 * 128; i += 256) {
            int r = i >> 7, c = i & 127;
            bufB[c * 65 + r] = k[(rowbase + ch * 64 + r) * Dd + colbase + c];
        }
        __syncthreads();
        float accs[4][4] = {};
#pragma unroll 4
        for (int kk = 0; kk < 128; kk++) {
            float a[4], bb[4];
#pragma unroll
            for (int i = 0; i < 4; i++) a[i]  = qsT[kk * 65 + ty*4 + i];
#pragma unroll
            for (int j = 0; j < 4; j++) bb[j] = bufB[kk * 65 + tx*4 + j];
#pragma unroll
            for (int i = 0; i < 4; i++)
#pragma unroll
                for (int j = 0; j < 4; j++)
                    accs[i][j] += a[i] * bb[j];
        }
#pragma unroll
        for (int i = 0; i < 4; i++)
#pragma unroll
            for (int j = 0; j < 4; j++)
                sc[(ty*4 + i) * 513 + ch*64 + tx*4 + j] = accs[i][j] * scale;
        __syncthreads();
    }

    // ---- phase 2: causal softmax per row ----
    {
        int warp = tid >> 5, lane = tid & 31;
        int mlim = (rb + 1) * 64;
        for (int rr = 0; rr < 8; rr++) {
            int row = warp * 8 + rr;
            int gr  = r0 + row;                 // last valid key index
            float* srow = sc + row * 513;
            float mx = -1e30f;
            for (int m = lane; m <= gr; m += 32) mx = fmaxf(mx, srow[m]);
#pragma unroll
            for (int o = 16; o > 0; o >>= 1) mx = fmaxf(mx, __shfl_xor_sync(0xffffffffu, mx, o));
            float s = 0.0f;
            for (int m = lane; m <= gr; m += 32) { float e = __expf(srow[m] - mx); srow[m] = e; s += e; }
#pragma unroll
            for (int o = 16; o > 0; o >>= 1) s += __shfl_xor_sync(0xffffffffu, s, o);
            float inv = 1.0f / s;
            for (int m = lane; m < mlim; m += 32) srow[m] = (m <= gr) ? srow[m] * inv : 0.0f;
        }
    }
    __syncthreads();

    // ---- phase 3: att_dot = P @ V ----
    float accd[4][8] = {};
    for (int ch = 0; ch <= rb; ch++) {
        for (int i = tid; i < 64 * 32; i += 256) {
            int r = i >> 5, c = (i & 31) * 4;
            *(float4*)&bufB[r * 128 + c] =
                *(const float4*)&v[(rowbase + ch * 64 + r) * Dd + colbase + c];
        }
        __syncthreads();
#pragma unroll 2
        for (int kk = 0; kk < 64; kk++) {
            float4 v0 = *(const float4*)&bufB[kk * 128 + tx*4];
            float4 v1 = *(const float4*)&bufB[kk * 128 + 64 + tx*4];
            float p[4];
#pragma unroll
            for (int i = 0; i < 4; i++) p[i] = sc[(ty*4 + i) * 513 + ch*64 + kk];
#pragma unroll
            for (int i = 0; i < 4; i++) {
                accd[i][0] += p[i]*v0.x; accd[i][1] += p[i]*v0.y;
                accd[i][2] += p[i]*v0.z; accd[i][3] += p[i]*v0.w;
                accd[i][4] += p[i]*v1.x; accd[i][5] += p[i]*v1.y;
                accd[i][6] += p[i]*v1.z; accd[i][7] += p[i]*v1.w;
            }
        }
        __syncthreads();
    }

    // ---- phase 4: memory retrieval (pre-update state) ----
    {
        size_t mbase = (size_t)bh * (128 * 128);
        for (int i = tid; i < 128 * 32; i += 256)
            *(float4*)&bufB[i * 4] = *(const float4*)&g_mem[mbase + (size_t)i * 4];
        if (tid < 128) z_s[tid] = g_zst[bh * 128 + tid];
        for (int i = tid; i < 64 * 128; i += 256) {   // qsT -> sigma(q) in place
            int r = i >> 7, c = i & 127;
            qsT[c * 65 + r] = elu1(qsT[c * 65 + r]);
        }
    }
    __syncthreads();

    float accn[4][8] = {};
    float den[4] = {};
#pragma unroll 2
    for (int kk = 0; kk < 128; kk++) {
        float a[4];
#pragma unroll
        for (int i = 0; i < 4; i++) a[i] = qsT[kk * 65 + ty*4 + i];
        float4 m0 = *(const float4*)&bufB[kk * 128 + tx*4];
        float4 m1 = *(const float4*)&bufB[kk * 128 + 64 + tx*4];
        float zk = z_s[kk];
#pragma unroll
        for (int i = 0; i < 4; i++) {
            den[i] += a[i] * zk;
            accn[i][0] += a[i]*m0.x; accn[i][1] += a[i]*m0.y;
            accn[i][2] += a[i]*m0.z; accn[i][3] += a[i]*m0.w;
            accn[i][4] += a[i]*m1.x; accn[i][5] += a[i]*m1.y;
            accn[i][6] += a[i]*m1.z; accn[i][7] += a[i]*m1.w;
        }
    }

    // ---- combine: out = gate*att_mem + (1-gate)*att_dot, write ----
#pragma unroll
    for (int i = 0; i < 4; i++) {
        size_t grow = rowbase + r0 + ty*4 + i;
        float invd = 1.0f / den[i];
#pragma unroll
        for (int g = 0; g < 2; g++) {
            int c0 = g*64 + tx*4;
            float4 o;
#pragma unroll
            for (int j = 0; j < 4; j++) {
                int col = c0 + j;
                float gt = 1.0f / (1.0f + __expf(-betas[h * 128 + col]));
                float val = gt * (accn[i][g*4+j] * invd) + (1.0f - gt) * accd[i][g*4+j];
                ((float*)&o)[j] = val;
            }
            *(float4*)&att[grow * Dd + colbase + c0] = o;
        }
    }
    __syncthreads();   // everyone done with sc before aliasing it as skT

    // ---- phase 4b: v_del = v - sigma(k)@mem / sigma(k)@z  (own rows) ----
    for (int i = tid; i < 64 * 128; i += 256) {
        int r = i >> 7, c = i & 127;
        skT[c * 65 + r] = elu1(k[(rowbase + r0 + r) * Dd + colbase + c]);
    }
    __syncthreads();

    float accv[4][8] = {};
    float denk[4] = {};
#pragma unroll 2
    for (int kk = 0; kk < 128; kk++) {
        float a[4];
#pragma unroll
        for (int i = 0; i < 4; i++) a[i] = skT[kk * 65 + ty*4 + i];
        float4 m0 = *(const float4*)&bufB[kk * 128 + tx*4];
        float4 m1 = *(const float4*)&bufB[kk * 128 + 64 + tx*4];
        float zk = z_s[kk];
#pragma unroll
        for (int i = 0; i < 4; i++) {
            denk[i] += a[i] * zk;
            accv[i][0] += a[i]*m0.x; accv[i][1] += a[i]*m0.y;
            accv[i][2] += a[i]*m0.z; accv[i][3] += a[i]*m0.w;
            accv[i][4] += a[i]*m1.x; accv[i][5] += a[i]*m1.y;
            accv[i][6] += a[i]*m1.z; accv[i][7] += a[i]*m1.w;
        }
    }
#pragma unroll
    for (int i = 0; i < 4; i++) {
        size_t grow = rowbase + r0 + ty*4 + i;
        float invd = 1.0f / denk[i];
#pragma unroll
        for (int g = 0; g < 2; g++) {
            int c0 = g*64 + tx*4;
            float4 vv = *(const float4*)&v[grow * Dd + colbase + c0];
            float4 o;
            o.x = vv.x - accv[i][g*4+0] * invd;
            o.y = vv.y - accv[i][g*4+1] * invd;
            o.z = vv.z - accv[i][g*4+2] * invd;
            o.w = vv.w - accv[i][g*4+3] * invd;
            *(float4*)&g_vdel[((size_t)bh * Ll + r0 + ty*4 + i) * 128 + c0] = o;
        }
    }
}

// ---------------- attention kernel B: mem += sk^T @ v_del ; z += sum(sk) ----------------
__global__ void __launch_bounds__(256)
attn_seg_b(const float* __restrict__ k, int seg)
{
    __shared__ float sk4[4][128];
    __shared__ float vd4[4][128];
    const int tid = threadIdx.x;
    const int tx = tid & 15, ty = tid >> 4;
    const int bh = blockIdx.x;
    const int b = bh >> 4, h = bh & 15;
    const size_t rowbase = (size_t)(b * Ss + seg * Ll);

    float acc[8][8] = {};
    float zacc[8] = {};

    for (int l0 = 0; l0 < Ll; l0 += 4) {
#pragma unroll
        for (int t = 0; t < 2; t++) {
            int idx = tid + t * 256;
            int l = idx >> 7, c = idx & 127;
            sk4[l][c] = elu1(k[(rowbase + l0 + l) * Dd + h * 128 + c]);
        }
#pragma unroll
        for (int t = 0; t < 2; t++) {
            int idx = tid + t * 256;
            int l = idx >> 7, c = idx & 127;
            vd4[l][c] = g_vdel[((size_t)bh * Ll + l0 + l) * 128 + c];
        }
        __syncthreads();
#pragma unroll
        for (int l = 0; l < 4; l++) {
            float a[8];
#pragma unroll
            for (int i = 0; i < 8; i++) a[i] = sk4[l][ty*8 + i];
            float4 b0 = *(const float4*)&vd4[l][tx*4];
            float4 b1 = *(const float4*)&vd4[l][64 + tx*4];
            float bb[8] = {b0.x, b0.y, b0.z, b0.w, b1.x, b1.y, b1.z, b1.w};
#pragma unroll
            for (int i = 0; i < 8; i++) {
                zacc[i] += a[i];
#pragma unroll
                for (int j = 0; j < 8; j++)
                    acc[i][j] += a[i] * bb[j];
            }
        }
        __syncthreads();
    }

    size_t mbase = (size_t)bh * 128 * 128;
#pragma unroll
    for (int i = 0; i < 8; i++) {
        int dk = ty*8 + i;
#pragma unroll
        for (int g = 0; g < 2; g++) {
            int dv = g*64 + tx*4;
            float4* p = (float4*)&g_mem[mbase + (size_t)dk * 128 + dv];
            float4 cur = *p;
            cur.x += acc[i][g*4+0]; cur.y += acc[i][g*4+1];
            cur.z += acc[i][g*4+2]; cur.w += acc[i][g*4+3];
            *p = cur;
        }
        if (tx == 0) g_zst[bh * 128 + dk] += zacc[i];
    }
}

// ---------------- residual + LayerNorm ----------------
__global__ void __launch_bounds__(256)
resid_ln(const float* __restrict__ h2, const float* __restrict__ x,
         const float* __restrict__ w, const float* __restrict__ bsh,
         float* __restrict__ out)
{
    __shared__ float ybuf[Dd];
    __shared__ float red[17];
    const int row = blockIdx.x;
    const int tid = threadIdx.x;
    const float* hr = h2 + (size_t)row * Dd;
    const float* xr = x  + (size_t)row * Dd;

    float s = 0.0f, sq = 0.0f;
    for (int c = tid; c < Dd; c += 256) {
        float yv = hr[c] + xr[c];
        ybuf[c] = yv;
        s += yv; sq += yv * yv;
    }
#pragma unroll
    for (int o = 16; o > 0; o >>= 1) {
        s  += __shfl_xor_sync(0xffffffffu, s, o);
        sq += __shfl_xor_sync(0xffffffffu, sq, o);
    }
    int warp = tid >> 5, lane = tid & 31;
    if (lane == 0) { red[warp] = s; red[8 + warp] = sq; }
    __syncthreads();
    if (tid == 0) {
        float S = 0, SQ = 0;
        for (int i = 0; i < 8; i++) { S += red[i]; SQ += red[8 + i]; }
        red[0] = S; red[1] = SQ;
    }
    __syncthreads();
    float mu  = red[0] / (float)Dd;
    float var = red[1] / (float)Dd - mu * mu;
    float inv = rsqrtf(var + 1e-5f);
    for (int c = tid; c < Dd; c += 256)
        out[(size_t)row * Dd + c] = (ybuf[c] - mu) * inv * w[c] + bsh[c];
}

// ---------------- launch ----------------
extern "C" void kernel_launch(void* const* d_in, const int* in_sizes, int n_in,
                              void* d_out, int out_size)
{
    const float* x    = (const float*)d_in[0];
    const float* Wq   = (const float*)d_in[1];
    const float* bq   = (const float*)d_in[2];
    const float* Wk   = (const float*)d_in[3];
    const float* bk   = (const float*)d_in[4];
    const float* Wv   = (const float*)d_in[5];
    const float* bv   = (const float*)d_in[6];
    const float* Wo   = (const float*)d_in[7];
    const float* bo   = (const float*)d_in[8];
    const float* beta = (const float*)d_in[9];
    const float* W1   = (const float*)d_in[10];
    const float* b1   = (const float*)d_in[11];
    const float* W2   = (const float*)d_in[12];
    const float* b2   = (const float*)d_in[13];
    const float* lnw  = (const float*)d_in[14];
    const float* lnb  = (const float*)d_in[15];
    float* out = (float*)d_out;

    float *pq, *pk, *pv, *patt, *pa, *ph1, *ph2;
    cudaGetSymbolAddress((void**)&pq,   g_q);
    cudaGetSymbolAddress((void**)&pk,   g_k);
    cudaGetSymbolAddress((void**)&pv,   g_v);
    cudaGetSymbolAddress((void**)&patt, g_att);
    cudaGetSymbolAddress((void**)&pa,   g_a);
    cudaGetSymbolAddress((void**)&ph1,  g_h1);
    cudaGetSymbolAddress((void**)&ph2,  g_h2);

    cudaFuncSetAttribute(attn_seg_a, cudaFuncAttributeMaxDynamicSharedMemorySize, SMEM_A_BYTES);

    init_state_kernel<<<2048, 256>>>();

    dim3 gQKV(2048 / 128, BSr / 128);             // (16, 64)
    gemm_kernel<0><<<gQKV, 256>>>(x, Wq, bq, pq, BSr, 2048, 2048);
    gemm_kernel<0><<<gQKV, 256>>>(x, Wk, bk, pk, BSr, 2048, 2048);
    gemm_kernel<0><<<gQKV, 256>>>(x, Wv, bv, pv, BSr, 2048, 2048);

    for (int seg = 0; seg < NSEGc; seg++) {
        attn_seg_a<<<dim3(8, 32), 256, SMEM_A_BYTES>>>(pq, pk, pv, beta, patt, seg);
        attn_seg_b<<<32, 256>>>(pk, seg);
    }

    gemm_kernel<0><<<gQKV, 256>>>(patt, Wo, bo, pa, BSr, 2048, 2048);

    dim3 gW1(DH / 128, BSr / 128);                // (64, 64)
    gemm_kernel<1><<<gW1, 256>>>(pa, W1, b1, ph1, BSr, DH, 2048);
    gemm_kernel<0><<<gQKV, 256>>>(ph1, W2, b2, ph2, BSr, 2048, DH);

    resid_ln<<<BSr, 256>>>(ph2, x, lnw, lnb, out);
}

// round 3
// speedup vs baseline: 2.0518x; 2.0518x over previous
#include <cuda_runtime.h>
#include <cuda_bf16.h>
#include <cstdint>

// ---------------- problem constants ----------------
#define Bb   2
#define Ss   4096
#define Dd   2048
#define Hh   16
#define DH   8192
#define Ll   512
#define NSEGc 8
#define BSr  (Bb*Ss)      // 8192 rows
#define BHn  (Bb*Hh)      // 32 (batch,head) pairs

// ---------------- scratch (device globals; no allocs allowed) ----------------
__device__ float g_q  [(size_t)BSr*Dd];
__device__ float g_k  [(size_t)BSr*Dd];
__device__ float g_v  [(size_t)BSr*Dd];
__device__ float g_h2 [(size_t)BSr*Dd];
__device__ __nv_bfloat16 g_x_hi [(size_t)BSr*Dd];
__device__ __nv_bfloat16 g_x_lo [(size_t)BSr*Dd];
__device__ __nv_bfloat16 g_att_hi[(size_t)BSr*Dd];
__device__ __nv_bfloat16 g_att_lo[(size_t)BSr*Dd];
__device__ __nv_bfloat16 g_a_hi [(size_t)BSr*Dd];
__device__ __nv_bfloat16 g_a_lo [(size_t)BSr*Dd];
__device__ __nv_bfloat16 g_h1_hi[(size_t)BSr*DH];
__device__ __nv_bfloat16 g_h1_lo[(size_t)BSr*DH];
// transposed bf16 weights [N,K]
__device__ __nv_bfloat16 g_wq_hi[(size_t)Dd*Dd], g_wq_lo[(size_t)Dd*Dd];
__device__ __nv_bfloat16 g_wk_hi[(size_t)Dd*Dd], g_wk_lo[(size_t)Dd*Dd];
__device__ __nv_bfloat16 g_wv_hi[(size_t)Dd*Dd], g_wv_lo[(size_t)Dd*Dd];
__device__ __nv_bfloat16 g_wo_hi[(size_t)Dd*Dd], g_wo_lo[(size_t)Dd*Dd];
__device__ __nv_bfloat16 g_w1_hi[(size_t)DH*Dd], g_w1_lo[(size_t)DH*Dd];
__device__ __nv_bfloat16 g_w2_hi[(size_t)Dd*DH], g_w2_lo[(size_t)Dd*DH];
// attention state
__device__ float g_mem [BHn*128*128];
__device__ float g_zst [BHn*128];
__device__ float g_vdel[BHn*Ll*128];

// ---------------- helpers ----------------
__device__ __forceinline__ float gelu_exact(float x) {
    return 0.5f * x * (1.0f + erff(x * 0.70710678118654752440f));
}
__device__ __forceinline__ float elu1(float x) {
    return (x > 0.0f) ? (x + 1.0f) : __expf(x);
}
__device__ __forceinline__ void split2(float v, __nv_bfloat16& hi, __nv_bfloat16& lo) {
    hi = __float2bfloat16(v);
    lo = __float2bfloat16(v - __bfloat162float(hi));
}
__device__ __forceinline__ uint32_t smem_u32(const void* p) {
    uint32_t a;
    asm("{ .reg .u64 t; cvta.to.shared.u64 t, %1; cvt.u32.u64 %0, t; }" : "=r"(a) : "l"(p));
    return a;
}

// ---------------- mma / ldmatrix / cp.async primitives (sm_80-level PTX) ----------------
__device__ __forceinline__ void mma16816(float* c, const uint32_t* a, const uint32_t* b) {
    asm volatile(
        "mma.sync.aligned.m16n8k16.row.col.f32.bf16.bf16.f32 "
        "{%0,%1,%2,%3}, {%4,%5,%6,%7}, {%8,%9}, {%0,%1,%2,%3};"
        : "+f"(c[0]), "+f"(c[1]), "+f"(c[2]), "+f"(c[3])
        : "r"(a[0]), "r"(a[1]), "r"(a[2]), "r"(a[3]), "r"(b[0]), "r"(b[1]));
}
__device__ __forceinline__ void ldsm4(uint32_t addr, uint32_t* r) {
    asm volatile("ldmatrix.sync.aligned.m8n8.x4.shared.b16 {%0,%1,%2,%3}, [%4];"
                 : "=r"(r[0]), "=r"(r[1]), "=r"(r[2]), "=r"(r[3]) : "r"(addr));
}
__device__ __forceinline__ void cp_async16(uint32_t saddr, const void* gaddr) {
    asm volatile("cp.async.cg.shared.global [%0], [%1], 16;" :: "r"(saddr), "l"(gaddr));
}
#define CP_COMMIT() asm volatile("cp.async.commit_group;" ::: "memory")
#define CP_WAIT2()  asm volatile("cp.async.wait_group 2;" ::: "memory")

// smem tile layout: 128 rows x 64 bytes (32 bf16), XOR swizzle on 16B chunks
__device__ __forceinline__ uint32_t swz_off(int row, int kbyte) {
    return (uint32_t)(row * 64 + ((((kbyte) >> 4) ^ ((row >> 1) & 3)) << 4));
}

// ---------------- state init ----------------
__global__ void init_state_kernel() {
    int i = blockIdx.x * blockDim.x + threadIdx.x;
    if (i < BHn*128*128) g_mem[i] = 0.0f;
    if (i < BHn*128)     g_zst[i] = 1.0f / 128.0f;
}

// ---------------- elementwise fp32 -> bf16 hi/lo split ----------------
__global__ void __launch_bounds__(256)
conv_split(const float* __restrict__ src, __nv_bfloat16* __restrict__ hi,
           __nv_bfloat16* __restrict__ lo)
{
    size_t i4 = (size_t)blockIdx.x * 256 + threadIdx.x;
    float4 v = ((const float4*)src)[i4];
    __nv_bfloat16 h, l;
    size_t o = i4 * 4;
    split2(v.x, h, l); hi[o+0] = h; lo[o+0] = l;
    split2(v.y, h, l); hi[o+1] = h; lo[o+1] = l;
    split2(v.z, h, l); hi[o+2] = h; lo[o+2] = l;
    split2(v.w, h, l); hi[o+3] = h; lo[o+3] = l;
}

// ---------------- weight convert + transpose: W[K,N] -> T[N,K] bf16 hi/lo ----------------
__global__ void __launch_bounds__(256)
convt_kernel(const float* __restrict__ W, __nv_bfloat16* __restrict__ Thi,
             __nv_bfloat16* __restrict__ Tlo, int K, int N)
{
    __shared__ float t[64][65];
    const int tid = threadIdx.x;
    const int n0 = blockIdx.x * 64, k0 = blockIdx.y * 64;
    for (int i = tid; i < 64*64; i += 256) {
        int r = i >> 6, c = i & 63;
        t[r][c] = W[(size_t)(k0 + r) * N + n0 + c];
    }
    __syncthreads();
    for (int i = tid; i < 64*64; i += 256) {
        int rn = i >> 6, ck = i & 63;
        float v = t[ck][rn];
        __nv_bfloat16 h, l; split2(v, h, l);
        size_t o = (size_t)(n0 + rn) * K + k0 + ck;
        Thi[o] = h; Tlo[o] = l;
    }
}

// ---------------- tensor-core GEMM via mma.sync: C[M,N] = A[M,K] @ Bt[N,K]^T + bias ----
// bf16 split-2 operands (3 accumulating MMAs), fp32 register accumulation.
// 128x128 CTA tile, BK=32, 4-stage cp.async pipeline, 8 warps (4m x 2n), warp = 32x64.
// EPI: 0 = fp32 out; 1 = bf16 hi/lo out; 2 = GELU then bf16 hi/lo out.
#define GEMM_STAGES 4
#define GEMM_STAGE_BYTES 32768                // 4 planes * 128 rows * 64B
#define GEMM_SMEM_BYTES  (GEMM_STAGES * GEMM_STAGE_BYTES)

template<int EPI>
__global__ void __launch_bounds__(256)
gemm_mma(const __nv_bfloat16* __restrict__ Ahi, const __nv_bfloat16* __restrict__ Alo,
         const __nv_bfloat16* __restrict__ Bhi, const __nv_bfloat16* __restrict__ Blo,
         const float* __restrict__ bias,
         float* __restrict__ Cf, __nv_bfloat16* __restrict__ Chi,
         __nv_bfloat16* __restrict__ Clo, int M, int N, int K)
{
    extern __shared__ char sm_raw[];
    const uint32_t smem = smem_u32(sm_raw);

    const int tid  = threadIdx.x;
    const int lane = tid & 31;
    const int w    = tid >> 5;
    const int wm   = w & 3;          // 4 m-groups of 32 rows
    const int wn   = w >> 2;         // 2 n-groups of 64 cols
    const size_t bm = (size_t)blockIdx.y * 128;
    const size_t bn = (size_t)blockIdx.x * 128;
    const int KT = K >> 5;

    // per-lane ldmatrix source coordinates
    const int a_row = wm * 32 + (lane & 7) + ((lane >> 3) & 1) * 8;
    const int a_kb  = ((lane >> 4) & 1) * 16;
    const int b_row = wn * 64 + (lane & 7) + ((lane >> 4) & 1) * 8;
    const int b_kb  = ((lane >> 3) & 1) * 16;

    // per-thread cp.async assignments (2 chunk sets per plane)
    const int r0c = tid >> 2, j0 = tid & 3;
    const int r1c = (tid + 256) >> 2, j1 = (tid + 256) & 3;
    const uint32_t so0 = swz_off(r0c, j0 * 16);
    const uint32_t so1 = swz_off(r1c, j1 * 16);

    float acc[2][8][4];
#pragma unroll
    for (int i = 0; i < 2; i++)
#pragma unroll
        for (int j = 0; j < 8; j++)
#pragma unroll
            for (int q = 0; q < 4; q++) acc[i][j][q] = 0.0f;

    auto load_stage = [&](int st, int itk) {
        const uint32_t sb = smem + st * GEMM_STAGE_BYTES;
        const size_t k0 = (size_t)itk * 32;
        const size_t gA0 = (bm + r0c) * (size_t)K + k0 + j0 * 8;
        const size_t gA1 = (bm + r1c) * (size_t)K + k0 + j1 * 8;
        const size_t gB0 = (bn + r0c) * (size_t)K + k0 + j0 * 8;
        const size_t gB1 = (bn + r1c) * (size_t)K + k0 + j1 * 8;
        cp_async16(sb +         so0, Ahi + gA0);
        cp_async16(sb +         so1, Ahi + gA1);
        cp_async16(sb +  8192 + so0, Alo + gA0);
        cp_async16(sb +  8192 + so1, Alo + gA1);
        cp_async16(sb + 16384 + so0, Bhi + gB0);
        cp_async16(sb + 16384 + so1, Bhi + gB1);
        cp_async16(sb + 24576 + so0, Blo + gB0);
        cp_async16(sb + 24576 + so1, Blo + gB1);
    };

    // prologue: stages 0..2
#pragma unroll
    for (int s = 0; s < GEMM_STAGES - 1; s++) {
        load_stage(s, s);
        CP_COMMIT();
    }

    for (int it = 0; it < KT; it++) {
        CP_WAIT2();
        __syncthreads();
        if (it + GEMM_STAGES - 1 < KT)
            load_stage((it + GEMM_STAGES - 1) & (GEMM_STAGES - 1), it + GEMM_STAGES - 1);
        CP_COMMIT();

        const uint32_t sb = smem + (it & (GEMM_STAGES - 1)) * GEMM_STAGE_BYTES;
#pragma unroll
        for (int ks = 0; ks < 2; ks++) {
            uint32_t ah[2][4], al[2][4];
#pragma unroll
            for (int mi = 0; mi < 2; mi++) {
                const uint32_t ra = sb + swz_off(a_row + mi * 16, ks * 32 + a_kb);
                ldsm4(ra, ah[mi]);
                ldsm4(ra + 8192, al[mi]);
            }
            uint32_t bh[8][2], bl[8][2];
#pragma unroll
            for (int nt = 0; nt < 4; nt++) {
                uint32_t t4[4];
                const uint32_t rb = sb + 16384 + swz_off(b_row + nt * 16, ks * 32 + b_kb);
                ldsm4(rb, t4);
                bh[2*nt][0] = t4[0]; bh[2*nt][1] = t4[1];
                bh[2*nt+1][0] = t4[2]; bh[2*nt+1][1] = t4[3];
                ldsm4(rb + 8192, t4);
                bl[2*nt][0] = t4[0]; bl[2*nt][1] = t4[1];
                bl[2*nt+1][0] = t4[2]; bl[2*nt+1][1] = t4[3];
            }
#pragma unroll
            for (int mi = 0; mi < 2; mi++) {
#pragma unroll
                for (int ni = 0; ni < 8; ni++) {
                    mma16816(acc[mi][ni], ah[mi], bh[ni]);
                    mma16816(acc[mi][ni], ah[mi], bl[ni]);
                    mma16816(acc[mi][ni], al[mi], bh[ni]);
                }
            }
        }
    }

    // ---- epilogue ----
    const int rl = lane >> 2, cl = (lane & 3) * 2;
#pragma unroll
    for (int mi = 0; mi < 2; mi++) {
#pragma unroll
        for (int ni = 0; ni < 8; ni++) {
            const float* c = acc[mi][ni];
            const size_t row0 = bm + wm * 32 + mi * 16 + rl;
            const size_t col  = bn + wn * 64 + ni * 8 + cl;
            const float b0 = bias[col], b1 = bias[col + 1];
            float v00 = c[0] + b0, v01 = c[1] + b1;
            float v10 = c[2] + b0, v11 = c[3] + b1;
            if (EPI == 2) {
                v00 = gelu_exact(v00); v01 = gelu_exact(v01);
                v10 = gelu_exact(v10); v11 = gelu_exact(v11);
            }
            if (EPI == 0) {
                *(float2*)(Cf + row0 * (size_t)N + col)       = make_float2(v00, v01);
                *(float2*)(Cf + (row0 + 8) * (size_t)N + col) = make_float2(v10, v11);
            } else {
                __nv_bfloat16 h0, l0, h1, l1;
                split2(v00, h0, l0); split2(v01, h1, l1);
                __nv_bfloat162 hh, ll;
                hh.x = h0; hh.y = h1; ll.x = l0; ll.y = l1;
                *(__nv_bfloat162*)(Chi + row0 * (size_t)N + col) = hh;
                *(__nv_bfloat162*)(Clo + row0 * (size_t)N + col) = ll;
                split2(v10, h0, l0); split2(v11, h1, l1);
                hh.x = h0; hh.y = h1; ll.x = l0; ll.y = l1;
                *(__nv_bfloat162*)(Chi + (row0 + 8) * (size_t)N + col) = hh;
                *(__nv_bfloat162*)(Clo + (row0 + 8) * (size_t)N + col) = ll;
            }
        }
    }
}

// ---------------- attention kernel A (per segment) ----------------
#define SM_QST 0
#define SM_BUF (128*65)
#define SM_SC  (128*65 + 128*128)
#define SM_Z   (128*65 + 128*128 + 64*513)
#define SMEM_A_FLOATS (128*65 + 128*128 + 64*513 + 128)
#define SMEM_A_BYTES  (SMEM_A_FLOATS * 4)

__global__ void __launch_bounds__(256)
attn_seg_a(const float* __restrict__ q, const float* __restrict__ k,
           const float* __restrict__ v, const float* __restrict__ betas,
           __nv_bfloat16* __restrict__ att_hi, __nv_bfloat16* __restrict__ att_lo, int seg)
{
    extern __shared__ float sm[];
    float* qsT  = sm + SM_QST;
    float* bufB = sm + SM_BUF;
    float* sc   = sm + SM_SC;
    float* skT  = sm + SM_SC;
    float* z_s  = sm + SM_Z;

    const int tid = threadIdx.x;
    const int tx = tid & 15, ty = tid >> 4;
    const int rb = blockIdx.x;
    const int bh = blockIdx.y;
    const int b  = bh >> 4, h = bh & 15;
    const int r0 = rb * 64;
    const size_t rowbase = (size_t)(b * Ss + seg * Ll);
    const int colbase = h * 128;

    for (int i = tid; i < 64 * 128; i += 256) {
        int r = i >> 7, c = i & 127;
        qsT[c * 65 + r] = q[(rowbase + r0 + r) * Dd + colbase + c];
    }
    __syncthreads();

    const float scale = 0.088388347648318447f;

    for (int ch = 0; ch <= rb; ch++) {
        for (int i = tid; i < 64 * 128; i += 256) {
            int r = i >> 7, c = i & 127;
            bufB[c * 65 + r] = k[(rowbase + ch * 64 + r) * Dd + colbase + c];
        }
        __syncthreads();
        float accs[4][4] = {};
#pragma unroll 4
        for (int kk = 0; kk < 128; kk++) {
            float a[4], bb[4];
#pragma unroll
            for (int i = 0; i < 4; i++) a[i]  = qsT[kk * 65 + ty*4 + i];
#pragma unroll
            for (int j = 0; j < 4; j++) bb[j] = bufB[kk * 65 + tx*4 + j];
#pragma unroll
            for (int i = 0; i < 4; i++)
#pragma unroll
                for (int j = 0; j < 4; j++)
                    accs[i][j] += a[i] * bb[j];
        }
#pragma unroll
        for (int i = 0; i < 4; i++)
#pragma unroll
            for (int j = 0; j < 4; j++)
                sc[(ty*4 + i) * 513 + ch*64 + tx*4 + j] = accs[i][j] * scale;
        __syncthreads();
    }

    {
        int warp = tid >> 5, lane = tid & 31;
        int mlim = (rb + 1) * 64;
        for (int rr = 0; rr < 8; rr++) {
            int row = warp * 8 + rr;
            int gr  = r0 + row;
            float* srow = sc + row * 513;
            float mx = -1e30f;
            for (int m = lane; m <= gr; m += 32) mx = fmaxf(mx, srow[m]);
#pragma unroll
            for (int o = 16; o > 0; o >>= 1) mx = fmaxf(mx, __shfl_xor_sync(0xffffffffu, mx, o));
            float s = 0.0f;
            for (int m = lane; m <= gr; m += 32) { float e = __expf(srow[m] - mx); srow[m] = e; s += e; }
#pragma unroll
            for (int o = 16; o > 0; o >>= 1) s += __shfl_xor_sync(0xffffffffu, s, o);
            float inv = 1.0f / s;
            for (int m = lane; m < mlim; m += 32) srow[m] = (m <= gr) ? srow[m] * inv : 0.0f;
        }
    }
    __syncthreads();

    float accd[4][8] = {};
    for (int ch = 0; ch <= rb; ch++) {
        for (int i = tid; i < 64 * 32; i += 256) {
            int r = i >> 5, c = (i & 31) * 4;
            *(float4*)&bufB[r * 128 + c] =
                *(const float4*)&v[(rowbase + ch * 64 + r) * Dd + colbase + c];
        }
        __syncthreads();
#pragma unroll 2
        for (int kk = 0; kk < 64; kk++) {
            float4 v0 = *(const float4*)&bufB[kk * 128 + tx*4];
            float4 v1 = *(const float4*)&bufB[kk * 128 + 64 + tx*4];
            float p[4];
#pragma unroll
            for (int i = 0; i < 4; i++) p[i] = sc[(ty*4 + i) * 513 + ch*64 + kk];
#pragma unroll
            for (int i = 0; i < 4; i++) {
                accd[i][0] += p[i]*v0.x; accd[i][1] += p[i]*v0.y;
                accd[i][2] += p[i]*v0.z; accd[i][3] += p[i]*v0.w;
                accd[i][4] += p[i]*v1.x; accd[i][5] += p[i]*v1.y;
                accd[i][6] += p[i]*v1.z; accd[i][7] += p[i]*v1.w;
            }
        }
        __syncthreads();
    }

    {
        size_t mbase = (size_t)bh * (128 * 128);
        for (int i = tid; i < 128 * 32; i += 256)
            *(float4*)&bufB[i * 4] = *(const float4*)&g_mem[mbase + (size_t)i * 4];
        if (tid < 128) z_s[tid] = g_zst[bh * 128 + tid];
        for (int i = tid; i < 64 * 128; i += 256) {
            int r = i >> 7, c = i & 127;
            qsT[c * 65 + r] = elu1(qsT[c * 65 + r]);
        }
    }
    __syncthreads();

    float accn[4][8] = {};
    float den[4] = {};
#pragma unroll 2
    for (int kk = 0; kk < 128; kk++) {
        float a[4];
#pragma unroll
        for (int i = 0; i < 4; i++) a[i] = qsT[kk * 65 + ty*4 + i];
        float4 m0 = *(const float4*)&bufB[kk * 128 + tx*4];
        float4 m1 = *(const float4*)&bufB[kk * 128 + 64 + tx*4];
        float zk = z_s[kk];
#pragma unroll
        for (int i = 0; i < 4; i++) {
            den[i] += a[i] * zk;
            accn[i][0] += a[i]*m0.x; accn[i][1] += a[i]*m0.y;
            accn[i][2] += a[i]*m0.z; accn[i][3] += a[i]*m0.w;
            accn[i][4] += a[i]*m1.x; accn[i][5] += a[i]*m1.y;
            accn[i][6] += a[i]*m1.z; accn[i][7] += a[i]*m1.w;
        }
    }

#pragma unroll
    for (int i = 0; i < 4; i++) {
        size_t grow = rowbase + r0 + ty*4 + i;
        float invd = 1.0f / den[i];
#pragma unroll
        for (int g = 0; g < 2; g++) {
            int c0 = g*64 + tx*4;
#pragma unroll
            for (int j = 0; j < 4; j++) {
                int col = c0 + j;
                float gt = 1.0f / (1.0f + __expf(-betas[h * 128 + col]));
                float val = gt * (accn[i][g*4+j] * invd) + (1.0f - gt) * accd[i][g*4+j];
                __nv_bfloat16 hb, lb; split2(val, hb, lb);
                att_hi[grow * Dd + colbase + col] = hb;
                att_lo[grow * Dd + colbase + col] = lb;
            }
        }
    }
    __syncthreads();

    for (int i = tid; i < 64 * 128; i += 256) {
        int r = i >> 7, c = i & 127;
        skT[c * 65 + r] = elu1(k[(rowbase + r0 + r) * Dd + colbase + c]);
    }
    __syncthreads();

    float accv[4][8] = {};
    float denk[4] = {};
#pragma unroll 2
    for (int kk = 0; kk < 128; kk++) {
        float a[4];
#pragma unroll
        for (int i = 0; i < 4; i++) a[i] = skT[kk * 65 + ty*4 + i];
        float4 m0 = *(const float4*)&bufB[kk * 128 + tx*4];
        float4 m1 = *(const float4*)&bufB[kk * 128 + 64 + tx*4];
        float zk = z_s[kk];
#pragma unroll
        for (int i = 0; i < 4; i++) {
            denk[i] += a[i] * zk;
            accv[i][0] += a[i]*m0.x; accv[i][1] += a[i]*m0.y;
            accv[i][2] += a[i]*m0.z; accv[i][3] += a[i]*m0.w;
            accv[i][4] += a[i]*m1.x; accv[i][5] += a[i]*m1.y;
            accv[i][6] += a[i]*m1.z; accv[i][7] += a[i]*m1.w;
        }
    }
#pragma unroll
    for (int i = 0; i < 4; i++) {
        size_t grow = rowbase + r0 + ty*4 + i;
        float invd = 1.0f / denk[i];
#pragma unroll
        for (int g = 0; g < 2; g++) {
            int c0 = g*64 + tx*4;
            float4 vv = *(const float4*)&v[grow * Dd + colbase + c0];
            float4 o;
            o.x = vv.x - accv[i][g*4+0] * invd;
            o.y = vv.y - accv[i][g*4+1] * invd;
            o.z = vv.z - accv[i][g*4+2] * invd;
            o.w = vv.w - accv[i][g*4+3] * invd;
            *(float4*)&g_vdel[((size_t)bh * Ll + r0 + ty*4 + i) * 128 + c0] = o;
        }
    }
}

// ---------------- attention kernel B: mem += sk^T @ v_del ; z += sum(sk) ----------------
__global__ void __launch_bounds__(256)
attn_seg_b(const float* __restrict__ k, int seg)
{
    __shared__ float sk4[4][128];
    __shared__ float vd4[4][128];
    const int tid = threadIdx.x;
    const int tx = tid & 15, ty = tid >> 4;
    const int bh = blockIdx.x;
    const int b = bh >> 4, h = bh & 15;
    const size_t rowbase = (size_t)(b * Ss + seg * Ll);

    float acc[8][8] = {};
    float zacc[8] = {};

    for (int l0 = 0; l0 < Ll; l0 += 4) {
#pragma unroll
        for (int t = 0; t < 2; t++) {
            int idx = tid + t * 256;
            int l = idx >> 7, c = idx & 127;
            sk4[l][c] = elu1(k[(rowbase + l0 + l) * Dd + h * 128 + c]);
        }
#pragma unroll
        for (int t = 0; t < 2; t++) {
            int idx = tid + t * 256;
            int l = idx >> 7, c = idx & 127;
            vd4[l][c] = g_vdel[((size_t)bh * Ll + l0 + l) * 128 + c];
        }
        __syncthreads();
#pragma unroll
        for (int l = 0; l < 4; l++) {
            float a[8];
#pragma unroll
            for (int i = 0; i < 8; i++) a[i] = sk4[l][ty*8 + i];
            float4 b0 = *(const float4*)&vd4[l][tx*4];
            float4 b1 = *(const float4*)&vd4[l][64 + tx*4];
            float bb[8] = {b0.x, b0.y, b0.z, b0.w, b1.x, b1.y, b1.z, b1.w};
#pragma unroll
            for (int i = 0; i < 8; i++) {
                zacc[i] += a[i];
#pragma unroll
                for (int j = 0; j < 8; j++)
                    acc[i][j] += a[i] * bb[j];
            }
        }
        __syncthreads();
    }

    size_t mbase = (size_t)bh * 128 * 128;
#pragma unroll
    for (int i = 0; i < 8; i++) {
        int dk = ty*8 + i;
#pragma unroll
        for (int g = 0; g < 2; g++) {
            int dv = g*64 + tx*4;
            float4* p = (float4*)&g_mem[mbase + (size_t)dk * 128 + dv];
            float4 cur = *p;
            cur.x += acc[i][g*4+0]; cur.y += acc[i][g*4+1];
            cur.z += acc[i][g*4+2]; cur.w += acc[i][g*4+3];
            *p = cur;
        }
        if (tx == 0) g_zst[bh * 128 + dk] += zacc[i];
    }
}

// ---------------- residual + LayerNorm ----------------
__global__ void __launch_bounds__(256)
resid_ln(const float* __restrict__ h2, const float* __restrict__ x,
         const float* __restrict__ w, const float* __restrict__ bsh,
         float* __restrict__ out)
{
    __shared__ float ybuf[Dd];
    __shared__ float red[17];
    const int row = blockIdx.x;
    const int tid = threadIdx.x;
    const float* hr = h2 + (size_t)row * Dd;
    const float* xr = x  + (size_t)row * Dd;

    float s = 0.0f, sq = 0.0f;
    for (int c = tid; c < Dd; c += 256) {
        float yv = hr[c] + xr[c];
        ybuf[c] = yv;
        s += yv; sq += yv * yv;
    }
#pragma unroll
    for (int o = 16; o > 0; o >>= 1) {
        s  += __shfl_xor_sync(0xffffffffu, s, o);
        sq += __shfl_xor_sync(0xffffffffu, sq, o);
    }
    int warp = tid >> 5, lane = tid & 31;
    if (lane == 0) { red[warp] = s; red[8 + warp] = sq; }
    __syncthreads();
    if (tid == 0) {
        float S = 0, SQ = 0;
        for (int i = 0; i < 8; i++) { S += red[i]; SQ += red[8 + i]; }
        red[0] = S; red[1] = SQ;
    }
    __syncthreads();
    float mu  = red[0] / (float)Dd;
    float var = red[1] / (float)Dd - mu * mu;
    float inv = rsqrtf(var + 1e-5f);
    for (int c = tid; c < Dd; c += 256)
        out[(size_t)row * Dd + c] = (ybuf[c] - mu) * inv * w[c] + bsh[c];
}

// ---------------- launch ----------------
extern "C" void kernel_launch(void* const* d_in, const int* in_sizes, int n_in,
                              void* d_out, int out_size)
{
    const float* x    = (const float*)d_in[0];
    const float* Wq   = (const float*)d_in[1];
    const float* bq   = (const float*)d_in[2];
    const float* Wk   = (const float*)d_in[3];
    const float* bk   = (const float*)d_in[4];
    const float* Wv   = (const float*)d_in[5];
    const float* bv   = (const float*)d_in[6];
    const float* Wo   = (const float*)d_in[7];
    const float* bo   = (const float*)d_in[8];
    const float* beta = (const float*)d_in[9];
    const float* W1   = (const float*)d_in[10];
    const float* b1   = (const float*)d_in[11];
    const float* W2   = (const float*)d_in[12];
    const float* b2   = (const float*)d_in[13];
    const float* lnw  = (const float*)d_in[14];
    const float* lnb  = (const float*)d_in[15];
    float* out = (float*)d_out;

    float *pq, *pk, *pv, *ph2;
    __nv_bfloat16 *pxh, *pxl, *path, *patl, *pah, *pal, *ph1h, *ph1l;
    __nv_bfloat16 *wqh, *wql, *wkh, *wkl, *wvh, *wvl, *woh, *wol, *w1h, *w1l, *w2h, *w2l;
    cudaGetSymbolAddress((void**)&pq,   g_q);
    cudaGetSymbolAddress((void**)&pk,   g_k);
    cudaGetSymbolAddress((void**)&pv,   g_v);
    cudaGetSymbolAddress((void**)&ph2,  g_h2);
    cudaGetSymbolAddress((void**)&pxh,  g_x_hi);  cudaGetSymbolAddress((void**)&pxl,  g_x_lo);
    cudaGetSymbolAddress((void**)&path, g_att_hi); cudaGetSymbolAddress((void**)&patl, g_att_lo);
    cudaGetSymbolAddress((void**)&pah,  g_a_hi);  cudaGetSymbolAddress((void**)&pal,  g_a_lo);
    cudaGetSymbolAddress((void**)&ph1h, g_h1_hi); cudaGetSymbolAddress((void**)&ph1l, g_h1_lo);
    cudaGetSymbolAddress((void**)&wqh, g_wq_hi); cudaGetSymbolAddress((void**)&wql, g_wq_lo);
    cudaGetSymbolAddress((void**)&wkh, g_wk_hi); cudaGetSymbolAddress((void**)&wkl, g_wk_lo);
    cudaGetSymbolAddress((void**)&wvh, g_wv_hi); cudaGetSymbolAddress((void**)&wvl, g_wv_lo);
    cudaGetSymbolAddress((void**)&woh, g_wo_hi); cudaGetSymbolAddress((void**)&wol, g_wo_lo);
    cudaGetSymbolAddress((void**)&w1h, g_w1_hi); cudaGetSymbolAddress((void**)&w1l, g_w1_lo);
    cudaGetSymbolAddress((void**)&w2h, g_w2_hi); cudaGetSymbolAddress((void**)&w2l, g_w2_lo);

    cudaFuncSetAttribute(attn_seg_a, cudaFuncAttributeMaxDynamicSharedMemorySize, SMEM_A_BYTES);
    cudaFuncSetAttribute(gemm_mma<0>, cudaFuncAttributeMaxDynamicSharedMemorySize, GEMM_SMEM_BYTES);
    cudaFuncSetAttribute(gemm_mma<1>, cudaFuncAttributeMaxDynamicSharedMemorySize, GEMM_SMEM_BYTES);
    cudaFuncSetAttribute(gemm_mma<2>, cudaFuncAttributeMaxDynamicSharedMemorySize, GEMM_SMEM_BYTES);

    init_state_kernel<<<2048, 256>>>();

    // convert x and weights
    conv_split<<<(BSr * Dd) / 1024, 256>>>(x, pxh, pxl);
    convt_kernel<<<dim3(Dd/64, Dd/64), 256>>>(Wq, wqh, wql, Dd, Dd);
    convt_kernel<<<dim3(Dd/64, Dd/64), 256>>>(Wk, wkh, wkl, Dd, Dd);
    convt_kernel<<<dim3(Dd/64, Dd/64), 256>>>(Wv, wvh, wvl, Dd, Dd);
    convt_kernel<<<dim3(Dd/64, Dd/64), 256>>>(Wo, woh, wol, Dd, Dd);
    convt_kernel<<<dim3(DH/64, Dd/64), 256>>>(W1, w1h, w1l, Dd, DH);   // [2048,8192]->[8192,2048]
    convt_kernel<<<dim3(Dd/64, DH/64), 256>>>(W2, w2h, w2l, DH, Dd);   // [8192,2048]->[2048,8192]

    // QKV projections (fp32 out)
    dim3 gP(Dd/128, BSr/128);   // (16, 64)
    gemm_mma<0><<<gP, 256, GEMM_SMEM_BYTES>>>(pxh, pxl, wqh, wql, bq, pq, nullptr, nullptr, BSr, Dd, Dd);
    gemm_mma<0><<<gP, 256, GEMM_SMEM_BYTES>>>(pxh, pxl, wkh, wkl, bk, pk, nullptr, nullptr, BSr, Dd, Dd);
    gemm_mma<0><<<gP, 256, GEMM_SMEM_BYTES>>>(pxh, pxl, wvh, wvl, bv, pv, nullptr, nullptr, BSr, Dd, Dd);

    // attention (outputs bf16 hi/lo att)
    for (int seg = 0; seg < NSEGc; seg++) {
        attn_seg_a<<<dim3(8, 32), 256, SMEM_A_BYTES>>>(pq, pk, pv, beta, path, patl, seg);
        attn_seg_b<<<32, 256>>>(pk, seg);
    }

    // output projection (bf16 hi/lo out)
    gemm_mma<1><<<gP, 256, GEMM_SMEM_BYTES>>>(path, patl, woh, wol, bo, nullptr, pah, pal, BSr, Dd, Dd);
    // MLP up + GELU (bf16 hi/lo out)
    dim3 gW1(DH/128, BSr/128);  // (64, 64)
    gemm_mma<2><<<gW1, 256, GEMM_SMEM_BYTES>>>(pah, pal, w1h, w1l, b1, nullptr, ph1h, ph1l, BSr, DH, Dd);
    // MLP down (fp32 out)
    gemm_mma<0><<<gP, 256, GEMM_SMEM_BYTES>>>(ph1h, ph1l, w2h, w2l, b2, ph2, nullptr, nullptr, BSr, Dd, DH);

    resid_ln<<<BSr, 256>>>(ph2, x, lnw, lnb, out);
}

// round 4
// speedup vs baseline: 3.0152x; 1.4696x over previous
#include <cuda_runtime.h>
#include <cuda_fp16.h>
#include <cstdint>

// ---------------- problem constants ----------------
#define Bb   2
#define Ss   4096
#define Dd   2048
#define Hh   16
#define DH   8192
#define Ll   512
#define NSEGc 8
#define BSr  (Bb*Ss)      // 8192 rows
#define BHn  (Bb*Hh)      // 32 (batch,head) pairs

// ---------------- scratch (device globals; no allocs allowed) ----------------
__device__ float g_q  [(size_t)BSr*Dd];
__device__ float g_k  [(size_t)BSr*Dd];
__device__ float g_v  [(size_t)BSr*Dd];
__device__ float g_h2 [(size_t)BSr*Dd];
__device__ __half g_x_h  [(size_t)BSr*Dd];
__device__ __half g_att_h[(size_t)BSr*Dd];
__device__ __half g_a_h  [(size_t)BSr*Dd];
__device__ __half g_h1_h [(size_t)BSr*DH];
// transposed fp16 weights [N,K], hi/lo planes
__device__ __half g_wq_hi[(size_t)Dd*Dd], g_wq_lo[(size_t)Dd*Dd];
__device__ __half g_wk_hi[(size_t)Dd*Dd], g_wk_lo[(size_t)Dd*Dd];
__device__ __half g_wv_hi[(size_t)Dd*Dd], g_wv_lo[(size_t)Dd*Dd];
__device__ __half g_wo_hi[(size_t)Dd*Dd], g_wo_lo[(size_t)Dd*Dd];
__device__ __half g_w1_hi[(size_t)DH*Dd], g_w1_lo[(size_t)DH*Dd];
__device__ __half g_w2_hi[(size_t)Dd*DH], g_w2_lo[(size_t)Dd*DH];
// attention state
__device__ float g_mem [BHn*128*128];
__device__ float g_zst [BHn*128];
__device__ float g_vdel[BHn*Ll*128];

// ---------------- helpers ----------------
__device__ __forceinline__ float gelu_exact(float x) {
    return 0.5f * x * (1.0f + erff(x * 0.70710678118654752440f));
}
__device__ __forceinline__ float elu1(float x) {
    return (x > 0.0f) ? (x + 1.0f) : __expf(x);
}
__device__ __forceinline__ void split2h(float v, __half& hi, __half& lo) {
    hi = __float2half_rn(v);
    lo = __float2half_rn(v - __half2float(hi));
}
__device__ __forceinline__ uint32_t smem_u32(const void* p) {
    uint32_t a;
    asm("{ .reg .u64 t; cvta.to.shared.u64 t, %1; cvt.u32.u64 %0, t; }" : "=r"(a) : "l"(p));
    return a;
}

// ---------------- mma / ldmatrix / cp.async primitives (sm_80-level PTX) ----------------
__device__ __forceinline__ void mma16816(float* c, const uint32_t* a, const uint32_t* b) {
    asm volatile(
        "mma.sync.aligned.m16n8k16.row.col.f32.f16.f16.f32 "
        "{%0,%1,%2,%3}, {%4,%5,%6,%7}, {%8,%9}, {%0,%1,%2,%3};"
        : "+f"(c[0]), "+f"(c[1]), "+f"(c[2]), "+f"(c[3])
        : "r"(a[0]), "r"(a[1]), "r"(a[2]), "r"(a[3]), "r"(b[0]), "r"(b[1]));
}
__device__ __forceinline__ void ldsm4(uint32_t addr, uint32_t* r) {
    asm volatile("ldmatrix.sync.aligned.m8n8.x4.shared.b16 {%0,%1,%2,%3}, [%4];"
                 : "=r"(r[0]), "=r"(r[1]), "=r"(r[2]), "=r"(r[3]) : "r"(addr));
}
__device__ __forceinline__ void cp_async16(uint32_t saddr, const void* gaddr) {
    asm volatile("cp.async.cg.shared.global [%0], [%1], 16;" :: "r"(saddr), "l"(gaddr));
}
#define CP_COMMIT() asm volatile("cp.async.commit_group;" ::: "memory")
#define CP_WAIT2()  asm volatile("cp.async.wait_group 2;" ::: "memory")

// smem tile layout: 128 rows x 64 bytes (32 fp16), XOR swizzle on 16B chunks
__device__ __forceinline__ uint32_t swz_off(int row, int kbyte) {
    return (uint32_t)(row * 64 + ((((kbyte) >> 4) ^ ((row >> 1) & 3)) << 4));
}

// ---------------- state init ----------------
__global__ void init_state_kernel() {
    int i = blockIdx.x * blockDim.x + threadIdx.x;
    if (i < BHn*128*128) g_mem[i] = 0.0f;
    if (i < BHn*128)     g_zst[i] = 1.0f / 128.0f;
}

// ---------------- x: fp32 -> fp16 single plane ----------------
__global__ void __launch_bounds__(256)
conv_x(const float* __restrict__ src, __half* __restrict__ dst)
{
    size_t i4 = (size_t)blockIdx.x * 256 + threadIdx.x;
    float4 v = ((const float4*)src)[i4];
    __half2 a, b;
    a.x = __float2half_rn(v.x); a.y = __float2half_rn(v.y);
    b.x = __float2half_rn(v.z); b.y = __float2half_rn(v.w);
    ((__half2*)dst)[i4*2]   = a;
    ((__half2*)dst)[i4*2+1] = b;
}

// ---------------- all weights: convert + transpose W[K,N] -> T[N,K] fp16 hi/lo ----------------
__global__ void __launch_bounds__(256)
convt_all(const float* __restrict__ Wq, const float* __restrict__ Wk,
          const float* __restrict__ Wv, const float* __restrict__ Wo,
          const float* __restrict__ W1, const float* __restrict__ W2,
          __half* qh, __half* ql, __half* kh, __half* kl, __half* vh, __half* vl,
          __half* oh, __half* ol, __half* m1h, __half* m1l, __half* m2h, __half* m2l)
{
    const int id = blockIdx.x;
    const float* W; __half *Th, *Tl; int K, N, nb, kb;
    if (id < 4096) {
        int w = id >> 10, t = id & 1023;
        nb = t & 31; kb = t >> 5; K = 2048; N = 2048;
        if (w == 0)      { W = Wq; Th = qh; Tl = ql; }
        else if (w == 1) { W = Wk; Th = kh; Tl = kl; }
        else if (w == 2) { W = Wv; Th = vh; Tl = vl; }
        else             { W = Wo; Th = oh; Tl = ol; }
    } else if (id < 8192) {
        int t = id - 4096; nb = t & 127; kb = t >> 7; K = 2048; N = 8192;
        W = W1; Th = m1h; Tl = m1l;
    } else {
        int t = id - 8192; nb = t & 31; kb = t >> 5; K = 8192; N = 2048;
        W = W2; Th = m2h; Tl = m2l;
    }
    __shared__ float tbuf[64][65];
    const int tid = threadIdx.x;
    const int n0 = nb * 64, k0 = kb * 64;
    for (int i = tid; i < 64*64; i += 256) {
        int r = i >> 6, c = i & 63;
        tbuf[r][c] = W[(size_t)(k0 + r) * N + n0 + c];
    }
    __syncthreads();
    for (int i = tid; i < 64*64; i += 256) {
        int rn = i >> 6, ck = i & 63;
        float v = tbuf[ck][rn];
        __half h, l; split2h(v, h, l);
        size_t o = (size_t)(n0 + rn) * K + k0 + ck;
        Th[o] = h; Tl[o] = l;
    }
}

// ---------------- tensor-core GEMM: C[M,N] = A[M,K] @ Bt[N,K]^T + bias ----------------
// A: single fp16 plane; B: fp16 hi/lo (2 accumulating MMAs); fp32 accumulation.
// 128x128 CTA tile, BK=32, 4-stage cp.async pipeline, 8 warps (4m x 2n), warp = 32x64.
// EPI: 0 = fp32 out; 1 = fp16 out; 2 = GELU then fp16 out.
#define GEMM_STAGES 4
#define GEMM_STAGE_BYTES 24576            // A 8KB + Bhi 8KB + Blo 8KB
#define GEMM_SMEM_BYTES  (GEMM_STAGES * GEMM_STAGE_BYTES)

template<int EPI>
__global__ void __launch_bounds__(256, 2)
gemm_mma(const __half* __restrict__ A, const __half* __restrict__ Bhp,
         const __half* __restrict__ Blp, const float* __restrict__ bias,
         float* __restrict__ Cf, __half* __restrict__ Ch, int M, int N, int K)
{
    extern __shared__ char sm_raw[];
    const uint32_t smem = smem_u32(sm_raw);

    const int tid  = threadIdx.x;
    const int lane = tid & 31;
    const int w    = tid >> 5;
    const int wm   = w & 3;
    const int wn   = w >> 2;
    const size_t bm = (size_t)blockIdx.y * 128;
    const size_t bn = (size_t)blockIdx.x * 128;
    const int KT = K >> 5;

    const int a_row = wm * 32 + (lane & 7) + ((lane >> 3) & 1) * 8;
    const int a_kb  = ((lane >> 4) & 1) * 16;
    const int b_row = wn * 64 + (lane & 7) + ((lane >> 4) & 1) * 8;
    const int b_kb  = ((lane >> 3) & 1) * 16;

    const int r0c = tid >> 2, j0 = tid & 3;
    const int r1c = (tid + 256) >> 2, j1 = (tid + 256) & 3;
    const uint32_t so0 = swz_off(r0c, j0 * 16);
    const uint32_t so1 = swz_off(r1c, j1 * 16);

    float acc[2][8][4];
#pragma unroll
    for (int i = 0; i < 2; i++)
#pragma unroll
        for (int j = 0; j < 8; j++)
#pragma unroll
            for (int q = 0; q < 4; q++) acc[i][j][q] = 0.0f;

    auto load_stage = [&](int st, int itk) {
        const uint32_t sb = smem + st * GEMM_STAGE_BYTES;
        const size_t k0 = (size_t)itk * 32;
        const size_t gA0 = (bm + r0c) * (size_t)K + k0 + j0 * 8;
        const size_t gA1 = (bm + r1c) * (size_t)K + k0 + j1 * 8;
        const size_t gB0 = (bn + r0c) * (size_t)K + k0 + j0 * 8;
        const size_t gB1 = (bn + r1c) * (size_t)K + k0 + j1 * 8;
        cp_async16(sb +         so0, A   + gA0);
        cp_async16(sb +         so1, A   + gA1);
        cp_async16(sb +  8192 + so0, Bhp + gB0);
        cp_async16(sb +  8192 + so1, Bhp + gB1);
        cp_async16(sb + 16384 + so0, Blp + gB0);
        cp_async16(sb + 16384 + so1, Blp + gB1);
    };

#pragma unroll
    for (int s = 0; s < GEMM_STAGES - 1; s++) {
        load_stage(s, s);
        CP_COMMIT();
    }

    for (int it = 0; it < KT; it++) {
        CP_WAIT2();
        __syncthreads();
        if (it + GEMM_STAGES - 1 < KT)
            load_stage((it + GEMM_STAGES - 1) & (GEMM_STAGES - 1), it + GEMM_STAGES - 1);
        CP_COMMIT();

        const uint32_t sb = smem + (it & (GEMM_STAGES - 1)) * GEMM_STAGE_BYTES;
#pragma unroll
        for (int ks = 0; ks < 2; ks++) {
            uint32_t ah[2][4];
#pragma unroll
            for (int mi = 0; mi < 2; mi++)
                ldsm4(sb + swz_off(a_row + mi * 16, ks * 32 + a_kb), ah[mi]);
            uint32_t bh[8][2], bl[8][2];
#pragma unroll
            for (int nt = 0; nt < 4; nt++) {
                uint32_t t4[4];
                const uint32_t rb = sb + 8192 + swz_off(b_row + nt * 16, ks * 32 + b_kb);
                ldsm4(rb, t4);
                bh[2*nt][0] = t4[0]; bh[2*nt][1] = t4[1];
                bh[2*nt+1][0] = t4[2]; bh[2*nt+1][1] = t4[3];
                ldsm4(rb + 8192, t4);
                bl[2*nt][0] = t4[0]; bl[2*nt][1] = t4[1];
                bl[2*nt+1][0] = t4[2]; bl[2*nt+1][1] = t4[3];
            }
#pragma unroll
            for (int mi = 0; mi < 2; mi++) {
#pragma unroll
                for (int ni = 0; ni < 8; ni++) {
                    mma16816(acc[mi][ni], ah[mi], bh[ni]);
                    mma16816(acc[mi][ni], ah[mi], bl[ni]);
                }
            }
        }
    }

    // ---- epilogue ----
    const int rl = lane >> 2, cl = (lane & 3) * 2;
#pragma unroll
    for (int mi = 0; mi < 2; mi++) {
#pragma unroll
        for (int ni = 0; ni < 8; ni++) {
            const float* c = acc[mi][ni];
            const size_t row0 = bm + wm * 32 + mi * 16 + rl;
            const size_t col  = bn + wn * 64 + ni * 8 + cl;
            const float b0 = bias[col], b1 = bias[col + 1];
            float v00 = c[0] + b0, v01 = c[1] + b1;
            float v10 = c[2] + b0, v11 = c[3] + b1;
            if (EPI == 2) {
                v00 = gelu_exact(v00); v01 = gelu_exact(v01);
                v10 = gelu_exact(v10); v11 = gelu_exact(v11);
            }
            if (EPI == 0) {
                *(float2*)(Cf + row0 * (size_t)N + col)       = make_float2(v00, v01);
                *(float2*)(Cf + (row0 + 8) * (size_t)N + col) = make_float2(v10, v11);
            } else {
                __half2 p0, p1;
                p0.x = __float2half_rn(v00); p0.y = __float2half_rn(v01);
                p1.x = __float2half_rn(v10); p1.y = __float2half_rn(v11);
                *(__half2*)(Ch + row0 * (size_t)N + col)       = p0;
                *(__half2*)(Ch + (row0 + 8) * (size_t)N + col) = p1;
            }
        }
    }
}

// ---------------- attention kernel A (per segment) ----------------
#define SM_QST 0
#define SM_BUF (128*65)
#define SM_SC  (128*65 + 128*128)
#define SM_Z   (128*65 + 128*128 + 64*513)
#define SMEM_A_FLOATS (128*65 + 128*128 + 64*513 + 128)
#define SMEM_A_BYTES  (SMEM_A_FLOATS * 4)

__global__ void __launch_bounds__(256)
attn_seg_a(const float* __restrict__ q, const float* __restrict__ k,
           const float* __restrict__ v, const float* __restrict__ betas,
           __half* __restrict__ att_h, int seg)
{
    extern __shared__ float sm[];
    float* qsT  = sm + SM_QST;
    float* bufB = sm + SM_BUF;
    float* sc   = sm + SM_SC;
    float* skT  = sm + SM_SC;
    float* z_s  = sm + SM_Z;

    const int tid = threadIdx.x;
    const int tx = tid & 15, ty = tid >> 4;
    const int rb = blockIdx.x;
    const int bh = blockIdx.y;
    const int b  = bh >> 4, h = bh & 15;
    const int r0 = rb * 64;
    const size_t rowbase = (size_t)(b * Ss + seg * Ll);
    const int colbase = h * 128;

    for (int i = tid; i < 64 * 128; i += 256) {
        int r = i >> 7, c = i & 127;
        qsT[c * 65 + r] = q[(rowbase + r0 + r) * Dd + colbase + c];
    }
    __syncthreads();

    const float scale = 0.088388347648318447f;

    for (int ch = 0; ch <= rb; ch++) {
        for (int i = tid; i < 64 * 128; i += 256) {
            int r = i >> 7, c = i & 127;
            bufB[c * 65 + r] = k[(rowbase + ch * 64 + r) * Dd + colbase + c];
        }
        __syncthreads();
        float accs[4][4] = {};
#pragma unroll 4
        for (int kk = 0; kk < 128; kk++) {
            float a[4], bb[4];
#pragma unroll
            for (int i = 0; i < 4; i++) a[i]  = qsT[kk * 65 + ty*4 + i];
#pragma unroll
            for (int j = 0; j < 4; j++) bb[j] = bufB[kk * 65 + tx*4 + j];
#pragma unroll
            for (int i = 0; i < 4; i++)
#pragma unroll
                for (int j = 0; j < 4; j++)
                    accs[i][j] += a[i] * bb[j];
        }
#pragma unroll
        for (int i = 0; i < 4; i++)
#pragma unroll
            for (int j = 0; j < 4; j++)
                sc[(ty*4 + i) * 513 + ch*64 + tx*4 + j] = accs[i][j] * scale;
        __syncthreads();
    }

    {
        int warp = tid >> 5, lane = tid & 31;
        int mlim = (rb + 1) * 64;
        for (int rr = 0; rr < 8; rr++) {
            int row = warp * 8 + rr;
            int gr  = r0 + row;
            float* srow = sc + row * 513;
            float mx = -1e30f;
            for (int m = lane; m <= gr; m += 32) mx = fmaxf(mx, srow[m]);
#pragma unroll
            for (int o = 16; o > 0; o >>= 1) mx = fmaxf(mx, __shfl_xor_sync(0xffffffffu, mx, o));
            float s = 0.0f;
            for (int m = lane; m <= gr; m += 32) { float e = __expf(srow[m] - mx); srow[m] = e; s += e; }
#pragma unroll
            for (int o = 16; o > 0; o >>= 1) s += __shfl_xor_sync(0xffffffffu, s, o);
            float inv = 1.0f / s;
            for (int m = lane; m < mlim; m += 32) srow[m] = (m <= gr) ? srow[m] * inv : 0.0f;
        }
    }
    __syncthreads();

    float accd[4][8] = {};
    for (int ch = 0; ch <= rb; ch++) {
        for (int i = tid; i < 64 * 32; i += 256) {
            int r = i >> 5, c = (i & 31) * 4;
            *(float4*)&bufB[r * 128 + c] =
                *(const float4*)&v[(rowbase + ch * 64 + r) * Dd + colbase + c];
        }
        __syncthreads();
#pragma unroll 2
        for (int kk = 0; kk < 64; kk++) {
            float4 v0 = *(const float4*)&bufB[kk * 128 + tx*4];
            float4 v1 = *(const float4*)&bufB[kk * 128 + 64 + tx*4];
            float p[4];
#pragma unroll
            for (int i = 0; i < 4; i++) p[i] = sc[(ty*4 + i) * 513 + ch*64 + kk];
#pragma unroll
            for (int i = 0; i < 4; i++) {
                accd[i][0] += p[i]*v0.x; accd[i][1] += p[i]*v0.y;
                accd[i][2] += p[i]*v0.z; accd[i][3] += p[i]*v0.w;
                accd[i][4] += p[i]*v1.x; accd[i][5] += p[i]*v1.y;
                accd[i][6] += p[i]*v1.z; accd[i][7] += p[i]*v1.w;
            }
        }
        __syncthreads();
    }

    {
        size_t mbase = (size_t)bh * (128 * 128);
        for (int i = tid; i < 128 * 32; i += 256)
            *(float4*)&bufB[i * 4] = *(const float4*)&g_mem[mbase + (size_t)i * 4];
        if (tid < 128) z_s[tid] = g_zst[bh * 128 + tid];
        for (int i = tid; i < 64 * 128; i += 256) {
            int r = i >> 7, c = i & 127;
            qsT[c * 65 + r] = elu1(qsT[c * 65 + r]);
        }
    }
    __syncthreads();

    float accn[4][8] = {};
    float den[4] = {};
#pragma unroll 2
    for (int kk = 0; kk < 128; kk++) {
        float a[4];
#pragma unroll
        for (int i = 0; i < 4; i++) a[i] = qsT[kk * 65 + ty*4 + i];
        float4 m0 = *(const float4*)&bufB[kk * 128 + tx*4];
        float4 m1 = *(const float4*)&bufB[kk * 128 + 64 + tx*4];
        float zk = z_s[kk];
#pragma unroll
        for (int i = 0; i < 4; i++) {
            den[i] += a[i] * zk;
            accn[i][0] += a[i]*m0.x; accn[i][1] += a[i]*m0.y;
            accn[i][2] += a[i]*m0.z; accn[i][3] += a[i]*m0.w;
            accn[i][4] += a[i]*m1.x; accn[i][5] += a[i]*m1.y;
            accn[i][6] += a[i]*m1.z; accn[i][7] += a[i]*m1.w;
        }
    }

#pragma unroll
    for (int i = 0; i < 4; i++) {
        size_t grow = rowbase + r0 + ty*4 + i;
        float invd = 1.0f / den[i];
#pragma unroll
        for (int g = 0; g < 2; g++) {
            int c0 = g*64 + tx*4;
#pragma unroll
            for (int j = 0; j < 4; j++) {
                int col = c0 + j;
                float gt = 1.0f / (1.0f + __expf(-betas[h * 128 + col]));
                float val = gt * (accn[i][g*4+j] * invd) + (1.0f - gt) * accd[i][g*4+j];
                att_h[grow * Dd + colbase + col] = __float2half_rn(val);
            }
        }
    }
    __syncthreads();

    for (int i = tid; i < 64 * 128; i += 256) {
        int r = i >> 7, c = i & 127;
        skT[c * 65 + r] = elu1(k[(rowbase + r0 + r) * Dd + colbase + c]);
    }
    __syncthreads();

    float accv[4][8] = {};
    float denk[4] = {};
#pragma unroll 2
    for (int kk = 0; kk < 128; kk++) {
        float a[4];
#pragma unroll
        for (int i = 0; i < 4; i++) a[i] = skT[kk * 65 + ty*4 + i];
        float4 m0 = *(const float4*)&bufB[kk * 128 + tx*4];
        float4 m1 = *(const float4*)&bufB[kk * 128 + 64 + tx*4];
        float zk = z_s[kk];
#pragma unroll
        for (int i = 0; i < 4; i++) {
            denk[i] += a[i] * zk;
            accv[i][0] += a[i]*m0.x; accv[i][1] += a[i]*m0.y;
            accv[i][2] += a[i]*m0.z; accv[i][3] += a[i]*m0.w;
            accv[i][4] += a[i]*m1.x; accv[i][5] += a[i]*m1.y;
            accv[i][6] += a[i]*m1.z; accv[i][7] += a[i]*m1.w;
        }
    }
#pragma unroll
    for (int i = 0; i < 4; i++) {
        size_t grow = rowbase + r0 + ty*4 + i;
        float invd = 1.0f / denk[i];
#pragma unroll
        for (int g = 0; g < 2; g++) {
            int c0 = g*64 + tx*4;
            float4 vv = *(const float4*)&v[grow * Dd + colbase + c0];
            float4 o;
            o.x = vv.x - accv[i][g*4+0] * invd;
            o.y = vv.y - accv[i][g*4+1] * invd;
            o.z = vv.z - accv[i][g*4+2] * invd;
            o.w = vv.w - accv[i][g*4+3] * invd;
            *(float4*)&g_vdel[((size_t)bh * Ll + r0 + ty*4 + i) * 128 + c0] = o;
        }
    }
}

// ---------------- attention kernel B: mem += sk^T @ v_del ; z += sum(sk) ----------------
// grid (32 bh, 4 dk-slices); each CTA owns mem rows [slice*32, slice*32+32).
__global__ void __launch_bounds__(256)
attn_seg_b(const float* __restrict__ k, int seg)
{
    __shared__ float sk8[8][32];
    __shared__ float vd8[8][128];
    const int tid = threadIdx.x;
    const int tx = tid & 15, ty = tid >> 4;
    const int bh = blockIdx.x;
    const int dkbase = blockIdx.y * 32;
    const int b = bh >> 4, h = bh & 15;
    const size_t rowbase = (size_t)(b * Ss + seg * Ll);

    float acc[2][8] = {};
    float zacc[2] = {};

    const int lrow = tid >> 5, lcol = tid & 31;

    for (int l0 = 0; l0 < Ll; l0 += 8) {
        sk8[lrow][lcol] = elu1(k[(rowbase + l0 + lrow) * Dd + h * 128 + dkbase + lcol]);
        *(float4*)&vd8[lrow][(tid & 31) * 4] =
            *(const float4*)&g_vdel[((size_t)bh * Ll + l0 + lrow) * 128 + (tid & 31) * 4];
        __syncthreads();
#pragma unroll
        for (int l = 0; l < 8; l++) {
            float a0 = sk8[l][ty*2];
            float a1 = sk8[l][ty*2 + 1];
            zacc[0] += a0; zacc[1] += a1;
            float4 b0 = *(const float4*)&vd8[l][tx*8];
            float4 b1 = *(const float4*)&vd8[l][tx*8 + 4];
            float bb[8] = {b0.x, b0.y, b0.z, b0.w, b1.x, b1.y, b1.z, b1.w};
#pragma unroll
            for (int j = 0; j < 8; j++) {
                acc[0][j] += a0 * bb[j];
                acc[1][j] += a1 * bb[j];
            }
        }
        __syncthreads();
    }

    size_t mbase = (size_t)bh * 128 * 128;
#pragma unroll
    for (int i = 0; i < 2; i++) {
        int dk = dkbase + ty*2 + i;
#pragma unroll
        for (int g = 0; g < 2; g++) {
            float4* p = (float4*)&g_mem[mbase + (size_t)dk * 128 + tx*8 + g*4];
            float4 cur = *p;
            cur.x += acc[i][g*4+0]; cur.y += acc[i][g*4+1];
            cur.z += acc[i][g*4+2]; cur.w += acc[i][g*4+3];
            *p = cur;
        }
        if (tx == 0) g_zst[bh * 128 + dk] += zacc[i];
    }
}

// ---------------- residual + LayerNorm ----------------
__global__ void __launch_bounds__(256)
resid_ln(const float* __restrict__ h2, const float* __restrict__ x,
         const float* __restrict__ w, const float* __restrict__ bsh,
         float* __restrict__ out)
{
    __shared__ float ybuf[Dd];
    __shared__ float red[17];
    const int row = blockIdx.x;
    const int tid = threadIdx.x;
    const float* hr = h2 + (size_t)row * Dd;
    const float* xr = x  + (size_t)row * Dd;

    float s = 0.0f, sq = 0.0f;
    for (int c = tid; c < Dd; c += 256) {
        float yv = hr[c] + xr[c];
        ybuf[c] = yv;
        s += yv; sq += yv * yv;
    }
#pragma unroll
    for (int o = 16; o > 0; o >>= 1) {
        s  += __shfl_xor_sync(0xffffffffu, s, o);
        sq += __shfl_xor_sync(0xffffffffu, sq, o);
    }
    int warp = tid >> 5, lane = tid & 31;
    if (lane == 0) { red[warp] = s; red[8 + warp] = sq; }
    __syncthreads();
    if (tid == 0) {
        float S = 0, SQ = 0;
        for (int i = 0; i < 8; i++) { S += red[i]; SQ += red[8 + i]; }
        red[0] = S; red[1] = SQ;
    }
    __syncthreads();
    float mu  = red[0] / (float)Dd;
    float var = red[1] / (float)Dd - mu * mu;
    float inv = rsqrtf(var + 1e-5f);
    for (int c = tid; c < Dd; c += 256)
        out[(size_t)row * Dd + c] = (ybuf[c] - mu) * inv * w[c] + bsh[c];
}

// ---------------- launch ----------------
extern "C" void kernel_launch(void* const* d_in, const int* in_sizes, int n_in,
                              void* d_out, int out_size)
{
    const float* x    = (const float*)d_in[0];
    const float* Wq   = (const float*)d_in[1];
    const float* bq   = (const float*)d_in[2];
    const float* Wk   = (const float*)d_in[3];
    const float* bk   = (const float*)d_in[4];
    const float* Wv   = (const float*)d_in[5];
    const float* bv   = (const float*)d_in[6];
    const float* Wo   = (const float*)d_in[7];
    const float* bo   = (const float*)d_in[8];
    const float* beta = (const float*)d_in[9];
    const float* W1   = (const float*)d_in[10];
    const float* b1   = (const float*)d_in[11];
    const float* W2   = (const float*)d_in[12];
    const float* b2   = (const float*)d_in[13];
    const float* lnw  = (const float*)d_in[14];
    const float* lnb  = (const float*)d_in[15];
    float* out = (float*)d_out;

    float *pq, *pk, *pv, *ph2;
    __half *pxh, *path, *pah, *ph1h;
    __half *wqh, *wql, *wkh, *wkl, *wvh, *wvl, *woh, *wol, *w1h, *w1l, *w2h, *w2l;
    cudaGetSymbolAddress((void**)&pq,   g_q);
    cudaGetSymbolAddress((void**)&pk,   g_k);
    cudaGetSymbolAddress((void**)&pv,   g_v);
    cudaGetSymbolAddress((void**)&ph2,  g_h2);
    cudaGetSymbolAddress((void**)&pxh,  g_x_h);
    cudaGetSymbolAddress((void**)&path, g_att_h);
    cudaGetSymbolAddress((void**)&pah,  g_a_h);
    cudaGetSymbolAddress((void**)&ph1h, g_h1_h);
    cudaGetSymbolAddress((void**)&wqh, g_wq_hi); cudaGetSymbolAddress((void**)&wql, g_wq_lo);
    cudaGetSymbolAddress((void**)&wkh, g_wk_hi); cudaGetSymbolAddress((void**)&wkl, g_wk_lo);
    cudaGetSymbolAddress((void**)&wvh, g_wv_hi); cudaGetSymbolAddress((void**)&wvl, g_wv_lo);
    cudaGetSymbolAddress((void**)&woh, g_wo_hi); cudaGetSymbolAddress((void**)&wol, g_wo_lo);
    cudaGetSymbolAddress((void**)&w1h, g_w1_hi); cudaGetSymbolAddress((void**)&w1l, g_w1_lo);
    cudaGetSymbolAddress((void**)&w2h, g_w2_hi); cudaGetSymbolAddress((void**)&w2l, g_w2_lo);

    cudaFuncSetAttribute(attn_seg_a, cudaFuncAttributeMaxDynamicSharedMemorySize, SMEM_A_BYTES);
    cudaFuncSetAttribute(gemm_mma<0>, cudaFuncAttributeMaxDynamicSharedMemorySize, GEMM_SMEM_BYTES);
    cudaFuncSetAttribute(gemm_mma<1>, cudaFuncAttributeMaxDynamicSharedMemorySize, GEMM_SMEM_BYTES);
    cudaFuncSetAttribute(gemm_mma<2>, cudaFuncAttributeMaxDynamicSharedMemorySize, GEMM_SMEM_BYTES);

    // launch order chosen so ncu (-s 5 -c 1) captures launch #6 = V projection GEMM
    init_state_kernel<<<2048, 256>>>();                                   // 1
    conv_x<<<(BSr * Dd) / 1024, 256>>>(x, pxh);                           // 2
    convt_all<<<12288, 256>>>(Wq, Wk, Wv, Wo, W1, W2,                     // 3
                              wqh, wql, wkh, wkl, wvh, wvl,
                              woh, wol, w1h, w1l, w2h, w2l);

    dim3 gP(Dd/128, BSr/128);   // (16, 64)
    gemm_mma<0><<<gP, 256, GEMM_SMEM_BYTES>>>(pxh, wqh, wql, bq, pq, nullptr, BSr, Dd, Dd);  // 4
    gemm_mma<0><<<gP, 256, GEMM_SMEM_BYTES>>>(pxh, wkh, wkl, bk, pk, nullptr, BSr, Dd, Dd);  // 5
    gemm_mma<0><<<gP, 256, GEMM_SMEM_BYTES>>>(pxh, wvh, wvl, bv, pv, nullptr, BSr, Dd, Dd);  // 6

    for (int seg = 0; seg < NSEGc; seg++) {
        attn_seg_a<<<dim3(8, 32), 256, SMEM_A_BYTES>>>(pq, pk, pv, beta, path, seg);
        attn_seg_b<<<dim3(32, 4), 256>>>(pk, seg);
    }

    gemm_mma<1><<<gP, 256, GEMM_SMEM_BYTES>>>(path, woh, wol, bo, nullptr, pah, BSr, Dd, Dd);
    dim3 gW1(DH/128, BSr/128);  // (64, 64)
    gemm_mma<2><<<gW1, 256, GEMM_SMEM_BYTES>>>(pah, w1h, w1l, b1, nullptr, ph1h, BSr, DH, Dd);
    gemm_mma<0><<<gP, 256, GEMM_SMEM_BYTES>>>(ph1h, w2h, w2l, b2, ph2, nullptr, BSr, Dd, DH);

    resid_ln<<<BSr, 256>>>(ph2, x, lnw, lnb, out);
}

// round 5
// speedup vs baseline: 4.0156x; 1.3318x over previous
#include <cuda_runtime.h>
#include <cuda_fp16.h>
#include <cstdint>

// ---------------- problem constants ----------------
#define Bb   2
#define Ss   4096
#define Dd   2048
#define Hh   16
#define DH   8192
#define Ll   512
#define NSEGc 8
#define BSr  (Bb*Ss)      // 8192 rows
#define BHn  (Bb*Hh)      // 32 (batch,head) pairs

// ---------------- scratch (device globals; no allocs allowed) ----------------
__device__ float g_q  [(size_t)BSr*Dd];
__device__ float g_k  [(size_t)BSr*Dd];
__device__ float g_v  [(size_t)BSr*Dd];
__device__ float g_h2 [(size_t)BSr*Dd];
__device__ __half g_x_h  [(size_t)BSr*Dd];
__device__ __half g_att_h[(size_t)BSr*Dd];
__device__ __half g_a_h  [(size_t)BSr*Dd];
__device__ __half g_h1_h [(size_t)BSr*DH];
// transposed fp16 weights [N,K]
__device__ __half g_wq[(size_t)Dd*Dd];
__device__ __half g_wk[(size_t)Dd*Dd];
__device__ __half g_wv[(size_t)Dd*Dd];
__device__ __half g_wo[(size_t)Dd*Dd];
__device__ __half g_w1[(size_t)DH*Dd];
__device__ __half g_w2[(size_t)Dd*DH];
// attention state
__device__ float g_mem [BHn*128*128];
__device__ float g_zst [BHn*128];
__device__ float g_vdel[BHn*Ll*128];

// ---------------- helpers ----------------
__device__ __forceinline__ float gelu_exact(float x) {
    return 0.5f * x * (1.0f + erff(x * 0.70710678118654752440f));
}
__device__ __forceinline__ float elu1(float x) {
    return (x > 0.0f) ? (x + 1.0f) : __expf(x);
}
__device__ __forceinline__ uint32_t smem_u32(const void* p) {
    uint32_t a;
    asm("{ .reg .u64 t; cvta.to.shared.u64 t, %1; cvt.u32.u64 %0, t; }" : "=r"(a) : "l"(p));
    return a;
}

// ---------------- mma / ldmatrix / cp.async primitives (sm_80-level PTX) ----------------
__device__ __forceinline__ void mma16816(float* c, const uint32_t* a, const uint32_t* b) {
    asm volatile(
        "mma.sync.aligned.m16n8k16.row.col.f32.f16.f16.f32 "
        "{%0,%1,%2,%3}, {%4,%5,%6,%7}, {%8,%9}, {%0,%1,%2,%3};"
        : "+f"(c[0]), "+f"(c[1]), "+f"(c[2]), "+f"(c[3])
        : "r"(a[0]), "r"(a[1]), "r"(a[2]), "r"(a[3]), "r"(b[0]), "r"(b[1]));
}
__device__ __forceinline__ void ldsm4(uint32_t addr, uint32_t* r) {
    asm volatile("ldmatrix.sync.aligned.m8n8.x4.shared.b16 {%0,%1,%2,%3}, [%4];"
                 : "=r"(r[0]), "=r"(r[1]), "=r"(r[2]), "=r"(r[3]) : "r"(addr));
}
__device__ __forceinline__ void cp_async16(uint32_t saddr, const void* gaddr) {
    asm volatile("cp.async.cg.shared.global [%0], [%1], 16;" :: "r"(saddr), "l"(gaddr));
}
#define CP_COMMIT() asm volatile("cp.async.commit_group;" ::: "memory")
#define CP_WAIT2()  asm volatile("cp.async.wait_group 2;" ::: "memory")

// smem tile layout: 128 rows x 64 bytes (32 fp16), XOR swizzle on 16B chunks
__device__ __forceinline__ uint32_t swz_off(int row, int kbyte) {
    return (uint32_t)(row * 64 + ((((kbyte) >> 4) ^ ((row >> 1) & 3)) << 4));
}

// ---------------- state init ----------------
__global__ void init_state_kernel() {
    int i = blockIdx.x * blockDim.x + threadIdx.x;
    if (i < BHn*128*128) g_mem[i] = 0.0f;
    if (i < BHn*128)     g_zst[i] = 1.0f / 128.0f;
}

// ---------------- x: fp32 -> fp16 ----------------
__global__ void __launch_bounds__(256)
conv_x(const float* __restrict__ src, __half* __restrict__ dst)
{
    size_t i4 = (size_t)blockIdx.x * 256 + threadIdx.x;
    float4 v = ((const float4*)src)[i4];
    __half2 a, b;
    a.x = __float2half_rn(v.x); a.y = __float2half_rn(v.y);
    b.x = __float2half_rn(v.z); b.y = __float2half_rn(v.w);
    ((__half2*)dst)[i4*2]   = a;
    ((__half2*)dst)[i4*2+1] = b;
}

// ---------------- all weights: convert + transpose W[K,N] -> T[N,K] fp16 ----------------
__global__ void __launch_bounds__(256)
convt_all(const float* __restrict__ Wq, const float* __restrict__ Wk,
          const float* __restrict__ Wv, const float* __restrict__ Wo,
          const float* __restrict__ W1, const float* __restrict__ W2,
          __half* tq, __half* tk, __half* tv, __half* to_, __half* t1, __half* t2)
{
    const int id = blockIdx.x;
    const float* W; __half* T; int K, N, nb, kb;
    if (id < 4096) {
        int w = id >> 10, t = id & 1023;
        nb = t & 31; kb = t >> 5; K = 2048; N = 2048;
        if (w == 0)      { W = Wq; T = tq; }
        else if (w == 1) { W = Wk; T = tk; }
        else if (w == 2) { W = Wv; T = tv; }
        else             { W = Wo; T = to_; }
    } else if (id < 8192) {
        int t = id - 4096; nb = t & 127; kb = t >> 7; K = 2048; N = 8192;
        W = W1; T = t1;
    } else {
        int t = id - 8192; nb = t & 31; kb = t >> 5; K = 8192; N = 2048;
        W = W2; T = t2;
    }
    __shared__ float tbuf[64][65];
    const int tid = threadIdx.x;
    const int n0 = nb * 64, k0 = kb * 64;
    for (int i = tid; i < 64*64; i += 256) {
        int r = i >> 6, c = i & 63;
        tbuf[r][c] = W[(size_t)(k0 + r) * N + n0 + c];
    }
    __syncthreads();
    for (int i = tid; i < 64*64; i += 256) {
        int rn = i >> 6, ck = i & 63;
        T[(size_t)(n0 + rn) * K + k0 + ck] = __float2half_rn(tbuf[ck][rn]);
    }
}

// ---------------- tensor-core GEMM: C[M,N] = A[M,K] @ Bt[N,K]^T + bias ----------------
// fp16 operands, fp32 accumulation. 128x128 CTA tile, BK=32, 4-stage cp.async pipeline,
// 8 warps (4m x 2n), warp = 32x64.
// EPI: 0 = fp32 out; 1 = fp16 out; 2 = GELU then fp16 out.
#define GEMM_STAGES 4
#define GEMM_STAGE_BYTES 16384            // A 8KB + B 8KB
#define GEMM_SMEM_BYTES  (GEMM_STAGES * GEMM_STAGE_BYTES)

template<int EPI>
__global__ void __launch_bounds__(256, 2)
gemm_mma(const __half* __restrict__ A, const __half* __restrict__ Bp,
         const float* __restrict__ bias,
         float* __restrict__ Cf, __half* __restrict__ Ch, int M, int N, int K)
{
    extern __shared__ char sm_raw[];
    const uint32_t smem = smem_u32(sm_raw);

    const int tid  = threadIdx.x;
    const int lane = tid & 31;
    const int w    = tid >> 5;
    const int wm   = w & 3;
    const int wn   = w >> 2;
    const size_t bm = (size_t)blockIdx.y * 128;
    const size_t bn = (size_t)blockIdx.x * 128;
    const int KT = K >> 5;

    const int a_row = wm * 32 + (lane & 7) + ((lane >> 3) & 1) * 8;
    const int a_kb  = ((lane >> 4) & 1) * 16;
    const int b_row = wn * 64 + (lane & 7) + ((lane >> 4) & 1) * 8;
    const int b_kb  = ((lane >> 3) & 1) * 16;

    const int r0c = tid >> 2, j0 = tid & 3;
    const int r1c = (tid + 256) >> 2, j1 = (tid + 256) & 3;
    const uint32_t so0 = swz_off(r0c, j0 * 16);
    const uint32_t so1 = swz_off(r1c, j1 * 16);

    float acc[2][8][4];
#pragma unroll
    for (int i = 0; i < 2; i++)
#pragma unroll
        for (int j = 0; j < 8; j++)
#pragma unroll
            for (int q = 0; q < 4; q++) acc[i][j][q] = 0.0f;

    auto load_stage = [&](int st, int itk) {
        const uint32_t sb = smem + st * GEMM_STAGE_BYTES;
        const size_t k0 = (size_t)itk * 32;
        cp_async16(sb +        so0, A  + (bm + r0c) * (size_t)K + k0 + j0 * 8);
        cp_async16(sb +        so1, A  + (bm + r1c) * (size_t)K + k0 + j1 * 8);
        cp_async16(sb + 8192 + so0, Bp + (bn + r0c) * (size_t)K + k0 + j0 * 8);
        cp_async16(sb + 8192 + so1, Bp + (bn + r1c) * (size_t)K + k0 + j1 * 8);
    };

#pragma unroll
    for (int s = 0; s < GEMM_STAGES - 1; s++) {
        load_stage(s, s);
        CP_COMMIT();
    }

    for (int it = 0; it < KT; it++) {
        CP_WAIT2();
        __syncthreads();
        if (it + GEMM_STAGES - 1 < KT)
            load_stage((it + GEMM_STAGES - 1) & (GEMM_STAGES - 1), it + GEMM_STAGES - 1);
        CP_COMMIT();

        const uint32_t sb = smem + (it & (GEMM_STAGES - 1)) * GEMM_STAGE_BYTES;
#pragma unroll
        for (int ks = 0; ks < 2; ks++) {
            uint32_t ah[2][4];
#pragma unroll
            for (int mi = 0; mi < 2; mi++)
                ldsm4(sb + swz_off(a_row + mi * 16, ks * 32 + a_kb), ah[mi]);
            uint32_t bh[8][2];
#pragma unroll
            for (int nt = 0; nt < 4; nt++) {
                uint32_t t4[4];
                ldsm4(sb + 8192 + swz_off(b_row + nt * 16, ks * 32 + b_kb), t4);
                bh[2*nt][0] = t4[0]; bh[2*nt][1] = t4[1];
                bh[2*nt+1][0] = t4[2]; bh[2*nt+1][1] = t4[3];
            }
#pragma unroll
            for (int mi = 0; mi < 2; mi++)
#pragma unroll
                for (int ni = 0; ni < 8; ni++)
                    mma16816(acc[mi][ni], ah[mi], bh[ni]);
        }
    }

    // ---- epilogue ----
    const int rl = lane >> 2, cl = (lane & 3) * 2;
#pragma unroll
    for (int mi = 0; mi < 2; mi++) {
#pragma unroll
        for (int ni = 0; ni < 8; ni++) {
            const float* c = acc[mi][ni];
            const size_t row0 = bm + wm * 32 + mi * 16 + rl;
            const size_t col  = bn + wn * 64 + ni * 8 + cl;
            const float b0 = bias[col], b1 = bias[col + 1];
            float v00 = c[0] + b0, v01 = c[1] + b1;
            float v10 = c[2] + b0, v11 = c[3] + b1;
            if (EPI == 2) {
                v00 = gelu_exact(v00); v01 = gelu_exact(v01);
                v10 = gelu_exact(v10); v11 = gelu_exact(v11);
            }
            if (EPI == 0) {
                *(float2*)(Cf + row0 * (size_t)N + col)       = make_float2(v00, v01);
                *(float2*)(Cf + (row0 + 8) * (size_t)N + col) = make_float2(v10, v11);
            } else {
                __half2 p0, p1;
                p0.x = __float2half_rn(v00); p0.y = __float2half_rn(v01);
                p1.x = __float2half_rn(v10); p1.y = __float2half_rn(v11);
                *(__half2*)(Ch + row0 * (size_t)N + col)       = p0;
                *(__half2*)(Ch + (row0 + 8) * (size_t)N + col) = p1;
            }
        }
    }
}

// ---------------- attention kernel A (per segment) ----------------
#define SM_QST 0
#define SM_BUF (128*65)
#define SM_SC  (128*65 + 128*128)
#define SM_Z   (128*65 + 128*128 + 64*513)
#define SMEM_A_FLOATS (128*65 + 128*128 + 64*513 + 128)
#define SMEM_A_BYTES  (SMEM_A_FLOATS * 4)

__global__ void __launch_bounds__(256)
attn_seg_a(const float* __restrict__ q, const float* __restrict__ k,
           const float* __restrict__ v, const float* __restrict__ betas,
           __half* __restrict__ att_h, int seg)
{
    extern __shared__ float sm[];
    float* qsT  = sm + SM_QST;
    float* bufB = sm + SM_BUF;
    float* sc   = sm + SM_SC;
    float* skT  = sm + SM_SC;
    float* z_s  = sm + SM_Z;

    const int tid = threadIdx.x;
    const int tx = tid & 15, ty = tid >> 4;
    const int rb = blockIdx.x;
    const int bh = blockIdx.y;
    const int b  = bh >> 4, h = bh & 15;
    const int r0 = rb * 64;
    const size_t rowbase = (size_t)(b * Ss + seg * Ll);
    const int colbase = h * 128;

    for (int i = tid; i < 64 * 128; i += 256) {
        int r = i >> 7, c = i & 127;
        qsT[c * 65 + r] = q[(rowbase + r0 + r) * Dd + colbase + c];
    }
    __syncthreads();

    const float scale = 0.088388347648318447f;

    for (int ch = 0; ch <= rb; ch++) {
        for (int i = tid; i < 64 * 128; i += 256) {
            int r = i >> 7, c = i & 127;
            bufB[c * 65 + r] = k[(rowbase + ch * 64 + r) * Dd + colbase + c];
        }
        __syncthreads();
        float accs[4][4] = {};
#pragma unroll 4
        for (int kk = 0; kk < 128; kk++) {
            float a[4], bb[4];
#pragma unroll
            for (int i = 0; i < 4; i++) a[i]  = qsT[kk * 65 + ty*4 + i];
#pragma unroll
            for (int j = 0; j < 4; j++) bb[j] = bufB[kk * 65 + tx*4 + j];
#pragma unroll
            for (int i = 0; i < 4; i++)
#pragma unroll
                for (int j = 0; j < 4; j++)
                    accs[i][j] += a[i] * bb[j];
        }
#pragma unroll
        for (int i = 0; i < 4; i++)
#pragma unroll
            for (int j = 0; j < 4; j++)
                sc[(ty*4 + i) * 513 + ch*64 + tx*4 + j] = accs[i][j] * scale;
        __syncthreads();
    }

    {
        int warp = tid >> 5, lane = tid & 31;
        int mlim = (rb + 1) * 64;
        for (int rr = 0; rr < 8; rr++) {
            int row = warp * 8 + rr;
            int gr  = r0 + row;
            float* srow = sc + row * 513;
            float mx = -1e30f;
            for (int m = lane; m <= gr; m += 32) mx = fmaxf(mx, srow[m]);
#pragma unroll
            for (int o = 16; o > 0; o >>= 1) mx = fmaxf(mx, __shfl_xor_sync(0xffffffffu, mx, o));
            float s = 0.0f;
            for (int m = lane; m <= gr; m += 32) { float e = __expf(srow[m] - mx); srow[m] = e; s += e; }
#pragma unroll
            for (int o = 16; o > 0; o >>= 1) s += __shfl_xor_sync(0xffffffffu, s, o);
            float inv = 1.0f / s;
            for (int m = lane; m < mlim; m += 32) srow[m] = (m <= gr) ? srow[m] * inv : 0.0f;
        }
    }
    __syncthreads();

    float accd[4][8] = {};
    for (int ch = 0; ch <= rb; ch++) {
        for (int i = tid; i < 64 * 32; i += 256) {
            int r = i >> 5, c = (i & 31) * 4;
            *(float4*)&bufB[r * 128 + c] =
                *(const float4*)&v[(rowbase + ch * 64 + r) * Dd + colbase + c];
        }
        __syncthreads();
#pragma unroll 2
        for (int kk = 0; kk < 64; kk++) {
            float4 v0 = *(const float4*)&bufB[kk * 128 + tx*4];
            float4 v1 = *(const float4*)&bufB[kk * 128 + 64 + tx*4];
            float p[4];
#pragma unroll
            for (int i = 0; i < 4; i++) p[i] = sc[(ty*4 + i) * 513 + ch*64 + kk];
#pragma unroll
            for (int i = 0; i < 4; i++) {
                accd[i][0] += p[i]*v0.x; accd[i][1] += p[i]*v0.y;
                accd[i][2] += p[i]*v0.z; accd[i][3] += p[i]*v0.w;
                accd[i][4] += p[i]*v1.x; accd[i][5] += p[i]*v1.y;
                accd[i][6] += p[i]*v1.z; accd[i][7] += p[i]*v1.w;
            }
        }
        __syncthreads();
    }

    {
        size_t mbase = (size_t)bh * (128 * 128);
        for (int i = tid; i < 128 * 32; i += 256)
            *(float4*)&bufB[i * 4] = *(const float4*)&g_mem[mbase + (size_t)i * 4];
        if (tid < 128) z_s[tid] = g_zst[bh * 128 + tid];
        for (int i = tid; i < 64 * 128; i += 256) {
            int r = i >> 7, c = i & 127;
            qsT[c * 65 + r] = elu1(qsT[c * 65 + r]);
        }
    }
    __syncthreads();

    float accn[4][8] = {};
    float den[4] = {};
#pragma unroll 2
    for (int kk = 0; kk < 128; kk++) {
        float a[4];
#pragma unroll
        for (int i = 0; i < 4; i++) a[i] = qsT[kk * 65 + ty*4 + i];
        float4 m0 = *(const float4*)&bufB[kk * 128 + tx*4];
        float4 m1 = *(const float4*)&bufB[kk * 128 + 64 + tx*4];
        float zk = z_s[kk];
#pragma unroll
        for (int i = 0; i < 4; i++) {
            den[i] += a[i] * zk;
            accn[i][0] += a[i]*m0.x; accn[i][1] += a[i]*m0.y;
            accn[i][2] += a[i]*m0.z; accn[i][3] += a[i]*m0.w;
            accn[i][4] += a[i]*m1.x; accn[i][5] += a[i]*m1.y;
            accn[i][6] += a[i]*m1.z; accn[i][7] += a[i]*m1.w;
        }
    }

#pragma unroll
    for (int i = 0; i < 4; i++) {
        size_t grow = rowbase + r0 + ty*4 + i;
        float invd = 1.0f / den[i];
#pragma unroll
        for (int g = 0; g < 2; g++) {
            int c0 = g*64 + tx*4;
#pragma unroll
            for (int j = 0; j < 4; j++) {
                int col = c0 + j;
                float gt = 1.0f / (1.0f + __expf(-betas[h * 128 + col]));
                float val = gt * (accn[i][g*4+j] * invd) + (1.0f - gt) * accd[i][g*4+j];
                att_h[grow * Dd + colbase + col] = __float2half_rn(val);
            }
        }
    }
    __syncthreads();

    for (int i = tid; i < 64 * 128; i += 256) {
        int r = i >> 7, c = i & 127;
        skT[c * 65 + r] = elu1(k[(rowbase + r0 + r) * Dd + colbase + c]);
    }
    __syncthreads();

    float accv[4][8] = {};
    float denk[4] = {};
#pragma unroll 2
    for (int kk = 0; kk < 128; kk++) {
        float a[4];
#pragma unroll
        for (int i = 0; i < 4; i++) a[i] = skT[kk * 65 + ty*4 + i];
        float4 m0 = *(const float4*)&bufB[kk * 128 + tx*4];
        float4 m1 = *(const float4*)&bufB[kk * 128 + 64 + tx*4];
        float zk = z_s[kk];
#pragma unroll
        for (int i = 0; i < 4; i++) {
            denk[i] += a[i] * zk;
            accv[i][0] += a[i]*m0.x; accv[i][1] += a[i]*m0.y;
            accv[i][2] += a[i]*m0.z; accv[i][3] += a[i]*m0.w;
            accv[i][4] += a[i]*m1.x; accv[i][5] += a[i]*m1.y;
            accv[i][6] += a[i]*m1.z; accv[i][7] += a[i]*m1.w;
        }
    }
#pragma unroll
    for (int i = 0; i < 4; i++) {
        size_t grow = rowbase + r0 + ty*4 + i;
        float invd = 1.0f / denk[i];
#pragma unroll
        for (int g = 0; g < 2; g++) {
            int c0 = g*64 + tx*4;
            float4 vv = *(const float4*)&v[grow * Dd + colbase + c0];
            float4 o;
            o.x = vv.x - accv[i][g*4+0] * invd;
            o.y = vv.y - accv[i][g*4+1] * invd;
            o.z = vv.z - accv[i][g*4+2] * invd;
            o.w = vv.w - accv[i][g*4+3] * invd;
            *(float4*)&g_vdel[((size_t)bh * Ll + r0 + ty*4 + i) * 128 + c0] = o;
        }
    }
}

// ---------------- attention kernel B: mem += sk^T @ v_del ; z += sum(sk) ----------------
__global__ void __launch_bounds__(256)
attn_seg_b(const float* __restrict__ k, int seg)
{
    __shared__ float sk8[8][32];
    __shared__ float vd8[8][128];
    const int tid = threadIdx.x;
    const int tx = tid & 15, ty = tid >> 4;
    const int bh = blockIdx.x;
    const int dkbase = blockIdx.y * 32;
    const int b = bh >> 4, h = bh & 15;
    const size_t rowbase = (size_t)(b * Ss + seg * Ll);

    float acc[2][8] = {};
    float zacc[2] = {};

    const int lrow = tid >> 5, lcol = tid & 31;

    for (int l0 = 0; l0 < Ll; l0 += 8) {
        sk8[lrow][lcol] = elu1(k[(rowbase + l0 + lrow) * Dd + h * 128 + dkbase + lcol]);
        *(float4*)&vd8[lrow][(tid & 31) * 4] =
            *(const float4*)&g_vdel[((size_t)bh * Ll + l0 + lrow) * 128 + (tid & 31) * 4];
        __syncthreads();
#pragma unroll
        for (int l = 0; l < 8; l++) {
            float a0 = sk8[l][ty*2];
            float a1 = sk8[l][ty*2 + 1];
            zacc[0] += a0; zacc[1] += a1;
            float4 b0 = *(const float4*)&vd8[l][tx*8];
            float4 b1 = *(const float4*)&vd8[l][tx*8 + 4];
            float bb[8] = {b0.x, b0.y, b0.z, b0.w, b1.x, b1.y, b1.z, b1.w};
#pragma unroll
            for (int j = 0; j < 8; j++) {
                acc[0][j] += a0 * bb[j];
                acc[1][j] += a1 * bb[j];
            }
        }
        __syncthreads();
    }

    size_t mbase = (size_t)bh * 128 * 128;
#pragma unroll
    for (int i = 0; i < 2; i++) {
        int dk = dkbase + ty*2 + i;
#pragma unroll
        for (int g = 0; g < 2; g++) {
            float4* p = (float4*)&g_mem[mbase + (size_t)dk * 128 + tx*8 + g*4];
            float4 cur = *p;
            cur.x += acc[i][g*4+0]; cur.y += acc[i][g*4+1];
            cur.z += acc[i][g*4+2]; cur.w += acc[i][g*4+3];
            *p = cur;
        }
        if (tx == 0) g_zst[bh * 128 + dk] += zacc[i];
    }
}

// ---------------- residual + LayerNorm ----------------
__global__ void __launch_bounds__(256)
resid_ln(const float* __restrict__ h2, const float* __restrict__ x,
         const float* __restrict__ w, const float* __restrict__ bsh,
         float* __restrict__ out)
{
    __shared__ float ybuf[Dd];
    __shared__ float red[17];
    const int row = blockIdx.x;
    const int tid = threadIdx.x;
    const float* hr = h2 + (size_t)row * Dd;
    const float* xr = x  + (size_t)row * Dd;

    float s = 0.0f, sq = 0.0f;
    for (int c = tid; c < Dd; c += 256) {
        float yv = hr[c] + xr[c];
        ybuf[c] = yv;
        s += yv; sq += yv * yv;
    }
#pragma unroll
    for (int o = 16; o > 0; o >>= 1) {
        s  += __shfl_xor_sync(0xffffffffu, s, o);
        sq += __shfl_xor_sync(0xffffffffu, sq, o);
    }
    int warp = tid >> 5, lane = tid & 31;
    if (lane == 0) { red[warp] = s; red[8 + warp] = sq; }
    __syncthreads();
    if (tid == 0) {
        float S = 0, SQ = 0;
        for (int i = 0; i < 8; i++) { S += red[i]; SQ += red[8 + i]; }
        red[0] = S; red[1] = SQ;
    }
    __syncthreads();
    float mu  = red[0] / (float)Dd;
    float var = red[1] / (float)Dd - mu * mu;
    float inv = rsqrtf(var + 1e-5f);
    for (int c = tid; c < Dd; c += 256)
        out[(size_t)row * Dd + c] = (ybuf[c] - mu) * inv * w[c] + bsh[c];
}

// ---------------- launch ----------------
extern "C" void kernel_launch(void* const* d_in, const int* in_sizes, int n_in,
                              void* d_out, int out_size)
{
    const float* x    = (const float*)d_in[0];
    const float* Wq   = (const float*)d_in[1];
    const float* bq   = (const float*)d_in[2];
    const float* Wk   = (const float*)d_in[3];
    const float* bk   = (const float*)d_in[4];
    const float* Wv   = (const float*)d_in[5];
    const float* bv   = (const float*)d_in[6];
    const float* Wo   = (const float*)d_in[7];
    const float* bo   = (const float*)d_in[8];
    const float* beta = (const float*)d_in[9];
    const float* W1   = (const float*)d_in[10];
    const float* b1   = (const float*)d_in[11];
    const float* W2   = (const float*)d_in[12];
    const float* b2   = (const float*)d_in[13];
    const float* lnw  = (const float*)d_in[14];
    const float* lnb  = (const float*)d_in[15];
    float* out = (float*)d_out;

    float *pq, *pk, *pv, *ph2;
    __half *pxh, *path, *pah, *ph1h;
    __half *wq, *wk, *wv, *wo, *w1, *w2;
    cudaGetSymbolAddress((void**)&pq,   g_q);
    cudaGetSymbolAddress((void**)&pk,   g_k);
    cudaGetSymbolAddress((void**)&pv,   g_v);
    cudaGetSymbolAddress((void**)&ph2,  g_h2);
    cudaGetSymbolAddress((void**)&pxh,  g_x_h);
    cudaGetSymbolAddress((void**)&path, g_att_h);
    cudaGetSymbolAddress((void**)&pah,  g_a_h);
    cudaGetSymbolAddress((void**)&ph1h, g_h1_h);
    cudaGetSymbolAddress((void**)&wq, g_wq);
    cudaGetSymbolAddress((void**)&wk, g_wk);
    cudaGetSymbolAddress((void**)&wv, g_wv);
    cudaGetSymbolAddress((void**)&wo, g_wo);
    cudaGetSymbolAddress((void**)&w1, g_w1);
    cudaGetSymbolAddress((void**)&w2, g_w2);

    cudaFuncSetAttribute(attn_seg_a, cudaFuncAttributeMaxDynamicSharedMemorySize, SMEM_A_BYTES);
    cudaFuncSetAttribute(gemm_mma<0>, cudaFuncAttributeMaxDynamicSharedMemorySize, GEMM_SMEM_BYTES);
    cudaFuncSetAttribute(gemm_mma<1>, cudaFuncAttributeMaxDynamicSharedMemorySize, GEMM_SMEM_BYTES);
    cudaFuncSetAttribute(gemm_mma<2>, cudaFuncAttributeMaxDynamicSharedMemorySize, GEMM_SMEM_BYTES);

    // launch order chosen so ncu (-s 5 -c 1) captures launch #6 = V projection GEMM
    init_state_kernel<<<2048, 256>>>();                                   // 1
    conv_x<<<(BSr * Dd) / 1024, 256>>>(x, pxh);                           // 2
    convt_all<<<12288, 256>>>(Wq, Wk, Wv, Wo, W1, W2,                     // 3
                              wq, wk, wv, wo, w1, w2);

    dim3 gP(Dd/128, BSr/128);   // (16, 64)
    gemm_mma<0><<<gP, 256, GEMM_SMEM_BYTES>>>(pxh, wq, bq, pq, nullptr, BSr, Dd, Dd);  // 4
    gemm_mma<0><<<gP, 256, GEMM_SMEM_BYTES>>>(pxh, wk, bk, pk, nullptr, BSr, Dd, Dd);  // 5
    gemm_mma<0><<<gP, 256, GEMM_SMEM_BYTES>>>(pxh, wv, bv, pv, nullptr, BSr, Dd, Dd);  // 6

    for (int seg = 0; seg < NSEGc; seg++) {
        attn_seg_a<<<dim3(8, 32), 256, SMEM_A_BYTES>>>(pq, pk, pv, beta, path, seg);
        attn_seg_b<<<dim3(32, 4), 256>>>(pk, seg);
    }

    gemm_mma<1><<<gP, 256, GEMM_SMEM_BYTES>>>(path, wo, bo, nullptr, pah, BSr, Dd, Dd);
    dim3 gW1(DH/128, BSr/128);  // (64, 64)
    gemm_mma<2><<<gW1, 256, GEMM_SMEM_BYTES>>>(pah, w1, b1, nullptr, ph1h, BSr, DH, Dd);
    gemm_mma<0><<<gP, 256, GEMM_SMEM_BYTES>>>(ph1h, w2, b2, ph2, nullptr, BSr, Dd, DH);

    resid_ln<<<BSr, 256>>>(ph2, x, lnw, lnb, out);
}

// round 6
// speedup vs baseline: 5.9061x; 1.4708x over previous
#include <cuda_runtime.h>
#include <cuda_fp16.h>
#include <cstdint>

// ---------------- problem constants ----------------
#define Bb   2
#define Ss   4096
#define Dd   2048
#define Hh   16
#define DH   8192
#define Ll   512
#define NSEGc 8
#define BSr  (Bb*Ss)      // 8192 rows
#define BHn  (Bb*Hh)      // 32 (batch,head) pairs

// ---------------- scratch (device globals; no allocs allowed) ----------------
__device__ float g_h2 [(size_t)BSr*Dd];
__device__ __half g_x_h  [(size_t)BSr*Dd];
__device__ __half g_q_h  [(size_t)BSr*Dd];
__device__ __half g_k_h  [(size_t)BSr*Dd];
__device__ __half g_v_h  [(size_t)BSr*Dd];
__device__ __half g_att_h[(size_t)BSr*Dd];
__device__ __half g_a_h  [(size_t)BSr*Dd];
__device__ __half g_h1_h [(size_t)BSr*DH];
// transposed fp16 weights [N,K]
__device__ __half g_wq[(size_t)Dd*Dd];
__device__ __half g_wk[(size_t)Dd*Dd];
__device__ __half g_wv[(size_t)Dd*Dd];
__device__ __half g_wo[(size_t)Dd*Dd];
__device__ __half g_w1[(size_t)DH*Dd];
__device__ __half g_w2[(size_t)Dd*DH];
// attention state
__device__ float  g_mem  [BHn*128*128];
__device__ __half g_mem_h[BHn*128*128];
__device__ float  g_zst  [BHn*128];
__device__ __half g_vdel_h[BHn*Ll*128];

// ---------------- helpers ----------------
__device__ __forceinline__ float gelu_exact(float x) {
    return 0.5f * x * (1.0f + erff(x * 0.70710678118654752440f));
}
__device__ __forceinline__ float elu1(float x) {
    return (x > 0.0f) ? (x + 1.0f) : __expf(x);
}
__device__ __forceinline__ uint32_t smem_u32(const void* p) {
    uint32_t a;
    asm("{ .reg .u64 t; cvta.to.shared.u64 t, %1; cvt.u32.u64 %0, t; }" : "=r"(a) : "l"(p));
    return a;
}

// ---------------- mma / ldmatrix / cp.async primitives ----------------
__device__ __forceinline__ void mma16816(float* c, const uint32_t* a, const uint32_t* b) {
    asm volatile(
        "mma.sync.aligned.m16n8k16.row.col.f32.f16.f16.f32 "
        "{%0,%1,%2,%3}, {%4,%5,%6,%7}, {%8,%9}, {%0,%1,%2,%3};"
        : "+f"(c[0]), "+f"(c[1]), "+f"(c[2]), "+f"(c[3])
        : "r"(a[0]), "r"(a[1]), "r"(a[2]), "r"(a[3]), "r"(b[0]), "r"(b[1]));
}
__device__ __forceinline__ void ldsm4(uint32_t addr, uint32_t* r) {
    asm volatile("ldmatrix.sync.aligned.m8n8.x4.shared.b16 {%0,%1,%2,%3}, [%4];"
                 : "=r"(r[0]), "=r"(r[1]), "=r"(r[2]), "=r"(r[3]) : "r"(addr));
}
__device__ __forceinline__ void ldsm4t(uint32_t addr, uint32_t* r) {
    asm volatile("ldmatrix.sync.aligned.m8n8.x4.trans.shared.b16 {%0,%1,%2,%3}, [%4];"
                 : "=r"(r[0]), "=r"(r[1]), "=r"(r[2]), "=r"(r[3]) : "r"(addr));
}
__device__ __forceinline__ void cp_async16(uint32_t saddr, const void* gaddr) {
    asm volatile("cp.async.cg.shared.global [%0], [%1], 16;" :: "r"(saddr), "l"(gaddr));
}
#define CP_COMMIT() asm volatile("cp.async.commit_group;" ::: "memory")
#define CP_WAIT2()  asm volatile("cp.async.wait_group 2;" ::: "memory")
#define CP_WAIT0()  asm volatile("cp.async.wait_group 0;" ::: "memory")

// GEMM smem tile: 128 rows x 64B, XOR swizzle on 16B chunks
__device__ __forceinline__ uint32_t swz_off(int row, int kbyte) {
    return (uint32_t)(row * 64 + ((((kbyte) >> 4) ^ ((row >> 1) & 3)) << 4));
}
// attention fp16 tile: rows of 128 halves = 256B, chunk16 = colhalf/8 (0..15)
__device__ __forceinline__ uint32_t swzh(int row, int chunk16) {
    return (uint32_t)(row * 256 + ((chunk16 ^ (row & 7)) << 4));
}

// ---------------- state init ----------------
__global__ void init_state_kernel() {
    int i = blockIdx.x * blockDim.x + threadIdx.x;
    if (i < BHn*128*128) { g_mem[i] = 0.0f; g_mem_h[i] = __float2half(0.0f); }
    if (i < BHn*128)     g_zst[i] = 1.0f / 128.0f;
}

// ---------------- weights convert+transpose AND x convert (fused) ----------------
__global__ void __launch_bounds__(256)
convt_all(const float* __restrict__ x, __half* __restrict__ xh,
          const float* __restrict__ Wq, const float* __restrict__ Wk,
          const float* __restrict__ Wv, const float* __restrict__ Wo,
          const float* __restrict__ W1, const float* __restrict__ W2,
          __half* tq, __half* tk, __half* tv, __half* to_, __half* t1, __half* t2)
{
    const int id = blockIdx.x;
    const int tid = threadIdx.x;
    if (id >= 12288) {  // x convert: 4096 blocks x 4096 elems
        size_t base4 = (size_t)(id - 12288) * 1024;
#pragma unroll
        for (int j = 0; j < 4; j++) {
            size_t i4 = base4 + tid + j * 256;
            float4 v = ((const float4*)x)[i4];
            __half2 a, b;
            a.x = __float2half_rn(v.x); a.y = __float2half_rn(v.y);
            b.x = __float2half_rn(v.z); b.y = __float2half_rn(v.w);
            ((__half2*)xh)[i4*2]   = a;
            ((__half2*)xh)[i4*2+1] = b;
        }
        return;
    }
    const float* W; __half* T; int K, N, nb, kb;
    if (id < 4096) {
        int w = id >> 10, t = id & 1023;
        nb = t & 31; kb = t >> 5; K = 2048; N = 2048;
        if (w == 0)      { W = Wq; T = tq; }
        else if (w == 1) { W = Wk; T = tk; }
        else if (w == 2) { W = Wv; T = tv; }
        else             { W = Wo; T = to_; }
    } else if (id < 8192) {
        int t = id - 4096; nb = t & 127; kb = t >> 7; K = 2048; N = 8192;
        W = W1; T = t1;
    } else {
        int t = id - 8192; nb = t & 31; kb = t >> 5; K = 8192; N = 2048;
        W = W2; T = t2;
    }
    __shared__ float tbuf[64][65];
    const int n0 = nb * 64, k0 = kb * 64;
    for (int i = tid; i < 64*64; i += 256) {
        int r = i >> 6, c = i & 63;
        tbuf[r][c] = W[(size_t)(k0 + r) * N + n0 + c];
    }
    __syncthreads();
    for (int i = tid; i < 64*64; i += 256) {
        int rn = i >> 6, ck = i & 63;
        T[(size_t)(n0 + rn) * K + k0 + ck] = __float2half_rn(tbuf[ck][rn]);
    }
}

// ---------------- tensor-core GEMM (unchanged from R5 core) ----------------
#define GEMM_STAGES 4
#define GEMM_STAGE_BYTES 16384
#define GEMM_SMEM_BYTES  (GEMM_STAGES * GEMM_STAGE_BYTES)

template<int EPI>   // 0 fp32 out, 1 fp16 out, 2 GELU+fp16 out
__global__ void __launch_bounds__(256, 2)
gemm_mma(const __half* __restrict__ A, const __half* __restrict__ Bp,
         const float* __restrict__ bias,
         float* __restrict__ Cf, __half* __restrict__ Ch, int M, int N, int K)
{
    extern __shared__ char sm_raw[];
    const uint32_t smem = smem_u32(sm_raw);
    const int tid  = threadIdx.x;
    const int lane = tid & 31;
    const int w    = tid >> 5;
    const int wm   = w & 3;
    const int wn   = w >> 2;
    const size_t bm = (size_t)blockIdx.y * 128;
    const size_t bn = (size_t)blockIdx.x * 128;
    const int KT = K >> 5;

    const int a_row = wm * 32 + (lane & 7) + ((lane >> 3) & 1) * 8;
    const int a_kb  = ((lane >> 4) & 1) * 16;
    const int b_row = wn * 64 + (lane & 7) + ((lane >> 4) & 1) * 8;
    const int b_kb  = ((lane >> 3) & 1) * 16;

    const int r0c = tid >> 2, j0 = tid & 3;
    const int r1c = (tid + 256) >> 2, j1 = (tid + 256) & 3;
    const uint32_t so0 = swz_off(r0c, j0 * 16);
    const uint32_t so1 = swz_off(r1c, j1 * 16);

    float acc[2][8][4];
#pragma unroll
    for (int i = 0; i < 2; i++)
#pragma unroll
        for (int j = 0; j < 8; j++)
#pragma unroll
            for (int q = 0; q < 4; q++) acc[i][j][q] = 0.0f;

    auto load_stage = [&](int st, int itk) {
        const uint32_t sb = smem + st * GEMM_STAGE_BYTES;
        const size_t k0 = (size_t)itk * 32;
        cp_async16(sb +        so0, A  + (bm + r0c) * (size_t)K + k0 + j0 * 8);
        cp_async16(sb +        so1, A  + (bm + r1c) * (size_t)K + k0 + j1 * 8);
        cp_async16(sb + 8192 + so0, Bp + (bn + r0c) * (size_t)K + k0 + j0 * 8);
        cp_async16(sb + 8192 + so1, Bp + (bn + r1c) * (size_t)K + k0 + j1 * 8);
    };

#pragma unroll
    for (int s = 0; s < GEMM_STAGES - 1; s++) { load_stage(s, s); CP_COMMIT(); }

    for (int it = 0; it < KT; it++) {
        CP_WAIT2();
        __syncthreads();
        if (it + GEMM_STAGES - 1 < KT)
            load_stage((it + GEMM_STAGES - 1) & (GEMM_STAGES - 1), it + GEMM_STAGES - 1);
        CP_COMMIT();

        const uint32_t sb = smem + (it & (GEMM_STAGES - 1)) * GEMM_STAGE_BYTES;
#pragma unroll
        for (int ks = 0; ks < 2; ks++) {
            uint32_t ah[2][4];
#pragma unroll
            for (int mi = 0; mi < 2; mi++)
                ldsm4(sb + swz_off(a_row + mi * 16, ks * 32 + a_kb), ah[mi]);
            uint32_t bh[8][2];
#pragma unroll
            for (int nt = 0; nt < 4; nt++) {
                uint32_t t4[4];
                ldsm4(sb + 8192 + swz_off(b_row + nt * 16, ks * 32 + b_kb), t4);
                bh[2*nt][0] = t4[0]; bh[2*nt][1] = t4[1];
                bh[2*nt+1][0] = t4[2]; bh[2*nt+1][1] = t4[3];
            }
#pragma unroll
            for (int mi = 0; mi < 2; mi++)
#pragma unroll
                for (int ni = 0; ni < 8; ni++)
                    mma16816(acc[mi][ni], ah[mi], bh[ni]);
        }
    }

    const int rl = lane >> 2, cl = (lane & 3) * 2;
#pragma unroll
    for (int mi = 0; mi < 2; mi++) {
#pragma unroll
        for (int ni = 0; ni < 8; ni++) {
            const float* c = acc[mi][ni];
            const size_t row0 = bm + wm * 32 + mi * 16 + rl;
            const size_t col  = bn + wn * 64 + ni * 8 + cl;
            const float b0 = bias[col], b1 = bias[col + 1];
            float v00 = c[0] + b0, v01 = c[1] + b1;
            float v10 = c[2] + b0, v11 = c[3] + b1;
            if (EPI == 2) {
                v00 = gelu_exact(v00); v01 = gelu_exact(v01);
                v10 = gelu_exact(v10); v11 = gelu_exact(v11);
            }
            if (EPI == 0) {
                *(float2*)(Cf + row0 * (size_t)N + col)       = make_float2(v00, v01);
                *(float2*)(Cf + (row0 + 8) * (size_t)N + col) = make_float2(v10, v11);
            } else {
                __half2 p0, p1;
                p0.x = __float2half_rn(v00); p0.y = __float2half_rn(v01);
                p1.x = __float2half_rn(v10); p1.y = __float2half_rn(v11);
                *(__half2*)(Ch + row0 * (size_t)N + col)       = p0;
                *(__half2*)(Ch + (row0 + 8) * (size_t)N + col) = p1;
            }
        }
    }
}

// ---------------- attention kernel A (tensor-core) ----------------
// dyn smem: qs fp16 [64][256B] @0 ; kv fp16 [64][256B] @16384 ;
//           memb fp16 [128][256B] @32768 ; sc fp32 [64] rows of 2176B @65536
#define AS_KV  16384
#define AS_MEM 32768
#define AS_SC  65536
#define SC_ROWB 2176
#define SMEM_A_BYTES (65536 + 64*SC_ROWB)   // 204800

__device__ __forceinline__ uint32_t sc_off(int row, int col) {
    return (uint32_t)(row * SC_ROWB + ((((col >> 2) ^ (row & 7))) << 4) + ((col & 3) << 2));
}
__device__ __forceinline__ uint32_t p_off(int row, int colh) {
    return (uint32_t)(row * SC_ROWB + ((((colh >> 3) ^ (row & 7))) << 4) + ((colh & 7) << 1));
}

__global__ void __launch_bounds__(256)
attn_seg_a(const __half* __restrict__ q, const __half* __restrict__ k,
           const __half* __restrict__ v, const float* __restrict__ betas,
           __half* __restrict__ att_h, int seg)
{
    extern __shared__ char sma[];
    const uint32_t s_qs  = smem_u32(sma);
    const uint32_t s_kv  = s_qs + AS_KV;
    const uint32_t s_mem = s_qs + AS_MEM;
    const uint32_t s_sc  = s_qs + AS_SC;
    __shared__ float z_s[128], gate_s[128], den_s[64], denk_s[64];

    const int tid = threadIdx.x;
    const int lane = tid & 31;
    const int w = tid >> 5;
    const int wm = w >> 2;      // 0..1
    const int wn = w & 3;       // 0..3
    const int rb = blockIdx.x;  // 0..7
    const int bh = blockIdx.y;  // 0..31
    const int b  = bh >> 4, h = bh & 15;
    const int r0 = rb * 64;
    const size_t rowbase = (size_t)(b * Ss + seg * Ll);
    const int colbase = h * 128;

    // initial async loads: qs (own rows), memb (fp16 mem mirror)
#pragma unroll
    for (int t = 0; t < 4; t++) {
        int idx = tid + t * 256, row = idx >> 4, c = idx & 15;
        cp_async16(s_qs + swzh(row, c), q + (rowbase + r0 + row) * Dd + colbase + c * 8);
    }
#pragma unroll
    for (int t = 0; t < 8; t++) {
        int idx = tid + t * 256, row = idx >> 4, c = idx & 15;
        cp_async16(s_mem + swzh(row, c), g_mem_h + (size_t)bh * 16384 + row * 128 + c * 8);
    }
    CP_COMMIT();
    if (tid < 128) {
        z_s[tid]    = g_zst[bh * 128 + tid];
        gate_s[tid] = 1.0f / (1.0f + __expf(-betas[h * 128 + tid]));
    }

    const float scale = 0.088388347648318447f;
    const int rl = lane >> 2, cl = (lane & 3) * 2;

    // ---- phase 1: scores into sc ----
    for (int ch = 0; ch <= rb; ch++) {
        __syncthreads();
#pragma unroll
        for (int t = 0; t < 4; t++) {
            int idx = tid + t * 256, row = idx >> 4, c = idx & 15;
            cp_async16(s_kv + swzh(row, c), k + (rowbase + ch * 64 + row) * Dd + colbase + c * 8);
        }
        CP_COMMIT(); CP_WAIT0();
        __syncthreads();

        float accs[2][2][4] = {};
#pragma unroll
        for (int ks = 0; ks < 8; ks++) {
            uint32_t a[2][4];
#pragma unroll
            for (int mi = 0; mi < 2; mi++) {
                int arow = wm*32 + mi*16 + (lane & 7) + ((lane >> 3) & 1) * 8;
                int ach  = ks*2 + ((lane >> 4) & 1);
                ldsm4(s_qs + swzh(arow, ach), a[mi]);
            }
            uint32_t t4[4];
            int brow = wn*16 + (lane & 7) + ((lane >> 4) & 1) * 8;
            int bch  = ks*2 + ((lane >> 3) & 1);
            ldsm4(s_kv + swzh(brow, bch), t4);
            uint32_t b0[2] = {t4[0], t4[1]}, b1[2] = {t4[2], t4[3]};
#pragma unroll
            for (int mi = 0; mi < 2; mi++) {
                mma16816(accs[mi][0], a[mi], b0);
                mma16816(accs[mi][1], a[mi], b1);
            }
        }
        // scale + mask + store
#pragma unroll
        for (int mi = 0; mi < 2; mi++)
#pragma unroll
            for (int ni = 0; ni < 2; ni++) {
                int rowl = wm*32 + mi*16 + rl;
                int coll = wn*16 + ni*8 + cl;           // within chunk
                float c0 = accs[mi][ni][0] * scale, c1 = accs[mi][ni][1] * scale;
                float c2 = accs[mi][ni][2] * scale, c3 = accs[mi][ni][3] * scale;
                if (ch == rb) {
                    if (coll     > rowl) c0 = -1e9f;
                    if (coll + 1 > rowl) c1 = -1e9f;
                    if (coll     > rowl + 8) c2 = -1e9f;
                    if (coll + 1 > rowl + 8) c3 = -1e9f;
                }
                int colg = ch*64 + coll;
                *(float2*)(sma + (s_sc - s_qs) + sc_off(rowl,     colg)) = make_float2(c0, c1);
                *(float2*)(sma + (s_sc - s_qs) + sc_off(rowl + 8, colg)) = make_float2(c2, c3);
            }
    }
    __syncthreads();

    // ---- phase 2: softmax + P fp16 convert (per-warp rows) ----
    {
        char* scb = sma + (s_sc - s_qs);
        const int mlim = (rb + 1) * 64;
        for (int rr = 0; rr < 8; rr++) {
            int row = w * 8 + rr;
            int gr  = r0 + row;
            float mx = -1e30f;
            for (int m = lane; m <= gr; m += 32) mx = fmaxf(mx, *(float*)(scb + sc_off(row, m)));
#pragma unroll
            for (int o = 16; o > 0; o >>= 1) mx = fmaxf(mx, __shfl_xor_sync(0xffffffffu, mx, o));
            float s = 0.0f;
            for (int m = lane; m <= gr; m += 32) {
                float* p = (float*)(scb + sc_off(row, m));
                float e = __expf(*p - mx); *p = e; s += e;
            }
#pragma unroll
            for (int o = 16; o > 0; o >>= 1) s += __shfl_xor_sync(0xffffffffu, s, o);
            float inv = 1.0f / s;
            for (int m = lane; m < mlim; m += 32) {
                float* p = (float*)(scb + sc_off(row, m));
                *p = (m <= gr) ? (*p) * inv : 0.0f;
            }
            // convert row to fp16 P (stage then write)
            float tmp[16];
            int nj = mlim >> 5;
            for (int j = 0; j < nj; j++) tmp[j] = *(float*)(scb + sc_off(row, lane + 32*j));
            __syncwarp();
            for (int j = 0; j < nj; j++) {
                int colh = lane + 32*j;
                *(__half*)(scb + p_off(row, colh)) = __float2half_rn(tmp[j]);
            }
            __syncwarp();
        }
    }
    __syncthreads();

    // ---- phase 3: att_dot = P @ V ----
    float accd[2][4][4] = {};
    for (int ch = 0; ch <= rb; ch++) {
        __syncthreads();
#pragma unroll
        for (int t = 0; t < 4; t++) {
            int idx = tid + t * 256, row = idx >> 4, c = idx & 15;
            cp_async16(s_kv + swzh(row, c), v + (rowbase + ch * 64 + row) * Dd + colbase + c * 8);
        }
        CP_COMMIT(); CP_WAIT0();
        __syncthreads();
#pragma unroll
        for (int ks = 0; ks < 4; ks++) {
            uint32_t pa[2][4];
#pragma unroll
            for (int mi = 0; mi < 2; mi++) {
                int arow = wm*32 + mi*16 + (lane & 7) + ((lane >> 3) & 1) * 8;
                int pch  = ch*8 + ks*2 + ((lane >> 4) & 1);
                ldsm4(s_sc + (uint32_t)(arow * SC_ROWB) + (((uint32_t)(pch ^ (arow & 7))) << 4), pa[mi]);
            }
#pragma unroll
            for (int ntp = 0; ntp < 2; ntp++) {
                int vrow = ks*16 + (lane & 7) + ((lane >> 3) & 1) * 8;
                int vch  = wn*4 + ntp*2 + ((lane >> 4) & 1);
                uint32_t t4[4];
                ldsm4t(s_kv + swzh(vrow, vch), t4);
                uint32_t b0[2] = {t4[0], t4[1]}, b1[2] = {t4[2], t4[3]};
#pragma unroll
                for (int mi = 0; mi < 2; mi++) {
                    mma16816(accd[mi][ntp*2],     pa[mi], b0);
                    mma16816(accd[mi][ntp*2 + 1], pa[mi], b1);
                }
            }
        }
    }

    // ---- phase 4: sq = elu1(q); den; att_mem = sq @ mem ----
    __syncthreads();
    for (int i = tid; i < 64 * 64; i += 256) {       // elu1 in place on qs (half2)
        int row = i >> 6, p = i & 63;
        uint32_t adr = s_qs + swzh(row, p >> 2) + (p & 3) * 4;
        __half2 hv = *(__half2*)(sma + (adr - s_qs));
        hv.x = __float2half_rn(elu1(__half2float(hv.x)));
        hv.y = __float2half_rn(elu1(__half2float(hv.y)));
        *(__half2*)(sma + (adr - s_qs)) = hv;
    }
    __syncthreads();
    {
        int row = tid >> 2, qtr = tid & 3;
        float dsum = 0.0f;
        for (int pi = 0; pi < 16; pi++) {
            int p = qtr * 16 + pi;
            uint32_t adr = s_qs + swzh(row, p >> 2) + (p & 3) * 4;
            __half2 hv = *(__half2*)(sma + (adr - s_qs));
            dsum += __half2float(hv.x) * z_s[2*p] + __half2float(hv.y) * z_s[2*p + 1];
        }
        dsum += __shfl_xor_sync(0xffffffffu, dsum, 1);
        dsum += __shfl_xor_sync(0xffffffffu, dsum, 2);
        if (qtr == 0) den_s[row] = dsum;
    }
    float accm[2][4][4] = {};
#pragma unroll
    for (int ks = 0; ks < 8; ks++) {
        uint32_t a[2][4];
#pragma unroll
        for (int mi = 0; mi < 2; mi++) {
            int arow = wm*32 + mi*16 + (lane & 7) + ((lane >> 3) & 1) * 8;
            int ach  = ks*2 + ((lane >> 4) & 1);
            ldsm4(s_qs + swzh(arow, ach), a[mi]);
        }
#pragma unroll
        for (int ntp = 0; ntp < 2; ntp++) {
            int mrow = ks*16 + (lane & 7) + ((lane >> 3) & 1) * 8;
            int mch  = wn*4 + ntp*2 + ((lane >> 4) & 1);
            uint32_t t4[4];
            ldsm4t(s_mem + swzh(mrow, mch), t4);
            uint32_t b0[2] = {t4[0], t4[1]}, b1[2] = {t4[2], t4[3]};
#pragma unroll
            for (int mi = 0; mi < 2; mi++) {
                mma16816(accm[mi][ntp*2],     a[mi], b0);
                mma16816(accm[mi][ntp*2 + 1], a[mi], b1);
            }
        }
    }
    __syncthreads();

    // ---- combine + store att ----
#pragma unroll
    for (int mi = 0; mi < 2; mi++)
#pragma unroll
        for (int ni = 0; ni < 4; ni++) {
            int rowl0 = wm*32 + mi*16 + rl;
            int col   = wn*32 + ni*8 + cl;
            float g0 = gate_s[col], g1 = gate_s[col + 1];
#pragma unroll
            for (int rr = 0; rr < 2; rr++) {
                int rowl = rowl0 + rr*8;
                float invd = 1.0f / den_s[rowl];
                float m0 = accm[mi][ni][rr*2]   * invd;
                float m1 = accm[mi][ni][rr*2+1] * invd;
                float d0 = accd[mi][ni][rr*2], d1 = accd[mi][ni][rr*2+1];
                __half2 o;
                o.x = __float2half_rn(g0 * m0 + (1.0f - g0) * d0);
                o.y = __float2half_rn(g1 * m1 + (1.0f - g1) * d1);
                *(__half2*)(att_h + (rowbase + r0 + rowl) * Dd + colbase + col) = o;
            }
        }

    // ---- phase 5: sk = elu1(k own rows); denk; v_del ----
    __syncthreads();
#pragma unroll
    for (int t = 0; t < 4; t++) {
        int idx = tid + t * 256, row = idx >> 4, c = idx & 15;
        cp_async16(s_kv + swzh(row, c), k + (rowbase + r0 + row) * Dd + colbase + c * 8);
    }
    CP_COMMIT(); CP_WAIT0();
    __syncthreads();
    for (int i = tid; i < 64 * 64; i += 256) {
        int row = i >> 6, p = i & 63;
        uint32_t adr = s_kv + swzh(row, p >> 2) + (p & 3) * 4;
        __half2 hv = *(__half2*)(sma + (adr - s_qs));
        hv.x = __float2half_rn(elu1(__half2float(hv.x)));
        hv.y = __float2half_rn(elu1(__half2float(hv.y)));
        *(__half2*)(sma + (adr - s_qs)) = hv;
    }
    __syncthreads();
    {
        int row = tid >> 2, qtr = tid & 3;
        float dsum = 0.0f;
        for (int pi = 0; pi < 16; pi++) {
            int p = qtr * 16 + pi;
            uint32_t adr = s_kv + swzh(row, p >> 2) + (p & 3) * 4;
            __half2 hv = *(__half2*)(sma + (adr - s_qs));
            dsum += __half2float(hv.x) * z_s[2*p] + __half2float(hv.y) * z_s[2*p + 1];
        }
        dsum += __shfl_xor_sync(0xffffffffu, dsum, 1);
        dsum += __shfl_xor_sync(0xffffffffu, dsum, 2);
        if (qtr == 0) denk_s[row] = dsum;
    }
    float accv[2][4][4] = {};
#pragma unroll
    for (int ks = 0; ks < 8; ks++) {
        uint32_t a[2][4];
#pragma unroll
        for (int mi = 0; mi < 2; mi++) {
            int arow = wm*32 + mi*16 + (lane & 7) + ((lane >> 3) & 1) * 8;
            int ach  = ks*2 + ((lane >> 4) & 1);
            ldsm4(s_kv + swzh(arow, ach), a[mi]);
        }
#pragma unroll
        for (int ntp = 0; ntp < 2; ntp++) {
            int mrow = ks*16 + (lane & 7) + ((lane >> 3) & 1) * 8;
            int mch  = wn*4 + ntp*2 + ((lane >> 4) & 1);
            uint32_t t4[4];
            ldsm4t(s_mem + swzh(mrow, mch), t4);
            uint32_t b0[2] = {t4[0], t4[1]}, b1[2] = {t4[2], t4[3]};
#pragma unroll
            for (int mi = 0; mi < 2; mi++) {
                mma16816(accv[mi][ntp*2],     a[mi], b0);
                mma16816(accv[mi][ntp*2 + 1], a[mi], b1);
            }
        }
    }
    __syncthreads();
#pragma unroll
    for (int mi = 0; mi < 2; mi++)
#pragma unroll
        for (int ni = 0; ni < 4; ni++) {
            int rowl0 = wm*32 + mi*16 + rl;
            int col   = wn*32 + ni*8 + cl;
#pragma unroll
            for (int rr = 0; rr < 2; rr++) {
                int rowl = rowl0 + rr*8;
                float invk = 1.0f / denk_s[rowl];
                __half2 vv = *(const __half2*)(v + (rowbase + r0 + rowl) * Dd + colbase + col);
                __half2 o;
                o.x = __float2half_rn(__half2float(vv.x) - accv[mi][ni][rr*2]   * invk);
                o.y = __float2half_rn(__half2float(vv.y) - accv[mi][ni][rr*2+1] * invk);
                *(__half2*)(g_vdel_h + ((size_t)bh * Ll + r0 + rowl) * 128 + col) = o;
            }
        }
}

// ---------------- attention kernel B: mem += sk^T @ v_del ; z += colsum(sk) ----------------
__global__ void __launch_bounds__(256)
attn_seg_b(const __half* __restrict__ k, int seg)
{
    __shared__ __align__(16) char skb[16384];   // 64 x 256B
    __shared__ __align__(16) char vdb[16384];
    const uint32_t s_sk = smem_u32(skb);
    const uint32_t s_vd = smem_u32(vdb);

    const int tid = threadIdx.x;
    const int lane = tid & 31;
    const int w = tid >> 5;
    const int wm = w >> 2;      // 0..1 (64 dk rows each)
    const int wn = w & 3;       // 0..3 (32 dv cols each)
    const int bh = blockIdx.x;
    const int b = bh >> 4, h = bh & 15;
    const size_t rowbase = (size_t)(b * Ss + seg * Ll);
    const int colbase = h * 128;

    float acc[4][4][4] = {};
    float zacc = 0.0f;

    for (int ch = 0; ch < 8; ch++) {
        __syncthreads();
        // sk: scalar elu convert into swizzled smem
        for (int i = tid; i < 64 * 64; i += 256) {
            int row = i >> 6, p = i & 63;
            __half2 hv = *(const __half2*)(k + (rowbase + ch*64 + row) * Dd + colbase + 2*p);
            hv.x = __float2half_rn(elu1(__half2float(hv.x)));
            hv.y = __float2half_rn(elu1(__half2float(hv.y)));
            *(__half2*)(skb + swzh(row, p >> 2) + (p & 3) * 4) = hv;
        }
        // v_del: cp.async
#pragma unroll
        for (int t = 0; t < 4; t++) {
            int idx = tid + t * 256, row = idx >> 4, c = idx & 15;
            cp_async16(s_vd + swzh(row, c),
                       g_vdel_h + ((size_t)bh * Ll + ch*64 + row) * 128 + c * 8);
        }
        CP_COMMIT(); CP_WAIT0();
        __syncthreads();

#pragma unroll
        for (int ks = 0; ks < 4; ks++) {
            uint32_t a[4][4];
#pragma unroll
            for (int mt = 0; mt < 4; mt++) {
                int srow = ks*16 + (lane & 7) + ((lane >> 4) & 1) * 8;
                int sch  = ((wm*64 + mt*16) >> 3) + ((lane >> 3) & 1);
                ldsm4t(s_sk + swzh(srow, sch), a[mt]);
            }
#pragma unroll
            for (int ntp = 0; ntp < 2; ntp++) {
                int vrow = ks*16 + (lane & 7) + ((lane >> 3) & 1) * 8;
                int vch  = wn*4 + ntp*2 + ((lane >> 4) & 1);
                uint32_t t4[4];
                ldsm4t(s_vd + swzh(vrow, vch), t4);
                uint32_t b0[2] = {t4[0], t4[1]}, b1[2] = {t4[2], t4[3]};
#pragma unroll
                for (int mt = 0; mt < 4; mt++) {
                    mma16816(acc[mt][ntp*2],     a[mt], b0);
                    mma16816(acc[mt][ntp*2 + 1], a[mt], b1);
                }
            }
        }
        // z partial: threads 0-127 own a dk column
        if (tid < 128) {
            int col = tid;
            for (int r = 0; r < 64; r++) {
                __half hv = *(__half*)(skb + swzh(r, col >> 3) + (col & 7) * 2);
                zacc += __half2float(hv);
            }
        }
    }

    // epilogue: mem fp32 RMW + fp16 mirror
    const int rl = lane >> 2, cl = (lane & 3) * 2;
    size_t mbase = (size_t)bh * 16384;
#pragma unroll
    for (int mt = 0; mt < 4; mt++)
#pragma unroll
        for (int ni = 0; ni < 4; ni++) {
            int col = wn*32 + ni*8 + cl;
#pragma unroll
            for (int rr = 0; rr < 2; rr++) {
                int row = wm*64 + mt*16 + rl + rr*8;
                float2* pf = (float2*)(g_mem + mbase + (size_t)row * 128 + col);
                float2 cur = *pf;
                cur.x += acc[mt][ni][rr*2];
                cur.y += acc[mt][ni][rr*2+1];
                *pf = cur;
                __half2 hm;
                hm.x = __float2half_rn(cur.x); hm.y = __float2half_rn(cur.y);
                *(__half2*)(g_mem_h + mbase + (size_t)row * 128 + col) = hm;
            }
        }
    if (tid < 128) g_zst[bh * 128 + tid] += zacc;
}

// ---------------- residual + LayerNorm ----------------
__global__ void __launch_bounds__(256)
resid_ln(const float* __restrict__ h2, const float* __restrict__ x,
         const float* __restrict__ w, const float* __restrict__ bsh,
         float* __restrict__ out)
{
    __shared__ float ybuf[Dd];
    __shared__ float red[17];
    const int row = blockIdx.x;
    const int tid = threadIdx.x;
    const float* hr = h2 + (size_t)row * Dd;
    const float* xr = x  + (size_t)row * Dd;

    float s = 0.0f, sq = 0.0f;
    for (int c = tid; c < Dd; c += 256) {
        float yv = hr[c] + xr[c];
        ybuf[c] = yv;
        s += yv; sq += yv * yv;
    }
#pragma unroll
    for (int o = 16; o > 0; o >>= 1) {
        s  += __shfl_xor_sync(0xffffffffu, s, o);
        sq += __shfl_xor_sync(0xffffffffu, sq, o);
    }
    int warp = tid >> 5, lane = tid & 31;
    if (lane == 0) { red[warp] = s; red[8 + warp] = sq; }
    __syncthreads();
    if (tid == 0) {
        float S = 0, SQ = 0;
        for (int i = 0; i < 8; i++) { S += red[i]; SQ += red[8 + i]; }
        red[0] = S; red[1] = SQ;
    }
    __syncthreads();
    float mu  = red[0] / (float)Dd;
    float var = red[1] / (float)Dd - mu * mu;
    float inv = rsqrtf(var + 1e-5f);
    for (int c = tid; c < Dd; c += 256)
        out[(size_t)row * Dd + c] = (ybuf[c] - mu) * inv * w[c] + bsh[c];
}

// ---------------- launch ----------------
extern "C" void kernel_launch(void* const* d_in, const int* in_sizes, int n_in,
                              void* d_out, int out_size)
{
    const float* x    = (const float*)d_in[0];
    const float* Wq   = (const float*)d_in[1];
    const float* bq   = (const float*)d_in[2];
    const float* Wk   = (const float*)d_in[3];
    const float* bk   = (const float*)d_in[4];
    const float* Wv   = (const float*)d_in[5];
    const float* bv   = (const float*)d_in[6];
    const float* Wo   = (const float*)d_in[7];
    const float* bo   = (const float*)d_in[8];
    const float* beta = (const float*)d_in[9];
    const float* W1   = (const float*)d_in[10];
    const float* b1   = (const float*)d_in[11];
    const float* W2   = (const float*)d_in[12];
    const float* b2   = (const float*)d_in[13];
    const float* lnw  = (const float*)d_in[14];
    const float* lnb  = (const float*)d_in[15];
    float* out = (float*)d_out;

    float *ph2;
    __half *pxh, *pqh, *pkh, *pvh, *path, *pah, *ph1h;
    __half *wq, *wk, *wv, *wo, *w1, *w2;
    cudaGetSymbolAddress((void**)&ph2,  g_h2);
    cudaGetSymbolAddress((void**)&pxh,  g_x_h);
    cudaGetSymbolAddress((void**)&pqh,  g_q_h);
    cudaGetSymbolAddress((void**)&pkh,  g_k_h);
    cudaGetSymbolAddress((void**)&pvh,  g_v_h);
    cudaGetSymbolAddress((void**)&path, g_att_h);
    cudaGetSymbolAddress((void**)&pah,  g_a_h);
    cudaGetSymbolAddress((void**)&ph1h, g_h1_h);
    cudaGetSymbolAddress((void**)&wq, g_wq);
    cudaGetSymbolAddress((void**)&wk, g_wk);
    cudaGetSymbolAddress((void**)&wv, g_wv);
    cudaGetSymbolAddress((void**)&wo, g_wo);
    cudaGetSymbolAddress((void**)&w1, g_w1);
    cudaGetSymbolAddress((void**)&w2, g_w2);

    cudaFuncSetAttribute(attn_seg_a, cudaFuncAttributeMaxDynamicSharedMemorySize, SMEM_A_BYTES);
    cudaFuncSetAttribute(gemm_mma<0>, cudaFuncAttributeMaxDynamicSharedMemorySize, GEMM_SMEM_BYTES);
    cudaFuncSetAttribute(gemm_mma<1>, cudaFuncAttributeMaxDynamicSharedMemorySize, GEMM_SMEM_BYTES);
    cudaFuncSetAttribute(gemm_mma<2>, cudaFuncAttributeMaxDynamicSharedMemorySize, GEMM_SMEM_BYTES);

    // launch order: #6 = attn_seg_a(seg0) gets profiled by ncu -s 5 -c 1
    init_state_kernel<<<2048, 256>>>();                                    // 1
    convt_all<<<16384, 256>>>(x, pxh, Wq, Wk, Wv, Wo, W1, W2,              // 2
                              wq, wk, wv, wo, w1, w2);

    dim3 gP(Dd/128, BSr/128);
    gemm_mma<1><<<gP, 256, GEMM_SMEM_BYTES>>>(pxh, wq, bq, nullptr, pqh, BSr, Dd, Dd);  // 3
    gemm_mma<1><<<gP, 256, GEMM_SMEM_BYTES>>>(pxh, wk, bk, nullptr, pkh, BSr, Dd, Dd);  // 4
    gemm_mma<1><<<gP, 256, GEMM_SMEM_BYTES>>>(pxh, wv, bv, nullptr, pvh, BSr, Dd, Dd);  // 5

    for (int seg = 0; seg < NSEGc; seg++) {
        attn_seg_a<<<dim3(8, 32), 256, SMEM_A_BYTES>>>(pqh, pkh, pvh, beta, path, seg); // 6 (seg0)
        attn_seg_b<<<32, 256>>>(pkh, seg);
    }

    gemm_mma<1><<<gP, 256, GEMM_SMEM_BYTES>>>(path, wo, bo, nullptr, pah, BSr, Dd, Dd);
    dim3 gW1(DH/128, BSr/128);
    gemm_mma<2><<<gW1, 256, GEMM_SMEM_BYTES>>>(pah, w1, b1, nullptr, ph1h, BSr, DH, Dd);
    gemm_mma<0><<<gP, 256, GEMM_SMEM_BYTES>>>(ph1h, w2, b2, ph2, nullptr, BSr, Dd, DH);

    resid_ln<<<BSr, 256>>>(ph2, x, lnw, lnb, out);
}

// round 7
// speedup vs baseline: 6.8389x; 1.1579x over previous
#include <cuda_runtime.h>
#include <cuda_fp16.h>
#include <cstdint>

// ---------------- problem constants ----------------
#define Bb   2
#define Ss   4096
#define Dd   2048
#define Hh   16
#define DH   8192
#define Ll   512
#define NSEGc 8
#define BSr  (Bb*Ss)
#define BHn  (Bb*Hh)

// ---------------- scratch ----------------
__device__ float g_h2 [(size_t)BSr*Dd];
__device__ __half g_x_h  [(size_t)BSr*Dd];
__device__ __half g_q_h  [(size_t)BSr*Dd];
__device__ __half g_k_h  [(size_t)BSr*Dd];
__device__ __half g_v_h  [(size_t)BSr*Dd];
__device__ __half g_sq_h [(size_t)BSr*Dd];
__device__ __half g_sk_h [(size_t)BSr*Dd];
__device__ __half g_att_h[(size_t)BSr*Dd];
__device__ __half g_a_h  [(size_t)BSr*Dd];
__device__ __half g_h1_h [(size_t)BSr*DH];
// weights [N,K] fp16; qkv concatenated along N
__device__ __half g_wqkv[(size_t)3*Dd*Dd];
__device__ __half g_wo[(size_t)Dd*Dd];
__device__ __half g_w1[(size_t)DH*Dd];
__device__ __half g_w2[(size_t)Dd*DH];
// attention state
__device__ float  g_mem  [BHn*128*128];
__device__ __half g_mem_h[BHn*128*128];
__device__ float  g_zst  [BHn*128];
__device__ __half g_vdel_h[BHn*Ll*128];

// ---------------- helpers ----------------
__device__ __forceinline__ float gelu_exact(float x) {
    return 0.5f * x * (1.0f + erff(x * 0.70710678118654752440f));
}
__device__ __forceinline__ float elu1(float x) {
    return (x > 0.0f) ? (x + 1.0f) : __expf(x);
}
__device__ __forceinline__ uint32_t smem_u32(const void* p) {
    uint32_t a;
    asm("{ .reg .u64 t; cvta.to.shared.u64 t, %1; cvt.u32.u64 %0, t; }" : "=r"(a) : "l"(p));
    return a;
}
__device__ __forceinline__ void mma16816(float* c, const uint32_t* a, const uint32_t* b) {
    asm volatile(
        "mma.sync.aligned.m16n8k16.row.col.f32.f16.f16.f32 "
        "{%0,%1,%2,%3}, {%4,%5,%6,%7}, {%8,%9}, {%0,%1,%2,%3};"
        : "+f"(c[0]), "+f"(c[1]), "+f"(c[2]), "+f"(c[3])
        : "r"(a[0]), "r"(a[1]), "r"(a[2]), "r"(a[3]), "r"(b[0]), "r"(b[1]));
}
__device__ __forceinline__ void ldsm4(uint32_t addr, uint32_t* r) {
    asm volatile("ldmatrix.sync.aligned.m8n8.x4.shared.b16 {%0,%1,%2,%3}, [%4];"
                 : "=r"(r[0]), "=r"(r[1]), "=r"(r[2]), "=r"(r[3]) : "r"(addr));
}
__device__ __forceinline__ void ldsm4t(uint32_t addr, uint32_t* r) {
    asm volatile("ldmatrix.sync.aligned.m8n8.x4.trans.shared.b16 {%0,%1,%2,%3}, [%4];"
                 : "=r"(r[0]), "=r"(r[1]), "=r"(r[2]), "=r"(r[3]) : "r"(addr));
}
__device__ __forceinline__ void cp_async16(uint32_t saddr, const void* gaddr) {
    asm volatile("cp.async.cg.shared.global [%0], [%1], 16;" :: "r"(saddr), "l"(gaddr));
}
#define CP_COMMIT() asm volatile("cp.async.commit_group;" ::: "memory")
#define CP_WAIT1()  asm volatile("cp.async.wait_group 1;" ::: "memory")
#define CP_WAIT0()  asm volatile("cp.async.wait_group 0;" ::: "memory")

// 128B-row tile swizzle (8 chunks of 16B per row)
__device__ __forceinline__ uint32_t aswz(int row, int chunk) {
    return (uint32_t)(row * 128 + ((chunk ^ (row & 7)) << 4));
}
// 256B-row tile swizzle (16 chunks per row; XOR low 3 bits)
__device__ __forceinline__ uint32_t swzh(int row, int chunk16) {
    return (uint32_t)(row * 256 + ((chunk16 ^ (row & 7)) << 4));
}

// ---------------- state init ----------------
__global__ void init_state_kernel() {
    int i = blockIdx.x * blockDim.x + threadIdx.x;
    if (i < BHn*128*128) { g_mem[i] = 0.0f; g_mem_h[i] = __float2half(0.0f); }
    if (i < BHn*128)     g_zst[i] = 1.0f / 128.0f;
}

// ---------------- weights convert+transpose + x convert (fused) ----------------
__global__ void __launch_bounds__(256)
convt_all(const float* __restrict__ x, __half* __restrict__ xh,
          const float* __restrict__ Wq, const float* __restrict__ Wk,
          const float* __restrict__ Wv, const float* __restrict__ Wo,
          const float* __restrict__ W1, const float* __restrict__ W2,
          __half* tqkv, __half* to_, __half* t1, __half* t2)
{
    const int id = blockIdx.x;
    const int tid = threadIdx.x;
    if (id >= 12288) {
        size_t base4 = (size_t)(id - 12288) * 1024;
#pragma unroll
        for (int j = 0; j < 4; j++) {
            size_t i4 = base4 + tid + j * 256;
            float4 v = ((const float4*)x)[i4];
            __half2 a, b;
            a.x = __float2half_rn(v.x); a.y = __float2half_rn(v.y);
            b.x = __float2half_rn(v.z); b.y = __float2half_rn(v.w);
            ((__half2*)xh)[i4*2]   = a;
            ((__half2*)xh)[i4*2+1] = b;
        }
        return;
    }
    const float* W; __half* T; int K, N, nb, kb;
    if (id < 4096) {
        int w = id >> 10, t = id & 1023;
        nb = t & 31; kb = t >> 5; K = 2048; N = 2048;
        if (w < 3)  { W = (w == 0) ? Wq : (w == 1) ? Wk : Wv; T = tqkv + (size_t)w * 4194304; }
        else        { W = Wo; T = to_; }
    } else if (id < 8192) {
        int t = id - 4096; nb = t & 127; kb = t >> 7; K = 2048; N = 8192;
        W = W1; T = t1;
    } else {
        int t = id - 8192; nb = t & 31; kb = t >> 5; K = 8192; N = 2048;
        W = W2; T = t2;
    }
    __shared__ float tbuf[64][65];
    const int n0 = nb * 64, k0 = kb * 64;
    for (int i = tid; i < 64*64; i += 256) {
        int r = i >> 6, c = i & 63;
        tbuf[r][c] = W[(size_t)(k0 + r) * N + n0 + c];
    }
    __syncthreads();
    for (int i = tid; i < 64*64; i += 256) {
        int rn = i >> 6, ck = i & 63;
        T[(size_t)(n0 + rn) * K + k0 + ck] = __float2half_rn(tbuf[ck][rn]);
    }
}

// ---------------- GEMM core (BK=64, 3-stage) ----------------
#define GEMM_STAGE_BYTES 32768            // A 16KB + B 16KB
#define GEMM_SMEM_BYTES  (3 * GEMM_STAGE_BYTES)

// shared mainloop: returns acc via reference arrays
struct GemmCtx {
    int a_row, b_row0, lane, wm, wn;
};

template<typename EpiF>
__device__ __forceinline__ void gemm_body(
    const __half* __restrict__ A, const __half* __restrict__ Bp,
    int M, int N, int K, uint32_t smem, EpiF epi)
{
    const int tid  = threadIdx.x;
    const int lane = tid & 31;
    const int w    = tid >> 5;
    const int wm   = w & 3;
    const int wn   = w >> 2;
    const size_t bm = (size_t)blockIdx.y * 128;
    const size_t bn = (size_t)blockIdx.x * 128;
    const int KT = K >> 6;

    const int a_row = wm * 32 + (lane & 7) + ((lane >> 3) & 1) * 8;
    const int a_ch  = (lane >> 4) & 1;
    const int b_rowb = wn * 64 + (lane & 7) + ((lane >> 4) & 1) * 8;
    const int b_ch  = (lane >> 3) & 1;

    const int rr = tid >> 3, cc = tid & 7;   // cp.async: 32 rows per 256-thread pass

    float acc[2][8][4];
#pragma unroll
    for (int i = 0; i < 2; i++)
#pragma unroll
        for (int j = 0; j < 8; j++)
#pragma unroll
            for (int q = 0; q < 4; q++) acc[i][j][q] = 0.0f;

    auto load_stage = [&](int st, int itk) {
        const uint32_t sb = smem + st * GEMM_STAGE_BYTES;
        const size_t k0 = (size_t)itk * 64;
#pragma unroll
        for (int t = 0; t < 4; t++) {
            int row = rr + t * 32;
            cp_async16(sb +         aswz(row, cc), A  + (bm + row) * (size_t)K + k0 + cc * 8);
            cp_async16(sb + 16384 + aswz(row, cc), Bp + (bn + row) * (size_t)K + k0 + cc * 8);
        }
    };

    load_stage(0, 0); CP_COMMIT();
    load_stage(1, 1); CP_COMMIT();

    int cur = 0;
    for (int it = 0; it < KT; it++) {
        CP_WAIT1();
        __syncthreads();
        int nxt = cur + 2; if (nxt >= 3) nxt -= 3;
        if (it + 2 < KT) load_stage(nxt, it + 2);
        CP_COMMIT();

        const uint32_t sb = smem + cur * GEMM_STAGE_BYTES;
#pragma unroll
        for (int ks = 0; ks < 4; ks++) {
            uint32_t ah[2][4];
#pragma unroll
            for (int mi = 0; mi < 2; mi++)
                ldsm4(sb + aswz(a_row + mi * 16, ks * 2 + a_ch), ah[mi]);
            uint32_t bh[8][2];
#pragma unroll
            for (int nt = 0; nt < 4; nt++) {
                uint32_t t4[4];
                ldsm4(sb + 16384 + aswz(b_rowb + nt * 16, ks * 2 + b_ch), t4);
                bh[2*nt][0] = t4[0]; bh[2*nt][1] = t4[1];
                bh[2*nt+1][0] = t4[2]; bh[2*nt+1][1] = t4[3];
            }
#pragma unroll
            for (int mi = 0; mi < 2; mi++)
#pragma unroll
                for (int ni = 0; ni < 8; ni++)
                    mma16816(acc[mi][ni], ah[mi], bh[ni]);
        }
        cur = cur + 1; if (cur >= 3) cur -= 3;
    }

    const int rl = lane >> 2, cl = (lane & 3) * 2;
#pragma unroll
    for (int mi = 0; mi < 2; mi++)
#pragma unroll
        for (int ni = 0; ni < 8; ni++) {
            size_t row0 = bm + wm * 32 + mi * 16 + rl;
            size_t col  = bn + wn * 64 + ni * 8 + cl;
            epi(acc[mi][ni], row0, col);
        }
}

template<int EPI>   // 0 fp32 out, 1 fp16 out, 2 GELU+fp16 out
__global__ void __launch_bounds__(256, 2)
gemm_mma(const __half* __restrict__ A, const __half* __restrict__ Bp,
         const float* __restrict__ bias,
         float* __restrict__ Cf, __half* __restrict__ Ch, int M, int N, int K)
{
    extern __shared__ char sm_raw[];
    gemm_body(A, Bp, M, N, K, smem_u32(sm_raw),
        [&](const float* c, size_t row0, size_t col) {
            const float b0 = bias[col], b1 = bias[col + 1];
            float v00 = c[0] + b0, v01 = c[1] + b1;
            float v10 = c[2] + b0, v11 = c[3] + b1;
            if (EPI == 2) {
                v00 = gelu_exact(v00); v01 = gelu_exact(v01);
                v10 = gelu_exact(v10); v11 = gelu_exact(v11);
            }
            if (EPI == 0) {
                *(float2*)(Cf + row0 * (size_t)N + col)       = make_float2(v00, v01);
                *(float2*)(Cf + (row0 + 8) * (size_t)N + col) = make_float2(v10, v11);
            } else {
                __half2 p0, p1;
                p0.x = __float2half_rn(v00); p0.y = __float2half_rn(v01);
                p1.x = __float2half_rn(v10); p1.y = __float2half_rn(v11);
                *(__half2*)(Ch + row0 * (size_t)N + col)       = p0;
                *(__half2*)(Ch + (row0 + 8) * (size_t)N + col) = p1;
            }
        });
}

// fused QKV GEMM: N = 6144 over concatenated weights; routes outputs, emits sq/sk
__global__ void __launch_bounds__(256, 2)
gemm_qkv(const __half* __restrict__ A, const __half* __restrict__ Bp,
         const float* __restrict__ bq, const float* __restrict__ bk,
         const float* __restrict__ bv,
         __half* __restrict__ qh, __half* __restrict__ kh, __half* __restrict__ vh,
         __half* __restrict__ sqh, __half* __restrict__ skh, int M, int K)
{
    extern __shared__ char sm_raw[];
    const int sel = (int)(blockIdx.x >> 4);          // 16 CTA-cols per 2048 block
    const float* bias = (sel == 0) ? bq : (sel == 1) ? bk : bv;
    __half* outp = (sel == 0) ? qh : (sel == 1) ? kh : vh;
    __half* sigp = (sel == 0) ? sqh : (sel == 1) ? skh : nullptr;

    gemm_body(A, Bp, M, 6144, K, smem_u32(sm_raw),
        [&](const float* c, size_t row0, size_t col) {
            size_t lc = col & 2047;
            const float b0 = bias[lc], b1 = bias[lc + 1];
            float v00 = c[0] + b0, v01 = c[1] + b1;
            float v10 = c[2] + b0, v11 = c[3] + b1;
            __half2 p0, p1;
            p0.x = __float2half_rn(v00); p0.y = __float2half_rn(v01);
            p1.x = __float2half_rn(v10); p1.y = __float2half_rn(v11);
            *(__half2*)(outp + row0 * (size_t)Dd + lc)       = p0;
            *(__half2*)(outp + (row0 + 8) * (size_t)Dd + lc) = p1;
            if (sel < 2) {
                __half2 s0, s1;
                s0.x = __float2half_rn(elu1(v00)); s0.y = __float2half_rn(elu1(v01));
                s1.x = __float2half_rn(elu1(v10)); s1.y = __float2half_rn(elu1(v11));
                *(__half2*)(sigp + row0 * (size_t)Dd + lc)       = s0;
                *(__half2*)(sigp + (row0 + 8) * (size_t)Dd + lc) = s1;
            }
        });
}

// ---------------- attention kernel A ----------------
#define AS_KV  16384
#define AS_MEM 32768
#define AS_SC  65536
#define SC_ROWB 2176
#define SMEM_A_BYTES (65536 + 64*SC_ROWB)

__device__ __forceinline__ uint32_t sc_off(int row, int col) {
    return (uint32_t)(row * SC_ROWB + ((((col >> 2) ^ (row & 7))) << 4) + ((col & 3) << 2));
}
__device__ __forceinline__ uint32_t p_off(int row, int colh) {
    return (uint32_t)(row * SC_ROWB + ((((colh >> 3) ^ (row & 7))) << 4) + ((colh & 7) << 1));
}

__global__ void __launch_bounds__(256)
attn_seg_a(const __half* __restrict__ q, const __half* __restrict__ k,
           const __half* __restrict__ v, const __half* __restrict__ sq,
           const __half* __restrict__ sk, const float* __restrict__ betas,
           __half* __restrict__ att_h, int seg)
{
    extern __shared__ char sma[];
    const uint32_t s_qs  = smem_u32(sma);
    const uint32_t s_kv  = s_qs + AS_KV;
    const uint32_t s_mem = s_qs + AS_MEM;
    const uint32_t s_sc  = s_qs + AS_SC;
    __shared__ float z_s[128], gate_s[128], den_s[64], denk_s[64];

    const int tid = threadIdx.x;
    const int lane = tid & 31;
    const int w = tid >> 5;
    const int wm = w >> 2;
    const int wn = w & 3;
    const int rb = blockIdx.x;
    const int bh = blockIdx.y;
    const int b  = bh >> 4, h = bh & 15;
    const int r0 = rb * 64;
    const size_t rowbase = (size_t)(b * Ss + seg * Ll);
    const int colbase = h * 128;

#pragma unroll
    for (int t = 0; t < 4; t++) {
        int idx = tid + t * 256, row = idx >> 4, c = idx & 15;
        cp_async16(s_qs + swzh(row, c), q + (rowbase + r0 + row) * Dd + colbase + c * 8);
    }
#pragma unroll
    for (int t = 0; t < 8; t++) {
        int idx = tid + t * 256, row = idx >> 4, c = idx & 15;
        cp_async16(s_mem + swzh(row, c), g_mem_h + (size_t)bh * 16384 + row * 128 + c * 8);
    }
    CP_COMMIT();
    if (tid < 128) {
        z_s[tid]    = g_zst[bh * 128 + tid];
        gate_s[tid] = 1.0f / (1.0f + __expf(-betas[h * 128 + tid]));
    }

    const float scale = 0.088388347648318447f;
    const int rl = lane >> 2, cl = (lane & 3) * 2;

    // ---- phase 1: scores ----
    for (int ch = 0; ch <= rb; ch++) {
        __syncthreads();
#pragma unroll
        for (int t = 0; t < 4; t++) {
            int idx = tid + t * 256, row = idx >> 4, c = idx & 15;
            cp_async16(s_kv + swzh(row, c), k + (rowbase + ch * 64 + row) * Dd + colbase + c * 8);
        }
        CP_COMMIT(); CP_WAIT0();
        __syncthreads();

        float accs[2][2][4] = {};
#pragma unroll
        for (int ks = 0; ks < 8; ks++) {
            uint32_t a[2][4];
#pragma unroll
            for (int mi = 0; mi < 2; mi++) {
                int arow = wm*32 + mi*16 + (lane & 7) + ((lane >> 3) & 1) * 8;
                int ach  = ks*2 + ((lane >> 4) & 1);
                ldsm4(s_qs + swzh(arow, ach), a[mi]);
            }
            uint32_t t4[4];
            int brow = wn*16 + (lane & 7) + ((lane >> 4) & 1) * 8;
            int bch  = ks*2 + ((lane >> 3) & 1);
            ldsm4(s_kv + swzh(brow, bch), t4);
            uint32_t b0[2] = {t4[0], t4[1]}, b1[2] = {t4[2], t4[3]};
#pragma unroll
            for (int mi = 0; mi < 2; mi++) {
                mma16816(accs[mi][0], a[mi], b0);
                mma16816(accs[mi][1], a[mi], b1);
            }
        }
#pragma unroll
        for (int mi = 0; mi < 2; mi++)
#pragma unroll
            for (int ni = 0; ni < 2; ni++) {
                int rowl = wm*32 + mi*16 + rl;
                int coll = wn*16 + ni*8 + cl;
                float c0 = accs[mi][ni][0] * scale, c1 = accs[mi][ni][1] * scale;
                float c2 = accs[mi][ni][2] * scale, c3 = accs[mi][ni][3] * scale;
                if (ch == rb) {
                    if (coll     > rowl) c0 = -1e9f;
                    if (coll + 1 > rowl) c1 = -1e9f;
                    if (coll     > rowl + 8) c2 = -1e9f;
                    if (coll + 1 > rowl + 8) c3 = -1e9f;
                }
                int colg = ch*64 + coll;
                *(float2*)(sma + (s_sc - s_qs) + sc_off(rowl,     colg)) = make_float2(c0, c1);
                *(float2*)(sma + (s_sc - s_qs) + sc_off(rowl + 8, colg)) = make_float2(c2, c3);
            }
    }
    __syncthreads();

    // overlap: start loading sq over q (q dead after phase 1)
#pragma unroll
    for (int t = 0; t < 4; t++) {
        int idx = tid + t * 256, row = idx >> 4, c = idx & 15;
        cp_async16(s_qs + swzh(row, c), sq + (rowbase + r0 + row) * Dd + colbase + c * 8);
    }
    CP_COMMIT();

    // ---- phase 2: softmax + fp16 P ----
    {
        char* scb = sma + (s_sc - s_qs);
        const int mlim = (rb + 1) * 64;
        for (int rr = 0; rr < 8; rr++) {
            int row = w * 8 + rr;
            int gr  = r0 + row;
            float mx = -1e30f;
            for (int m = lane; m <= gr; m += 32) mx = fmaxf(mx, *(float*)(scb + sc_off(row, m)));
#pragma unroll
            for (int o = 16; o > 0; o >>= 1) mx = fmaxf(mx, __shfl_xor_sync(0xffffffffu, mx, o));
            float s = 0.0f;
            for (int m = lane; m <= gr; m += 32) {
                float* p = (float*)(scb + sc_off(row, m));
                float e = __expf(*p - mx); *p = e; s += e;
            }
#pragma unroll
            for (int o = 16; o > 0; o >>= 1) s += __shfl_xor_sync(0xffffffffu, s, o);
            float inv = 1.0f / s;
            for (int m = lane; m < mlim; m += 32) {
                float* p = (float*)(scb + sc_off(row, m));
                *p = (m <= gr) ? (*p) * inv : 0.0f;
            }
            float tmp[16];
            int nj = mlim >> 5;
            for (int j = 0; j < nj; j++) tmp[j] = *(float*)(scb + sc_off(row, lane + 32*j));
            __syncwarp();
            for (int j = 0; j < nj; j++) {
                int colh = lane + 32*j;
                *(__half*)(scb + p_off(row, colh)) = __float2half_rn(tmp[j]);
            }
            __syncwarp();
        }
    }
    __syncthreads();

    // ---- phase 3: att_dot = P @ V ----
    float accd[2][4][4] = {};
    for (int ch = 0; ch <= rb; ch++) {
        __syncthreads();
#pragma unroll
        for (int t = 0; t < 4; t++) {
            int idx = tid + t * 256, row = idx >> 4, c = idx & 15;
            cp_async16(s_kv + swzh(row, c), v + (rowbase + ch * 64 + row) * Dd + colbase + c * 8);
        }
        CP_COMMIT(); CP_WAIT0();
        __syncthreads();
#pragma unroll
        for (int ks = 0; ks < 4; ks++) {
            uint32_t pa[2][4];
#pragma unroll
            for (int mi = 0; mi < 2; mi++) {
                int arow = wm*32 + mi*16 + (lane & 7) + ((lane >> 3) & 1) * 8;
                int pch  = ch*8 + ks*2 + ((lane >> 4) & 1);
                ldsm4(s_sc + (uint32_t)(arow * SC_ROWB) + (((uint32_t)(pch ^ (arow & 7))) << 4), pa[mi]);
            }
#pragma unroll
            for (int ntp = 0; ntp < 2; ntp++) {
                int vrow = ks*16 + (lane & 7) + ((lane >> 3) & 1) * 8;
                int vch  = wn*4 + ntp*2 + ((lane >> 4) & 1);
                uint32_t t4[4];
                ldsm4t(s_kv + swzh(vrow, vch), t4);
                uint32_t b0[2] = {t4[0], t4[1]}, b1[2] = {t4[2], t4[3]};
#pragma unroll
                for (int mi = 0; mi < 2; mi++) {
                    mma16816(accd[mi][ntp*2],     pa[mi], b0);
                    mma16816(accd[mi][ntp*2 + 1], pa[mi], b1);
                }
            }
        }
    }

    // ---- phase 4: den; att_mem = sq @ mem ----
    __syncthreads();
    {
        int row = tid >> 2, qtr = tid & 3;
        float dsum = 0.0f;
        for (int pi = 0; pi < 16; pi++) {
            int p = qtr * 16 + pi;
            uint32_t adr = s_qs + swzh(row, p >> 2) + (p & 3) * 4;
            __half2 hv = *(__half2*)(sma + (adr - s_qs));
            dsum += __half2float(hv.x) * z_s[2*p] + __half2float(hv.y) * z_s[2*p + 1];
        }
        dsum += __shfl_xor_sync(0xffffffffu, dsum, 1);
        dsum += __shfl_xor_sync(0xffffffffu, dsum, 2);
        if (qtr == 0) den_s[row] = dsum;
    }
    float accm[2][4][4] = {};
#pragma unroll
    for (int ks = 0; ks < 8; ks++) {
        uint32_t a[2][4];
#pragma unroll
        for (int mi = 0; mi < 2; mi++) {
            int arow = wm*32 + mi*16 + (lane & 7) + ((lane >> 3) & 1) * 8;
            int ach  = ks*2 + ((lane >> 4) & 1);
            ldsm4(s_qs + swzh(arow, ach), a[mi]);
        }
#pragma unroll
        for (int ntp = 0; ntp < 2; ntp++) {
            int mrow = ks*16 + (lane & 7) + ((lane >> 3) & 1) * 8;
            int mch  = wn*4 + ntp*2 + ((lane >> 4) & 1);
            uint32_t t4[4];
            ldsm4t(s_mem + swzh(mrow, mch), t4);
            uint32_t b0[2] = {t4[0], t4[1]}, b1[2] = {t4[2], t4[3]};
#pragma unroll
            for (int mi = 0; mi < 2; mi++) {
                mma16816(accm[mi][ntp*2],     a[mi], b0);
                mma16816(accm[mi][ntp*2 + 1], a[mi], b1);
            }
        }
    }
    __syncthreads();

    // ---- combine + store att ----
#pragma unroll
    for (int mi = 0; mi < 2; mi++)
#pragma unroll
        for (int ni = 0; ni < 4; ni++) {
            int rowl0 = wm*32 + mi*16 + rl;
            int col   = wn*32 + ni*8 + cl;
            float g0 = gate_s[col], g1 = gate_s[col + 1];
#pragma unroll
            for (int rr = 0; rr < 2; rr++) {
                int rowl = rowl0 + rr*8;
                float invd = 1.0f / den_s[rowl];
                float m0 = accm[mi][ni][rr*2]   * invd;
                float m1 = accm[mi][ni][rr*2+1] * invd;
                float d0 = accd[mi][ni][rr*2], d1 = accd[mi][ni][rr*2+1];
                __half2 o;
                o.x = __float2half_rn(g0 * m0 + (1.0f - g0) * d0);
                o.y = __float2half_rn(g1 * m1 + (1.0f - g1) * d1);
                *(__half2*)(att_h + (rowbase + r0 + rowl) * Dd + colbase + col) = o;
            }
        }

    // ---- phase 5: load sk; denk; v_del ----
    __syncthreads();
#pragma unroll
    for (int t = 0; t < 4; t++) {
        int idx = tid + t * 256, row = idx >> 4, c = idx & 15;
        cp_async16(s_kv + swzh(row, c), sk + (rowbase + r0 + row) * Dd + colbase + c * 8);
    }
    CP_COMMIT(); CP_WAIT0();
    __syncthreads();
    {
        int row = tid >> 2, qtr = tid & 3;
        float dsum = 0.0f;
        for (int pi = 0; pi < 16; pi++) {
            int p = qtr * 16 + pi;
            uint32_t adr = s_kv + swzh(row, p >> 2) + (p & 3) * 4;
            __half2 hv = *(__half2*)(sma + (adr - s_qs));
            dsum += __half2float(hv.x) * z_s[2*p] + __half2float(hv.y) * z_s[2*p + 1];
        }
        dsum += __shfl_xor_sync(0xffffffffu, dsum, 1);
        dsum += __shfl_xor_sync(0xffffffffu, dsum, 2);
        if (qtr == 0) denk_s[row] = dsum;
    }
    float accv[2][4][4] = {};
#pragma unroll
    for (int ks = 0; ks < 8; ks++) {
        uint32_t a[2][4];
#pragma unroll
        for (int mi = 0; mi < 2; mi++) {
            int arow = wm*32 + mi*16 + (lane & 7) + ((lane >> 3) & 1) * 8;
            int ach  = ks*2 + ((lane >> 4) & 1);
            ldsm4(s_kv + swzh(arow, ach), a[mi]);
        }
#pragma unroll
        for (int ntp = 0; ntp < 2; ntp++) {
            int mrow = ks*16 + (lane & 7) + ((lane >> 3) & 1) * 8;
            int mch  = wn*4 + ntp*2 + ((lane >> 4) & 1);
            uint32_t t4[4];
            ldsm4t(s_mem + swzh(mrow, mch), t4);
            uint32_t b0[2] = {t4[0], t4[1]}, b1[2] = {t4[2], t4[3]};
#pragma unroll
            for (int mi = 0; mi < 2; mi++) {
                mma16816(accv[mi][ntp*2],     a[mi], b0);
                mma16816(accv[mi][ntp*2 + 1], a[mi], b1);
            }
        }
    }
    __syncthreads();
#pragma unroll
    for (int mi = 0; mi < 2; mi++)
#pragma unroll
        for (int ni = 0; ni < 4; ni++) {
            int rowl0 = wm*32 + mi*16 + rl;
            int col   = wn*32 + ni*8 + cl;
#pragma unroll
            for (int rr = 0; rr < 2; rr++) {
                int rowl = rowl0 + rr*8;
                float invk = 1.0f / denk_s[rowl];
                __half2 vv = *(const __half2*)(v + (rowbase + r0 + rowl) * Dd + colbase + col);
                __half2 o;
                o.x = __float2half_rn(__half2float(vv.x) - accv[mi][ni][rr*2]   * invk);
                o.y = __float2half_rn(__half2float(vv.y) - accv[mi][ni][rr*2+1] * invk);
                *(__half2*)(g_vdel_h + ((size_t)bh * Ll + r0 + rowl) * 128 + col) = o;
            }
        }
}

// ---------------- attention kernel B: mem += sk^T @ v_del ; z += colsum(sk) ----------------
// grid (32 bh, 2 dv-halves)
__global__ void __launch_bounds__(256)
attn_seg_b(const __half* __restrict__ sk, int seg)
{
    __shared__ __align__(16) char skb[16384];   // 64 x 256B (full 128 dk cols)
    __shared__ __align__(16) char vdb[8192];    // 64 x 128B (64 dv cols)
    const uint32_t s_sk = smem_u32(skb);
    const uint32_t s_vd = smem_u32(vdb);

    const int tid = threadIdx.x;
    const int lane = tid & 31;
    const int w = tid >> 5;
    const int wm = w >> 2;      // 0..1 over dk halves
    const int wn = w & 3;       // 0..3 over 16 dv cols each
    const int bh = blockIdx.x;
    const int dvbase = blockIdx.y * 64;
    const int b = bh >> 4, h = bh & 15;
    const size_t rowbase = (size_t)(b * Ss + seg * Ll);
    const int colbase = h * 128;

    float acc[4][2][4] = {};
    float zacc = 0.0f;

    for (int ch = 0; ch < 8; ch++) {
        __syncthreads();
#pragma unroll
        for (int t = 0; t < 4; t++) {
            int idx = tid + t * 256, row = idx >> 4, c = idx & 15;
            cp_async16(s_sk + swzh(row, c), sk + (rowbase + ch*64 + row) * Dd + colbase + c * 8);
        }
#pragma unroll
        for (int t = 0; t < 2; t++) {
            int idx = tid + t * 256, row = idx >> 3, c = idx & 7;
            cp_async16(s_vd + aswz(row, c),
                       g_vdel_h + ((size_t)bh * Ll + ch*64 + row) * 128 + dvbase + c * 8);
        }
        CP_COMMIT(); CP_WAIT0();
        __syncthreads();

#pragma unroll
        for (int ks = 0; ks < 4; ks++) {
            uint32_t a[4][4];
#pragma unroll
            for (int mt = 0; mt < 4; mt++) {
                int srow = ks*16 + (lane & 7) + ((lane >> 4) & 1) * 8;
                int sch  = ((wm*64 + mt*16) >> 3) + ((lane >> 3) & 1);
                ldsm4t(s_sk + swzh(srow, sch), a[mt]);
            }
            int vrow = ks*16 + (lane & 7) + ((lane >> 3) & 1) * 8;
            int vch  = wn*2 + ((lane >> 4) & 1);
            uint32_t t4[4];
            ldsm4t(s_vd + aswz(vrow, vch), t4);
            uint32_t b0[2] = {t4[0], t4[1]}, b1[2] = {t4[2], t4[3]};
#pragma unroll
            for (int mt = 0; mt < 4; mt++) {
                mma16816(acc[mt][0], a[mt], b0);
                mma16816(acc[mt][1], a[mt], b1);
            }
        }
        if (blockIdx.y == 0 && tid < 128) {
            int col = tid;
            for (int r = 0; r < 64; r++) {
                __half hv = *(__half*)(skb + swzh(r, col >> 3) + (col & 7) * 2);
                zacc += __half2float(hv);
            }
        }
    }

    const int rl = lane >> 2, cl = (lane & 3) * 2;
    size_t mbase = (size_t)bh * 16384;
#pragma unroll
    for (int mt = 0; mt < 4; mt++)
#pragma unroll
        for (int ni = 0; ni < 2; ni++) {
            int col = dvbase + wn*16 + ni*8 + cl;
#pragma unroll
            for (int rr = 0; rr < 2; rr++) {
                int row = wm*64 + mt*16 + rl + rr*8;
                float2* pf = (float2*)(g_mem + mbase + (size_t)row * 128 + col);
                float2 cur = *pf;
                cur.x += acc[mt][ni][rr*2];
                cur.y += acc[mt][ni][rr*2+1];
                *pf = cur;
                __half2 hm;
                hm.x = __float2half_rn(cur.x); hm.y = __float2half_rn(cur.y);
                *(__half2*)(g_mem_h + mbase + (size_t)row * 128 + col) = hm;
            }
        }
    if (blockIdx.y == 0 && tid < 128) g_zst[bh * 128 + tid] += zacc;
}

// ---------------- residual + LayerNorm ----------------
__global__ void __launch_bounds__(256)
resid_ln(const float* __restrict__ h2, const float* __restrict__ x,
         const float* __restrict__ w, const float* __restrict__ bsh,
         float* __restrict__ out)
{
    __shared__ float ybuf[Dd];
    __shared__ float red[17];
    const int row = blockIdx.x;
    const int tid = threadIdx.x;
    const float* hr = h2 + (size_t)row * Dd;
    const float* xr = x  + (size_t)row * Dd;

    float s = 0.0f, sq = 0.0f;
    for (int c = tid; c < Dd; c += 256) {
        float yv = hr[c] + xr[c];
        ybuf[c] = yv;
        s += yv; sq += yv * yv;
    }
#pragma unroll
    for (int o = 16; o > 0; o >>= 1) {
        s  += __shfl_xor_sync(0xffffffffu, s, o);
        sq += __shfl_xor_sync(0xffffffffu, sq, o);
    }
    int warp = tid >> 5, lane = tid & 31;
    if (lane == 0) { red[warp] = s; red[8 + warp] = sq; }
    __syncthreads();
    if (tid == 0) {
        float S = 0, SQ = 0;
        for (int i = 0; i < 8; i++) { S += red[i]; SQ += red[8 + i]; }
        red[0] = S; red[1] = SQ;
    }
    __syncthreads();
    float mu  = red[0] / (float)Dd;
    float var = red[1] / (float)Dd - mu * mu;
    float inv = rsqrtf(var + 1e-5f);
    for (int c = tid; c < Dd; c += 256)
        out[(size_t)row * Dd + c] = (ybuf[c] - mu) * inv * w[c] + bsh[c];
}

// ---------------- launch ----------------
extern "C" void kernel_launch(void* const* d_in, const int* in_sizes, int n_in,
                              void* d_out, int out_size)
{
    const float* x    = (const float*)d_in[0];
    const float* Wq   = (const float*)d_in[1];
    const float* bq   = (const float*)d_in[2];
    const float* Wk   = (const float*)d_in[3];
    const float* bk   = (const float*)d_in[4];
    const float* Wv   = (const float*)d_in[5];
    const float* bv   = (const float*)d_in[6];
    const float* Wo   = (const float*)d_in[7];
    const float* bo   = (const float*)d_in[8];
    const float* beta = (const float*)d_in[9];
    const float* W1   = (const float*)d_in[10];
    const float* b1   = (const float*)d_in[11];
    const float* W2   = (const float*)d_in[12];
    const float* b2   = (const float*)d_in[13];
    const float* lnw  = (const float*)d_in[14];
    const float* lnb  = (const float*)d_in[15];
    float* out = (float*)d_out;

    float *ph2;
    __half *pxh, *pqh, *pkh, *pvh, *psq, *psk, *path, *pah, *ph1h;
    __half *wqkv, *wo, *w1, *w2;
    cudaGetSymbolAddress((void**)&ph2,  g_h2);
    cudaGetSymbolAddress((void**)&pxh,  g_x_h);
    cudaGetSymbolAddress((void**)&pqh,  g_q_h);
    cudaGetSymbolAddress((void**)&pkh,  g_k_h);
    cudaGetSymbolAddress((void**)&pvh,  g_v_h);
    cudaGetSymbolAddress((void**)&psq,  g_sq_h);
    cudaGetSymbolAddress((void**)&psk,  g_sk_h);
    cudaGetSymbolAddress((void**)&path, g_att_h);
    cudaGetSymbolAddress((void**)&pah,  g_a_h);
    cudaGetSymbolAddress((void**)&ph1h, g_h1_h);
    cudaGetSymbolAddress((void**)&wqkv, g_wqkv);
    cudaGetSymbolAddress((void**)&wo, g_wo);
    cudaGetSymbolAddress((void**)&w1, g_w1);
    cudaGetSymbolAddress((void**)&w2, g_w2);

    cudaFuncSetAttribute(attn_seg_a, cudaFuncAttributeMaxDynamicSharedMemorySize, SMEM_A_BYTES);
    cudaFuncSetAttribute(gemm_mma<0>, cudaFuncAttributeMaxDynamicSharedMemorySize, GEMM_SMEM_BYTES);
    cudaFuncSetAttribute(gemm_mma<1>, cudaFuncAttributeMaxDynamicSharedMemorySize, GEMM_SMEM_BYTES);
    cudaFuncSetAttribute(gemm_mma<2>, cudaFuncAttributeMaxDynamicSharedMemorySize, GEMM_SMEM_BYTES);
    cudaFuncSetAttribute(gemm_qkv,    cudaFuncAttributeMaxDynamicSharedMemorySize, GEMM_SMEM_BYTES);

    init_state_kernel<<<2048, 256>>>();                                    // 1
    convt_all<<<16384, 256>>>(x, pxh, Wq, Wk, Wv, Wo, W1, W2,              // 2
                              wqkv, wo, w1, w2);

    gemm_qkv<<<dim3(48, 64), 256, GEMM_SMEM_BYTES>>>(                      // 3
        pxh, wqkv, bq, bk, bv, pqh, pkh, pvh, psq, psk, BSr, Dd);

    for (int seg = 0; seg < NSEGc; seg++) {
        attn_seg_a<<<dim3(8, 32), 256, SMEM_A_BYTES>>>(pqh, pkh, pvh, psq, psk,
                                                       beta, path, seg);   // 4, 6(profiled), ...
        attn_seg_b<<<dim3(32, 2), 256>>>(psk, seg);                        // 5, ...
    }

    dim3 gP(Dd/128, BSr/128);
    gemm_mma<1><<<gP, 256, GEMM_SMEM_BYTES>>>(path, wo, bo, nullptr, pah, BSr, Dd, Dd);
    dim3 gW1(DH/128, BSr/128);
    gemm_mma<2><<<gW1, 256, GEMM_SMEM_BYTES>>>(pah, w1, b1, nullptr, ph1h, BSr, DH, Dd);
    gemm_mma<0><<<gP, 256, GEMM_SMEM_BYTES>>>(ph1h, w2, b2, ph2, nullptr, BSr, Dd, DH);

    resid_ln<<<BSr, 256>>>(ph2, x, lnw, lnb, out);
}

// round 8
// speedup vs baseline: 7.7554x; 1.1340x over previous
#include <cuda_runtime.h>
#include <cuda_fp16.h>
#include <cstdint>

// ---------------- problem constants ----------------
#define Bb   2
#define Ss   4096
#define Dd   2048
#define Hh   16
#define DH   8192
#define Ll   512
#define NSEGc 8
#define BSr  (Bb*Ss)
#define BHn  (Bb*Hh)

// ---------------- scratch ----------------
__device__ float g_h2 [(size_t)BSr*Dd];
__device__ __half g_x_h  [(size_t)BSr*Dd];
__device__ __half g_q_h  [(size_t)BSr*Dd];
__device__ __half g_k_h  [(size_t)BSr*Dd];
__device__ __half g_v_h  [(size_t)BSr*Dd];
__device__ __half g_sq_h [(size_t)BSr*Dd];
__device__ __half g_sk_h [(size_t)BSr*Dd];
__device__ __half g_dot_h[(size_t)BSr*Dd];
__device__ __half g_att_h[(size_t)BSr*Dd];
__device__ __half g_a_h  [(size_t)BSr*Dd];
__device__ __half g_h1_h [(size_t)BSr*DH];
__device__ __half g_wqkv[(size_t)3*Dd*Dd];
__device__ __half g_wo[(size_t)Dd*Dd];
__device__ __half g_w1[(size_t)DH*Dd];
__device__ __half g_w2[(size_t)Dd*DH];
__device__ float  g_mem  [BHn*128*128];
__device__ __half g_mem_h[BHn*128*128];
__device__ float  g_zst  [BHn*128];
__device__ __half g_vdel_h[BHn*Ll*128];

// ---------------- helpers ----------------
__device__ __forceinline__ float gelu_exact(float x) {
    return 0.5f * x * (1.0f + erff(x * 0.70710678118654752440f));
}
__device__ __forceinline__ float elu1(float x) {
    return (x > 0.0f) ? (x + 1.0f) : __expf(x);
}
__device__ __forceinline__ uint32_t smem_u32(const void* p) {
    uint32_t a;
    asm("{ .reg .u64 t; cvta.to.shared.u64 t, %1; cvt.u32.u64 %0, t; }" : "=r"(a) : "l"(p));
    return a;
}
__device__ __forceinline__ void mma16816(float* c, const uint32_t* a, const uint32_t* b) {
    asm volatile(
        "mma.sync.aligned.m16n8k16.row.col.f32.f16.f16.f32 "
        "{%0,%1,%2,%3}, {%4,%5,%6,%7}, {%8,%9}, {%0,%1,%2,%3};"
        : "+f"(c[0]), "+f"(c[1]), "+f"(c[2]), "+f"(c[3])
        : "r"(a[0]), "r"(a[1]), "r"(a[2]), "r"(a[3]), "r"(b[0]), "r"(b[1]));
}
__device__ __forceinline__ void ldsm4(uint32_t addr, uint32_t* r) {
    asm volatile("ldmatrix.sync.aligned.m8n8.x4.shared.b16 {%0,%1,%2,%3}, [%4];"
                 : "=r"(r[0]), "=r"(r[1]), "=r"(r[2]), "=r"(r[3]) : "r"(addr));
}
__device__ __forceinline__ void ldsm4t(uint32_t addr, uint32_t* r) {
    asm volatile("ldmatrix.sync.aligned.m8n8.x4.trans.shared.b16 {%0,%1,%2,%3}, [%4];"
                 : "=r"(r[0]), "=r"(r[1]), "=r"(r[2]), "=r"(r[3]) : "r"(addr));
}
__device__ __forceinline__ void cp_async16(uint32_t saddr, const void* gaddr) {
    asm volatile("cp.async.cg.shared.global [%0], [%1], 16;" :: "r"(saddr), "l"(gaddr));
}
#define CP_COMMIT() asm volatile("cp.async.commit_group;" ::: "memory")
#define CP_WAIT1()  asm volatile("cp.async.wait_group 1;" ::: "memory")
#define CP_WAIT0()  asm volatile("cp.async.wait_group 0;" ::: "memory")

__device__ __forceinline__ uint32_t aswz(int row, int chunk) {
    return (uint32_t)(row * 128 + ((chunk ^ (row & 7)) << 4));
}
__device__ __forceinline__ uint32_t swzh(int row, int chunk16) {
    return (uint32_t)(row * 256 + ((chunk16 ^ (row & 7)) << 4));
}

// ---------------- state init ----------------
__global__ void init_state_kernel() {
    int i = blockIdx.x * blockDim.x + threadIdx.x;
    if (i < BHn*128*128) { g_mem[i] = 0.0f; g_mem_h[i] = __float2half(0.0f); }
    if (i < BHn*128)     g_zst[i] = 1.0f / 128.0f;
}

// ---------------- weights convert+transpose + x convert (vectorized) ----------------
__global__ void __launch_bounds__(256)
convt_all(const float* __restrict__ x, __half* __restrict__ xh,
          const float* __restrict__ Wq, const float* __restrict__ Wk,
          const float* __restrict__ Wv, const float* __restrict__ Wo,
          const float* __restrict__ W1, const float* __restrict__ W2,
          __half* tqkv, __half* to_, __half* t1, __half* t2)
{
    const int id = blockIdx.x;
    const int tid = threadIdx.x;
    if (id >= 12288) {
        size_t base4 = (size_t)(id - 12288) * 1024;
#pragma unroll
        for (int j = 0; j < 4; j++) {
            size_t i4 = base4 + tid + j * 256;
            float4 v = ((const float4*)x)[i4];
            __half2 a, b;
            a.x = __float2half_rn(v.x); a.y = __float2half_rn(v.y);
            b.x = __float2half_rn(v.z); b.y = __float2half_rn(v.w);
            ((__half2*)xh)[i4*2]   = a;
            ((__half2*)xh)[i4*2+1] = b;
        }
        return;
    }
    const float* W; __half* T; int K, N, nb, kb;
    if (id < 4096) {
        int w = id >> 10, t = id & 1023;
        nb = t & 31; kb = t >> 5; K = 2048; N = 2048;
        if (w < 3)  { W = (w == 0) ? Wq : (w == 1) ? Wk : Wv; T = tqkv + (size_t)w * 4194304; }
        else        { W = Wo; T = to_; }
    } else if (id < 8192) {
        int t = id - 4096; nb = t & 127; kb = t >> 7; K = 2048; N = 8192;
        W = W1; T = t1;
    } else {
        int t = id - 8192; nb = t & 31; kb = t >> 5; K = 8192; N = 2048;
        W = W2; T = t2;
    }
    __shared__ float tbuf[64][65];
    const int n0 = nb * 64, k0 = kb * 64;
#pragma unroll
    for (int t = 0; t < 4; t++) {
        int i = tid + t * 256;            // 1024 float4 tiles
        int r = i >> 4, c4 = (i & 15) * 4;
        float4 v = *(const float4*)(W + (size_t)(k0 + r) * N + n0 + c4);
        tbuf[r][c4+0] = v.x; tbuf[r][c4+1] = v.y;
        tbuf[r][c4+2] = v.z; tbuf[r][c4+3] = v.w;
    }
    __syncthreads();
#pragma unroll
    for (int t = 0; t < 2; t++) {
        int i = tid + t * 256;            // 512 uint4 writes
        int rn = i >> 3, kg = i & 7;
        __half tmp[8];
#pragma unroll
        for (int j = 0; j < 8; j++) tmp[j] = __float2half_rn(tbuf[kg*8 + j][rn]);
        *(uint4*)(T + (size_t)(n0 + rn) * K + k0 + kg * 8) = *(uint4*)tmp;
    }
}

// ---------------- GEMM core (BK=64, 3-stage) ----------------
#define GEMM_STAGE_BYTES 32768
#define GEMM_SMEM_BYTES  (3 * GEMM_STAGE_BYTES)

template<typename EpiF>
__device__ __forceinline__ void gemm_body(
    const __half* __restrict__ A, const __half* __restrict__ Bp,
    int M, int N, int K, uint32_t smem, EpiF epi)
{
    const int tid  = threadIdx.x;
    const int lane = tid & 31;
    const int w    = tid >> 5;
    const int wm   = w & 3;
    const int wn   = w >> 2;
    const size_t bm = (size_t)blockIdx.y * 128;
    const size_t bn = (size_t)blockIdx.x * 128;
    const int KT = K >> 6;

    const int a_row = wm * 32 + (lane & 7) + ((lane >> 3) & 1) * 8;
    const int a_ch  = (lane >> 4) & 1;
    const int b_rowb = wn * 64 + (lane & 7) + ((lane >> 4) & 1) * 8;
    const int b_ch  = (lane >> 3) & 1;

    const int rr = tid >> 3, cc = tid & 7;

    float acc[2][8][4];
#pragma unroll
    for (int i = 0; i < 2; i++)
#pragma unroll
        for (int j = 0; j < 8; j++)
#pragma unroll
            for (int q = 0; q < 4; q++) acc[i][j][q] = 0.0f;

    auto load_stage = [&](int st, int itk) {
        const uint32_t sb = smem + st * GEMM_STAGE_BYTES;
        const size_t k0 = (size_t)itk * 64;
#pragma unroll
        for (int t = 0; t < 4; t++) {
            int row = rr + t * 32;
            cp_async16(sb +         aswz(row, cc), A  + (bm + row) * (size_t)K + k0 + cc * 8);
            cp_async16(sb + 16384 + aswz(row, cc), Bp + (bn + row) * (size_t)K + k0 + cc * 8);
        }
    };

    load_stage(0, 0); CP_COMMIT();
    load_stage(1, 1); CP_COMMIT();

    int cur = 0;
    for (int it = 0; it < KT; it++) {
        CP_WAIT1();
        __syncthreads();
        int nxt = cur + 2; if (nxt >= 3) nxt -= 3;
        if (it + 2 < KT) load_stage(nxt, it + 2);
        CP_COMMIT();

        const uint32_t sb = smem + cur * GEMM_STAGE_BYTES;
#pragma unroll
        for (int ks = 0; ks < 4; ks++) {
            uint32_t ah[2][4];
#pragma unroll
            for (int mi = 0; mi < 2; mi++)
                ldsm4(sb + aswz(a_row + mi * 16, ks * 2 + a_ch), ah[mi]);
            uint32_t bh[8][2];
#pragma unroll
            for (int nt = 0; nt < 4; nt++) {
                uint32_t t4[4];
                ldsm4(sb + 16384 + aswz(b_rowb + nt * 16, ks * 2 + b_ch), t4);
                bh[2*nt][0] = t4[0]; bh[2*nt][1] = t4[1];
                bh[2*nt+1][0] = t4[2]; bh[2*nt+1][1] = t4[3];
            }
#pragma unroll
            for (int mi = 0; mi < 2; mi++)
#pragma unroll
                for (int ni = 0; ni < 8; ni++)
                    mma16816(acc[mi][ni], ah[mi], bh[ni]);
        }
        cur = cur + 1; if (cur >= 3) cur -= 3;
    }

    const int rl = lane >> 2, cl = (lane & 3) * 2;
#pragma unroll
    for (int mi = 0; mi < 2; mi++)
#pragma unroll
        for (int ni = 0; ni < 8; ni++) {
            size_t row0 = bm + wm * 32 + mi * 16 + rl;
            size_t col  = bn + wn * 64 + ni * 8 + cl;
            epi(acc[mi][ni], row0, col);
        }
}

template<int EPI>
__global__ void __launch_bounds__(256, 2)
gemm_mma(const __half* __restrict__ A, const __half* __restrict__ Bp,
         const float* __restrict__ bias,
         float* __restrict__ Cf, __half* __restrict__ Ch, int M, int N, int K)
{
    extern __shared__ char sm_raw[];
    gemm_body(A, Bp, M, N, K, smem_u32(sm_raw),
        [&](const float* c, size_t row0, size_t col) {
            const float b0 = bias[col], b1 = bias[col + 1];
            float v00 = c[0] + b0, v01 = c[1] + b1;
            float v10 = c[2] + b0, v11 = c[3] + b1;
            if (EPI == 2) {
                v00 = gelu_exact(v00); v01 = gelu_exact(v01);
                v10 = gelu_exact(v10); v11 = gelu_exact(v11);
            }
            if (EPI == 0) {
                *(float2*)(Cf + row0 * (size_t)N + col)       = make_float2(v00, v01);
                *(float2*)(Cf + (row0 + 8) * (size_t)N + col) = make_float2(v10, v11);
            } else {
                __half2 p0, p1;
                p0.x = __float2half_rn(v00); p0.y = __float2half_rn(v01);
                p1.x = __float2half_rn(v10); p1.y = __float2half_rn(v11);
                *(__half2*)(Ch + row0 * (size_t)N + col)       = p0;
                *(__half2*)(Ch + (row0 + 8) * (size_t)N + col) = p1;
            }
        });
}

__global__ void __launch_bounds__(256, 2)
gemm_qkv(const __half* __restrict__ A, const __half* __restrict__ Bp,
         const float* __restrict__ bq, const float* __restrict__ bk,
         const float* __restrict__ bv,
         __half* __restrict__ qh, __half* __restrict__ kh, __half* __restrict__ vh,
         __half* __restrict__ sqh, __half* __restrict__ skh, int M, int K)
{
    extern __shared__ char sm_raw[];
    const int sel = (int)(blockIdx.x >> 4);
    const float* bias = (sel == 0) ? bq : (sel == 1) ? bk : bv;
    __half* outp = (sel == 0) ? qh : (sel == 1) ? kh : vh;
    __half* sigp = (sel == 0) ? sqh : (sel == 1) ? skh : nullptr;

    gemm_body(A, Bp, M, 6144, K, smem_u32(sm_raw),
        [&](const float* c, size_t row0, size_t col) {
            size_t lc = col & 2047;
            const float b0 = bias[lc], b1 = bias[lc + 1];
            float v00 = c[0] + b0, v01 = c[1] + b1;
            float v10 = c[2] + b0, v11 = c[3] + b1;
            __half2 p0, p1;
            p0.x = __float2half_rn(v00); p0.y = __float2half_rn(v01);
            p1.x = __float2half_rn(v10); p1.y = __float2half_rn(v11);
            *(__half2*)(outp + row0 * (size_t)Dd + lc)       = p0;
            *(__half2*)(outp + (row0 + 8) * (size_t)Dd + lc) = p1;
            if (sel < 2) {
                __half2 s0, s1;
                s0.x = __float2half_rn(elu1(v00)); s0.y = __float2half_rn(elu1(v01));
                s1.x = __float2half_rn(elu1(v10)); s1.y = __float2half_rn(elu1(v11));
                *(__half2*)(sigp + row0 * (size_t)Dd + lc)       = s0;
                *(__half2*)(sigp + (row0 + 8) * (size_t)Dd + lc) = s1;
            }
        });
}

// ---------------- attn_local: scores + softmax + P@V for ALL segments ----------------
// grid (8 rb, 8 seg, 32 bh). smem: qs 16K, kv0 16K, kv1 16K, sc 64x2176B.
#define SC_ROWB 2176
#define LS_SC   49152
#define SMEM_L_BYTES (49152 + 64*SC_ROWB)   // 188416

__device__ __forceinline__ uint32_t sc_off(int row, int col) {
    return (uint32_t)(row * SC_ROWB + ((((col >> 2) ^ (row & 7))) << 4) + ((col & 3) << 2));
}
__device__ __forceinline__ uint32_t p_off(int row, int colh) {
    return (uint32_t)(row * SC_ROWB + ((((colh >> 3) ^ (row & 7))) << 4) + ((colh & 7) << 1));
}

__global__ void __launch_bounds__(256)
attn_local(const __half* __restrict__ q, const __half* __restrict__ k,
           const __half* __restrict__ v, __half* __restrict__ dot)
{
    extern __shared__ char sma[];
    const uint32_t s_qs = smem_u32(sma);
    const uint32_t s_kvb[2] = { s_qs + 16384, s_qs + 32768 };
    const uint32_t s_sc = s_qs + LS_SC;

    const int tid = threadIdx.x;
    const int lane = tid & 31;
    const int w = tid >> 5;
    const int wm = w >> 2;
    const int wn = w & 3;
    const int rb  = blockIdx.x;
    const int seg = blockIdx.y;
    const int bh  = blockIdx.z;
    const int b = bh >> 4, h = bh & 15;
    const int r0 = rb * 64;
    const size_t rowbase = (size_t)(b * Ss + seg * Ll);
    const int colbase = h * 128;
    const int rl = lane >> 2, cl = (lane & 3) * 2;
    const float scale = 0.088388347648318447f;

    auto load_tile = [&](uint32_t dst, const __half* src, int ch) {
#pragma unroll
        for (int t = 0; t < 4; t++) {
            int idx = tid + t * 256, row = idx >> 4, c = idx & 15;
            cp_async16(dst + swzh(row, c), src + (rowbase + ch * 64 + row) * Dd + colbase + c * 8);
        }
    };

    // G0: q tile + k(0); G1: k(1)
#pragma unroll
    for (int t = 0; t < 4; t++) {
        int idx = tid + t * 256, row = idx >> 4, c = idx & 15;
        cp_async16(s_qs + swzh(row, c), q + (rowbase + r0 + row) * Dd + colbase + c * 8);
    }
    load_tile(s_kvb[0], k, 0); CP_COMMIT();
    if (rb >= 1) load_tile(s_kvb[1], k, 1);
    CP_COMMIT();

    // ---- phase 1: scores ----
    for (int ch = 0; ch <= rb; ch++) {
        CP_WAIT1();
        __syncthreads();
        const uint32_t s_kv = s_kvb[ch & 1];

        float accs[2][2][4] = {};
#pragma unroll
        for (int ks = 0; ks < 8; ks++) {
            uint32_t a[2][4];
#pragma unroll
            for (int mi = 0; mi < 2; mi++) {
                int arow = wm*32 + mi*16 + (lane & 7) + ((lane >> 3) & 1) * 8;
                int ach  = ks*2 + ((lane >> 4) & 1);
                ldsm4(s_qs + swzh(arow, ach), a[mi]);
            }
            uint32_t t4[4];
            int brow = wn*16 + (lane & 7) + ((lane >> 4) & 1) * 8;
            int bch  = ks*2 + ((lane >> 3) & 1);
            ldsm4(s_kv + swzh(brow, bch), t4);
            uint32_t b0[2] = {t4[0], t4[1]}, b1[2] = {t4[2], t4[3]};
#pragma unroll
            for (int mi = 0; mi < 2; mi++) {
                mma16816(accs[mi][0], a[mi], b0);
                mma16816(accs[mi][1], a[mi], b1);
            }
        }
#pragma unroll
        for (int mi = 0; mi < 2; mi++)
#pragma unroll
            for (int ni = 0; ni < 2; ni++) {
                int rowl = wm*32 + mi*16 + rl;
                int coll = wn*16 + ni*8 + cl;
                float c0 = accs[mi][ni][0] * scale, c1 = accs[mi][ni][1] * scale;
                float c2 = accs[mi][ni][2] * scale, c3 = accs[mi][ni][3] * scale;
                if (ch == rb) {
                    if (coll     > rowl) c0 = -1e9f;
                    if (coll + 1 > rowl) c1 = -1e9f;
                    if (coll     > rowl + 8) c2 = -1e9f;
                    if (coll + 1 > rowl + 8) c3 = -1e9f;
                }
                int colg = ch*64 + coll;
                *(float2*)(sma + LS_SC + sc_off(rowl,     colg)) = make_float2(c0, c1);
                *(float2*)(sma + LS_SC + sc_off(rowl + 8, colg)) = make_float2(c2, c3);
            }
        __syncthreads();
        if (ch + 2 <= rb) load_tile(s_kvb[ch & 1], k, ch + 2);
        CP_COMMIT();
    }

    // preload v(0), v(1) (overlaps softmax)
    load_tile(s_kvb[0], v, 0); CP_COMMIT();
    if (rb >= 1) load_tile(s_kvb[1], v, 1);
    CP_COMMIT();

    // ---- phase 2: softmax + fp16 P ----
    {
        char* scb = sma + LS_SC;
        const int mlim = (rb + 1) * 64;
        for (int rr2 = 0; rr2 < 8; rr2++) {
            int row = w * 8 + rr2;
            int gr  = r0 + row;
            float mx = -1e30f;
            for (int m = lane; m <= gr; m += 32) mx = fmaxf(mx, *(float*)(scb + sc_off(row, m)));
#pragma unroll
            for (int o = 16; o > 0; o >>= 1) mx = fmaxf(mx, __shfl_xor_sync(0xffffffffu, mx, o));
            float s = 0.0f;
            for (int m = lane; m <= gr; m += 32) {
                float* p = (float*)(scb + sc_off(row, m));
                float e = __expf(*p - mx); *p = e; s += e;
            }
#pragma unroll
            for (int o = 16; o > 0; o >>= 1) s += __shfl_xor_sync(0xffffffffu, s, o);
            float inv = 1.0f / s;
            for (int m = lane; m < mlim; m += 32) {
                float* p = (float*)(scb + sc_off(row, m));
                *p = (m <= gr) ? (*p) * inv : 0.0f;
            }
            float tmp[16];
            int nj = mlim >> 5;
            for (int j = 0; j < nj; j++) tmp[j] = *(float*)(scb + sc_off(row, lane + 32*j));
            __syncwarp();
            for (int j = 0; j < nj; j++) {
                int colh = lane + 32*j;
                *(__half*)(scb + p_off(row, colh)) = __float2half_rn(tmp[j]);
            }
            __syncwarp();
        }
    }

    // ---- phase 3: att_dot = P @ V ----
    float accd[2][4][4] = {};
    for (int ch = 0; ch <= rb; ch++) {
        CP_WAIT1();
        __syncthreads();
        const uint32_t s_kv = s_kvb[ch & 1];
#pragma unroll
        for (int ks = 0; ks < 4; ks++) {
            uint32_t pa[2][4];
#pragma unroll
            for (int mi = 0; mi < 2; mi++) {
                int arow = wm*32 + mi*16 + (lane & 7) + ((lane >> 3) & 1) * 8;
                int pch  = ch*8 + ks*2 + ((lane >> 4) & 1);
                ldsm4(s_sc + (uint32_t)(arow * SC_ROWB) + (((uint32_t)(pch ^ (arow & 7))) << 4), pa[mi]);
            }
#pragma unroll
            for (int ntp = 0; ntp < 2; ntp++) {
                int vrow = ks*16 + (lane & 7) + ((lane >> 3) & 1) * 8;
                int vch  = wn*4 + ntp*2 + ((lane >> 4) & 1);
                uint32_t t4[4];
                ldsm4t(s_kv + swzh(vrow, vch), t4);
                uint32_t b0[2] = {t4[0], t4[1]}, b1[2] = {t4[2], t4[3]};
#pragma unroll
                for (int mi = 0; mi < 2; mi++) {
                    mma16816(accd[mi][ntp*2],     pa[mi], b0);
                    mma16816(accd[mi][ntp*2 + 1], pa[mi], b1);
                }
            }
        }
        __syncthreads();
        if (ch + 2 <= rb) load_tile(s_kvb[ch & 1], v, ch + 2);
        CP_COMMIT();
    }

    // write att_dot
#pragma unroll
    for (int mi = 0; mi < 2; mi++)
#pragma unroll
        for (int ni = 0; ni < 4; ni++) {
            int rowl0 = wm*32 + mi*16 + rl;
            int col   = wn*32 + ni*8 + cl;
#pragma unroll
            for (int rr2 = 0; rr2 < 2; rr2++) {
                int rowl = rowl0 + rr2*8;
                __half2 o;
                o.x = __float2half_rn(accd[mi][ni][rr2*2]);
                o.y = __float2half_rn(accd[mi][ni][rr2*2+1]);
                *(__half2*)(dot + (rowbase + r0 + rowl) * Dd + colbase + col) = o;
            }
        }
}

// ---------------- attn_mem: retrieval + combine + v_del (per segment) ----------------
// grid (8 rb, 32 bh); smem 96KB -> 2 CTAs/SM.
#define MS_SK  16384
#define MS_V   32768
#define MS_DOT 49152
#define MS_MEM 65536
#define SMEM_M_BYTES 98304

__global__ void __launch_bounds__(256, 2)
attn_mem(const __half* __restrict__ sq, const __half* __restrict__ sk,
         const __half* __restrict__ v, const __half* __restrict__ dot,
         const float* __restrict__ betas, __half* __restrict__ att_h, int seg)
{
    extern __shared__ char smm[];
    const uint32_t s_sq  = smem_u32(smm);
    const uint32_t s_sk  = s_sq + MS_SK;
    const uint32_t s_v   = s_sq + MS_V;
    const uint32_t s_dot = s_sq + MS_DOT;
    const uint32_t s_mem = s_sq + MS_MEM;
    __shared__ float z_s[128], gate_s[128], den_s[64], denk_s[64];

    const int tid = threadIdx.x;
    const int lane = tid & 31;
    const int w = tid >> 5;
    const int wm = w >> 2;
    const int wn = w & 3;
    const int rb = blockIdx.x;
    const int bh = blockIdx.y;
    const int b = bh >> 4, h = bh & 15;
    const int r0 = rb * 64;
    const size_t rowbase = (size_t)(b * Ss + seg * Ll);
    const int colbase = h * 128;
    const int rl = lane >> 2, cl = (lane & 3) * 2;

#pragma unroll
    for (int t = 0; t < 4; t++) {
        int idx = tid + t * 256, row = idx >> 4, c = idx & 15;
        size_t goff = (rowbase + r0 + row) * Dd + colbase + c * 8;
        cp_async16(s_sq  + swzh(row, c), sq  + goff);
        cp_async16(s_sk  + swzh(row, c), sk  + goff);
        cp_async16(s_v   + swzh(row, c), v   + goff);
        cp_async16(s_dot + swzh(row, c), dot + goff);
    }
#pragma unroll
    for (int t = 0; t < 8; t++) {
        int idx = tid + t * 256, row = idx >> 4, c = idx & 15;
        cp_async16(s_mem + swzh(row, c), g_mem_h + (size_t)bh * 16384 + row * 128 + c * 8);
    }
    CP_COMMIT();
    if (tid < 128) {
        z_s[tid]    = g_zst[bh * 128 + tid];
        gate_s[tid] = 1.0f / (1.0f + __expf(-betas[h * 128 + tid]));
    }
    CP_WAIT0();
    __syncthreads();

    // den (sq.z) and denk (sk.z)
    {
        int row = tid >> 2, qtr = tid & 3;
        float ds = 0.0f, dk = 0.0f;
        for (int pi = 0; pi < 16; pi++) {
            int p = qtr * 16 + pi;
            uint32_t off = swzh(row, p >> 2) + (p & 3) * 4;
            __half2 hq = *(__half2*)(smm + off);
            __half2 hk = *(__half2*)(smm + MS_SK + off);
            float z0 = z_s[2*p], z1 = z_s[2*p + 1];
            ds += __half2float(hq.x) * z0 + __half2float(hq.y) * z1;
            dk += __half2float(hk.x) * z0 + __half2float(hk.y) * z1;
        }
        ds += __shfl_xor_sync(0xffffffffu, ds, 1);
        ds += __shfl_xor_sync(0xffffffffu, ds, 2);
        dk += __shfl_xor_sync(0xffffffffu, dk, 1);
        dk += __shfl_xor_sync(0xffffffffu, dk, 2);
        if (qtr == 0) { den_s[row] = ds; denk_s[row] = dk; }
    }

    // accm = sq @ mem ; accv = sk @ mem (share mem fragments)
    float accm[2][4][4] = {};
    float accv[2][4][4] = {};
#pragma unroll
    for (int ks = 0; ks < 8; ks++) {
        uint32_t aq[2][4], ak[2][4];
#pragma unroll
        for (int mi = 0; mi < 2; mi++) {
            int arow = wm*32 + mi*16 + (lane & 7) + ((lane >> 3) & 1) * 8;
            int ach  = ks*2 + ((lane >> 4) & 1);
            ldsm4(s_sq + swzh(arow, ach), aq[mi]);
            ldsm4(s_sk + swzh(arow, ach), ak[mi]);
        }
#pragma unroll
        for (int ntp = 0; ntp < 2; ntp++) {
            int mrow = ks*16 + (lane & 7) + ((lane >> 3) & 1) * 8;
            int mch  = wn*4 + ntp*2 + ((lane >> 4) & 1);
            uint32_t t4[4];
            ldsm4t(s_mem + swzh(mrow, mch), t4);
            uint32_t b0[2] = {t4[0], t4[1]}, b1[2] = {t4[2], t4[3]};
#pragma unroll
            for (int mi = 0; mi < 2; mi++) {
                mma16816(accm[mi][ntp*2],     aq[mi], b0);
                mma16816(accm[mi][ntp*2 + 1], aq[mi], b1);
                mma16816(accv[mi][ntp*2],     ak[mi], b0);
                mma16816(accv[mi][ntp*2 + 1], ak[mi], b1);
            }
        }
    }
    __syncthreads();

    // combine + att write; v_del write
#pragma unroll
    for (int mi = 0; mi < 2; mi++)
#pragma unroll
        for (int ni = 0; ni < 4; ni++) {
            int rowl0 = wm*32 + mi*16 + rl;
            int col   = wn*32 + ni*8 + cl;
            float g0 = gate_s[col], g1 = gate_s[col + 1];
#pragma unroll
            for (int rr2 = 0; rr2 < 2; rr2++) {
                int rowl = rowl0 + rr2*8;
                uint32_t soff = swzh(rowl, col >> 3) + (col & 7) * 2;
                float invd = 1.0f / den_s[rowl];
                float invk = 1.0f / denk_s[rowl];
                __half2 dd = *(__half2*)(smm + MS_DOT + soff);
                __half2 vv = *(__half2*)(smm + MS_V + soff);
                __half2 o, od;
                o.x = __float2half_rn(g0 * (accm[mi][ni][rr2*2]   * invd)
                                      + (1.0f - g0) * __half2float(dd.x));
                o.y = __float2half_rn(g1 * (accm[mi][ni][rr2*2+1] * invd)
                                      + (1.0f - g1) * __half2float(dd.y));
                od.x = __float2half_rn(__half2float(vv.x) - accv[mi][ni][rr2*2]   * invk);
                od.y = __float2half_rn(__half2float(vv.y) - accv[mi][ni][rr2*2+1] * invk);
                *(__half2*)(att_h + (rowbase + r0 + rowl) * Dd + colbase + col) = o;
                *(__half2*)(g_vdel_h + ((size_t)bh * Ll + r0 + rowl) * 128 + col) = od;
            }
        }
}

// ---------------- attn_seg_b: mem += sk^T @ v_del ; z += colsum(sk) ----------------
__global__ void __launch_bounds__(256)
attn_seg_b(const __half* __restrict__ sk, int seg)
{
    __shared__ __align__(16) char skb[16384];
    __shared__ __align__(16) char vdb[8192];
    const uint32_t s_sk = smem_u32(skb);
    const uint32_t s_vd = smem_u32(vdb);

    const int tid = threadIdx.x;
    const int lane = tid & 31;
    const int w = tid >> 5;
    const int wm = w >> 2;
    const int wn = w & 3;
    const int bh = blockIdx.x;
    const int dvbase = blockIdx.y * 64;
    const int b = bh >> 4, h = bh & 15;
    const size_t rowbase = (size_t)(b * Ss + seg * Ll);
    const int colbase = h * 128;

    float acc[4][2][4] = {};
    float zacc = 0.0f;

    for (int ch = 0; ch < 8; ch++) {
        __syncthreads();
#pragma unroll
        for (int t = 0; t < 4; t++) {
            int idx = tid + t * 256, row = idx >> 4, c = idx & 15;
            cp_async16(s_sk + swzh(row, c), sk + (rowbase + ch*64 + row) * Dd + colbase + c * 8);
        }
#pragma unroll
        for (int t = 0; t < 2; t++) {
            int idx = tid + t * 256, row = idx >> 3, c = idx & 7;
            cp_async16(s_vd + aswz(row, c),
                       g_vdel_h + ((size_t)bh * Ll + ch*64 + row) * 128 + dvbase + c * 8);
        }
        CP_COMMIT(); CP_WAIT0();
        __syncthreads();

#pragma unroll
        for (int ks = 0; ks < 4; ks++) {
            uint32_t a[4][4];
#pragma unroll
            for (int mt = 0; mt < 4; mt++) {
                int srow = ks*16 + (lane & 7) + ((lane >> 4) & 1) * 8;
                int sch  = ((wm*64 + mt*16) >> 3) + ((lane >> 3) & 1);
                ldsm4t(s_sk + swzh(srow, sch), a[mt]);
            }
            int vrow = ks*16 + (lane & 7) + ((lane >> 3) & 1) * 8;
            int vch  = wn*2 + ((lane >> 4) & 1);
            uint32_t t4[4];
            ldsm4t(s_vd + aswz(vrow, vch), t4);
            uint32_t b0[2] = {t4[0], t4[1]}, b1[2] = {t4[2], t4[3]};
#pragma unroll
            for (int mt = 0; mt < 4; mt++) {
                mma16816(acc[mt][0], a[mt], b0);
                mma16816(acc[mt][1], a[mt], b1);
            }
        }
        if (blockIdx.y == 0 && tid < 128) {
            int col = tid;
            for (int r = 0; r < 64; r++) {
                __half hv = *(__half*)(skb + swzh(r, col >> 3) + (col & 7) * 2);
                zacc += __half2float(hv);
            }
        }
    }

    const int rl = lane >> 2, cl = (lane & 3) * 2;
    size_t mbase = (size_t)bh * 16384;
#pragma unroll
    for (int mt = 0; mt < 4; mt++)
#pragma unroll
        for (int ni = 0; ni < 2; ni++) {
            int col = dvbase + wn*16 + ni*8 + cl;
#pragma unroll
            for (int rr = 0; rr < 2; rr++) {
                int row = wm*64 + mt*16 + rl + rr*8;
                float2* pf = (float2*)(g_mem + mbase + (size_t)row * 128 + col);
                float2 cur = *pf;
                cur.x += acc[mt][ni][rr*2];
                cur.y += acc[mt][ni][rr*2+1];
                *pf = cur;
                __half2 hm;
                hm.x = __float2half_rn(cur.x); hm.y = __float2half_rn(cur.y);
                *(__half2*)(g_mem_h + mbase + (size_t)row * 128 + col) = hm;
            }
        }
    if (blockIdx.y == 0 && tid < 128) g_zst[bh * 128 + tid] += zacc;
}

// ---------------- residual + LayerNorm ----------------
__global__ void __launch_bounds__(256)
resid_ln(const float* __restrict__ h2, const float* __restrict__ x,
         const float* __restrict__ w, const float* __restrict__ bsh,
         float* __restrict__ out)
{
    __shared__ float ybuf[Dd];
    __shared__ float red[17];
    const int row = blockIdx.x;
    const int tid = threadIdx.x;
    const float* hr = h2 + (size_t)row * Dd;
    const float* xr = x  + (size_t)row * Dd;

    float s = 0.0f, sq = 0.0f;
    for (int c = tid; c < Dd; c += 256) {
        float yv = hr[c] + xr[c];
        ybuf[c] = yv;
        s += yv; sq += yv * yv;
    }
#pragma unroll
    for (int o = 16; o > 0; o >>= 1) {
        s  += __shfl_xor_sync(0xffffffffu, s, o);
        sq += __shfl_xor_sync(0xffffffffu, sq, o);
    }
    int warp = tid >> 5, lane = tid & 31;
    if (lane == 0) { red[warp] = s; red[8 + warp] = sq; }
    __syncthreads();
    if (tid == 0) {
        float S = 0, SQ = 0;
        for (int i = 0; i < 8; i++) { S += red[i]; SQ += red[8 + i]; }
        red[0] = S; red[1] = SQ;
    }
    __syncthreads();
    float mu  = red[0] / (float)Dd;
    float var = red[1] / (float)Dd - mu * mu;
    float inv = rsqrtf(var + 1e-5f);
    for (int c = tid; c < Dd; c += 256)
        out[(size_t)row * Dd + c] = (ybuf[c] - mu) * inv * w[c] + bsh[c];
}

// ---------------- launch ----------------
extern "C" void kernel_launch(void* const* d_in, const int* in_sizes, int n_in,
                              void* d_out, int out_size)
{
    const float* x    = (const float*)d_in[0];
    const float* Wq   = (const float*)d_in[1];
    const float* bq   = (const float*)d_in[2];
    const float* Wk   = (const float*)d_in[3];
    const float* bk   = (const float*)d_in[4];
    const float* Wv   = (const float*)d_in[5];
    const float* bv   = (const float*)d_in[6];
    const float* Wo   = (const float*)d_in[7];
    const float* bo   = (const float*)d_in[8];
    const float* beta = (const float*)d_in[9];
    const float* W1   = (const float*)d_in[10];
    const float* b1   = (const float*)d_in[11];
    const float* W2   = (const float*)d_in[12];
    const float* b2   = (const float*)d_in[13];
    const float* lnw  = (const float*)d_in[14];
    const float* lnb  = (const float*)d_in[15];
    float* out = (float*)d_out;

    float *ph2;
    __half *pxh, *pqh, *pkh, *pvh, *psq, *psk, *pdot, *path, *pah, *ph1h;
    __half *wqkv, *wo, *w1, *w2;
    cudaGetSymbolAddress((void**)&ph2,  g_h2);
    cudaGetSymbolAddress((void**)&pxh,  g_x_h);
    cudaGetSymbolAddress((void**)&pqh,  g_q_h);
    cudaGetSymbolAddress((void**)&pkh,  g_k_h);
    cudaGetSymbolAddress((void**)&pvh,  g_v_h);
    cudaGetSymbolAddress((void**)&psq,  g_sq_h);
    cudaGetSymbolAddress((void**)&psk,  g_sk_h);
    cudaGetSymbolAddress((void**)&pdot, g_dot_h);
    cudaGetSymbolAddress((void**)&path, g_att_h);
    cudaGetSymbolAddress((void**)&pah,  g_a_h);
    cudaGetSymbolAddress((void**)&ph1h, g_h1_h);
    cudaGetSymbolAddress((void**)&wqkv, g_wqkv);
    cudaGetSymbolAddress((void**)&wo, g_wo);
    cudaGetSymbolAddress((void**)&w1, g_w1);
    cudaGetSymbolAddress((void**)&w2, g_w2);

    cudaFuncSetAttribute(attn_local, cudaFuncAttributeMaxDynamicSharedMemorySize, SMEM_L_BYTES);
    cudaFuncSetAttribute(attn_mem,   cudaFuncAttributeMaxDynamicSharedMemorySize, SMEM_M_BYTES);
    cudaFuncSetAttribute(gemm_mma<0>, cudaFuncAttributeMaxDynamicSharedMemorySize, GEMM_SMEM_BYTES);
    cudaFuncSetAttribute(gemm_mma<1>, cudaFuncAttributeMaxDynamicSharedMemorySize, GEMM_SMEM_BYTES);
    cudaFuncSetAttribute(gemm_mma<2>, cudaFuncAttributeMaxDynamicSharedMemorySize, GEMM_SMEM_BYTES);
    cudaFuncSetAttribute(gemm_qkv,    cudaFuncAttributeMaxDynamicSharedMemorySize, GEMM_SMEM_BYTES);

    init_state_kernel<<<2048, 256>>>();                                    // 1
    convt_all<<<16384, 256>>>(x, pxh, Wq, Wk, Wv, Wo, W1, W2,              // 2
                              wqkv, wo, w1, w2);
    gemm_qkv<<<dim3(48, 64), 256, GEMM_SMEM_BYTES>>>(                      // 3
        pxh, wqkv, bq, bk, bv, pqh, pkh, pvh, psq, psk, BSr, Dd);

    attn_local<<<dim3(8, 8, 32), 256, SMEM_L_BYTES>>>(pqh, pkh, pvh, pdot); // 4

    for (int seg = 0; seg < NSEGc; seg++) {
        attn_mem<<<dim3(8, 32), 256, SMEM_M_BYTES>>>(psq, psk, pvh, pdot,  // 5, 7, ...
                                                     beta, path, seg);
        attn_seg_b<<<dim3(32, 2), 256>>>(psk, seg);                        // 6 (profiled), ...
    }

    dim3 gP(Dd/128, BSr/128);
    gemm_mma<1><<<gP, 256, GEMM_SMEM_BYTES>>>(path, wo, bo, nullptr, pah, BSr, Dd, Dd);
    dim3 gW1(DH/128, BSr/128);
    gemm_mma<2><<<gW1, 256, GEMM_SMEM_BYTES>>>(pah, w1, b1, nullptr, ph1h, BSr, DH, Dd);
    gemm_mma<0><<<gP, 256, GEMM_SMEM_BYTES>>>(ph1h, w2, b2, ph2, nullptr, BSr, Dd, DH);

    resid_ln<<<BSr, 256>>>(ph2, x, lnw, lnb, out);
}